// round 7
// baseline (speedup 1.0000x reference)
#include <cuda_runtime.h>
#include <math.h>

#define NB 2048
#define NT 64
#define ND 15
#define NH 256
#define TB 32        // batch rows per GRU CTA (sorted tile)
#define NBT 64       // NB / TB
#define THR 128
#define WHH_N (2 * 4 * 256 * 192)

typedef unsigned long long u64;

// ---------------- f32x2 packed-FMA helpers ----------------
__device__ __forceinline__ void ffma2(u64& d, u64 a, u64 b) {
  asm("fma.rn.f32x2 %0, %1, %2, %3;" : "=l"(d) : "l"(a), "l"(b), "l"(d));
}
__device__ __forceinline__ u64 splat2(float w) {
  u64 d; asm("mov.b64 %0, {%1, %1};" : "=l"(d) : "f"(w)); return d;
}
__device__ __forceinline__ float2 unpk2(u64 v) {
  float2 r; asm("mov.b64 {%0, %1}, %2;" : "=f"(r.x), "=f"(r.y) : "l"(v)); return r;
}

// ---------------- mbarrier / bulk-copy helpers ----------------
__device__ __forceinline__ unsigned smem_u32(const void* p) {
  unsigned a;
  asm("{ .reg .u64 t; cvta.to.shared.u64 t, %1; cvt.u32.u64 %0, t; }" : "=r"(a) : "l"(p));
  return a;
}
__device__ __forceinline__ void mbar_init(unsigned mbar, unsigned cnt) {
  asm volatile("mbarrier.init.shared.b64 [%0], %1;" :: "r"(mbar), "r"(cnt) : "memory");
}
__device__ __forceinline__ void mbar_expect(unsigned mbar, unsigned bytes) {
  asm volatile("mbarrier.arrive.expect_tx.shared.b64 _, [%0], %1;"
               :: "r"(mbar), "r"(bytes) : "memory");
}
__device__ __forceinline__ void bulk_g2s(unsigned dst, const void* src,
                                         unsigned bytes, unsigned mbar) {
  asm volatile(
      "cp.async.bulk.shared::cta.global.mbarrier::complete_tx::bytes [%0], [%1], %2, [%3];"
      :: "r"(dst), "l"(src), "r"(bytes), "r"(mbar) : "memory");
}
__device__ __forceinline__ void mbar_wait(unsigned mbar, unsigned parity) {
  asm volatile(
      "{\n\t.reg .pred P;\n\t"
      "W%=:\n\t"
      "mbarrier.try_wait.parity.acquire.cta.shared::cta.b64 P, [%0], %1, 0x989680;\n\t"
      "@P bra.uni D%=;\n\t"
      "bra.uni W%=;\n\t"
      "D%=:\n\t}"
      :: "r"(mbar), "r"(parity) : "memory");
}

// ---------------- device scratch ----------------
__device__ float g_h[2][2][NB][NH];          // [parity][gru][sorted_pos][h]
__device__ float g_whhB[WHH_N];              // [g][jt][k][gate*64+c]
__device__ float g_wblk[8][3136];            // [g*4+jt]{ wihT[15][192], cbA[192], cbHn[64] }
__device__ float g_xin[2][NB][272];
__device__ float g_a1[2][NB][1024];
__device__ float g_a2[2][NB][1024];
__device__ float g_a3[2][NB][512];
__device__ float g_a4[2][NB][256];
__device__ int   g_perm[NB];
__device__ int   g_off[66];
__device__ int   g_hist[66];
__device__ int   g_tilemax[NBT];
__device__ int   g_invpos[NB];
__device__ int   g_finparp[NB];
__device__ int   g_lsort[NB];

// ---------------- fused length sort (single block) ----------------
__global__ void k_sort(const int* __restrict__ lengths) {
  int tid = threadIdx.x;
  if (tid < 66) g_hist[tid] = 0;
  __syncthreads();
  for (int b = tid; b < NB; b += 1024) atomicAdd(&g_hist[lengths[b]], 1);
  __syncthreads();
  if (tid == 0) {
    int s = 0;
    for (int l = 0; l < 66; ++l) { g_off[l] = s; s += g_hist[l]; }
  }
  __syncthreads();
  for (int b = tid; b < NB; b += 1024) {
    int p = atomicAdd(&g_off[lengths[b]], 1);
    g_perm[p] = b;
  }
  __syncthreads();
  if (tid < NBT) g_tilemax[tid] = lengths[g_perm[tid * TB + TB - 1]];
  __syncthreads();
  for (int p = tid; p < NB; p += 1024) {
    int b = g_perm[p];
    g_invpos[b] = p;
    g_finparp[p] = g_tilemax[p >> 5] & 1;
    g_lsort[p] = lengths[b];
  }
}

// ---------------- fused weight prep ----------------
__global__ void k_prep(const float* __restrict__ Whh0, const float* __restrict__ Whh1,
                       const float* __restrict__ Wih0, const float* __restrict__ bih0,
                       const float* __restrict__ bhh0,
                       const float* __restrict__ Wih1, const float* __restrict__ bih1,
                       const float* __restrict__ bhh1) {
  int i = blockIdx.x * blockDim.x + threadIdx.x;
  if (i < WHH_N) {
    int c  = i % 192;
    int k  = (i / 192) % 256;
    int jt = (i / (192 * 256)) & 3;
    int g  = i / (192 * 256 * 4);
    const float* W = g ? Whh1 : Whh0;
    int gg = c >> 6, cc = c & 63;
    g_whhB[i] = W[(size_t)(gg * 256 + jt * 64 + cc) * 256 + k];
    return;
  }
  int j = i - WHH_N;
  if (j >= 8 * 3136) return;
  int o  = j % 3136;
  int jt = (j / 3136) & 3;
  int g  = j / (3136 * 4);
  const float* Wih = g ? Wih1 : Wih0;
  const float* bih = g ? bih1 : bih0;
  const float* bhh = g ? bhh1 : bhh0;
  float v;
  if (o < 2880) {
    int k = o / 192, c = o % 192;
    int gg = c >> 6, cc = c & 63;
    v = Wih[(size_t)(gg * 256 + jt * 64 + cc) * ND + k];
  } else if (o < 3072) {
    int c = o - 2880;
    int gg = c >> 6, cc = c & 63;
    int row = gg * 256 + jt * 64 + cc;
    v = (gg < 2) ? (bih[row] + bhh[row]) : bih[row];
  } else {
    v = bhh[512 + jt * 64 + (o - 3072)];
  }
  g_wblk[g * 4 + jt][o] = v;
}

// ---------------- GRU step kernel (LDG-direct weights, 4b x 4c per thread) ----------------
struct GruS {
  float hs[TB][256];   // 32768 B (one bulk copy)
  float xs[TB][ND];
  int   ls[TB];
  u64   mb[2];
};

__global__ void __launch_bounds__(THR, 3)
k_gru_step(const float* __restrict__ state, int t)
{
  extern __shared__ char sraw[];
  GruS& s = *reinterpret_cast<GruS*>(sraw);
  const int bt = blockIdx.x, jt = blockIdx.y, g = blockIdx.z;
  const int tid = threadIdx.x;
  const int pi = t & 1, po = pi ^ 1;

  if (t >= g_tilemax[bt]) return;   // frozen tile

  const unsigned mb_h = smem_u32(&s.mb[0]);
  const int gjt = g * 4 + jt;
  const float* __restrict__ wp = g_whhB + (size_t)gjt * 256 * 192;
  const float* __restrict__ wi = &g_wblk[gjt][0];

  if (tid == 0) mbar_init(mb_h, 1);
  __syncthreads();
  if (tid == 0 && t > 0) {
    mbar_expect(mb_h, 32768u);
    bulk_g2s(smem_u32(&s.hs[0][0]), &g_h[pi][g][bt * TB][0], 32768u, mb_h);
  }

  // x gather + lengths (overlaps h TMA flight)
  for (int i = tid; i < TB * ND; i += THR) {
    int b = i / ND, c = i % ND;
    s.xs[b][c] = state[((size_t)g_perm[bt * TB + b] * NT + t) * ND + c];
  }
  if (tid < TB) s.ls[tid] = g_lsort[bt * TB + tid];
  __syncthreads();

  const int cg = tid & 15;   // 16 col groups x 4 cols
  const int bg = tid >> 4;   // 8 batch groups x 4 rows
  const int b0 = bg * 4;
  const int c4 = cg * 4;

  // accumulators: [batch row][col pair] packed f32x2
  u64 aR[4][2], aZ[4][2], aI[4][2], aN[4][2];
  {
    ulonglong2 bR = *reinterpret_cast<const ulonglong2*>(wi + 2880 + c4);
    ulonglong2 bZ = *reinterpret_cast<const ulonglong2*>(wi + 2944 + c4);
    ulonglong2 bI = *reinterpret_cast<const ulonglong2*>(wi + 3008 + c4);
    ulonglong2 bN = *reinterpret_cast<const ulonglong2*>(wi + 3072 + c4);
    #pragma unroll
    for (int i = 0; i < 4; ++i) {
      aR[i][0] = bR.x; aR[i][1] = bR.y;
      aZ[i][0] = bZ.x; aZ[i][1] = bZ.y;
      aI[i][0] = bI.x; aI[i][1] = bI.y;
      aN[i][0] = bN.x; aN[i][1] = bN.y;
    }
  }

  // input-gate contribution (K = 15)
  #pragma unroll
  for (int k = 0; k < ND; ++k) {
    const float* row = wi + k * 192;
    ulonglong2 wr = *reinterpret_cast<const ulonglong2*>(row + c4);
    ulonglong2 wz = *reinterpret_cast<const ulonglong2*>(row + 64 + c4);
    ulonglong2 wn = *reinterpret_cast<const ulonglong2*>(row + 128 + c4);
    #pragma unroll
    for (int i = 0; i < 4; ++i) {
      u64 xv = splat2(s.xs[b0 + i][k]);
      ffma2(aR[i][0], xv, wr.x); ffma2(aR[i][1], xv, wr.y);
      ffma2(aZ[i][0], xv, wz.x); ffma2(aZ[i][1], xv, wz.y);
      ffma2(aI[i][0], xv, wn.x); ffma2(aI[i][1], xv, wn.y);
    }
  }

  // recurrent contribution (K = 256): LDG->regs, distance-4 pipeline (4 buffer sets)
  if (t > 0) {
    mbar_wait(mb_h, 0);
    ulonglong2 fr[4], fz[4], fn[4];
    #pragma unroll
    for (int p = 0; p < 4; ++p) {
      const float* row = wp + p * 192;
      fr[p] = *reinterpret_cast<const ulonglong2*>(row + c4);
      fz[p] = *reinterpret_cast<const ulonglong2*>(row + 64 + c4);
      fn[p] = *reinterpret_cast<const ulonglong2*>(row + 128 + c4);
    }
    for (int kc = 0; kc < 256; kc += 4) {
      #pragma unroll
      for (int u = 0; u < 4; ++u) {
        const int kk = kc + u;
        ulonglong2 wr = fr[u], wz = fz[u], wn = fn[u];
        int kp = kk + 4; if (kp > 255) kp = 255;
        const float* row = wp + kp * 192;
        fr[u] = *reinterpret_cast<const ulonglong2*>(row + c4);
        fz[u] = *reinterpret_cast<const ulonglong2*>(row + 64 + c4);
        fn[u] = *reinterpret_cast<const ulonglong2*>(row + 128 + c4);
        #pragma unroll
        for (int i = 0; i < 4; ++i) {
          u64 hv = splat2(s.hs[b0 + i][kk]);
          ffma2(aR[i][0], hv, wr.x); ffma2(aR[i][1], hv, wr.y);
          ffma2(aZ[i][0], hv, wz.x); ffma2(aZ[i][1], hv, wz.y);
          ffma2(aN[i][0], hv, wn.x); ffma2(aN[i][1], hv, wn.y);
        }
      }
    }
  }

  // gates + masked update + write
  #pragma unroll
  for (int i = 0; i < 4; ++i) {
    bool act = (t < s.ls[b0 + i]);
    float2 r0 = unpk2(aR[i][0]), r1 = unpk2(aR[i][1]);
    float2 z0 = unpk2(aZ[i][0]), z1 = unpk2(aZ[i][1]);
    float2 i0 = unpk2(aI[i][0]), i1 = unpk2(aI[i][1]);
    float2 n0 = unpk2(aN[i][0]), n1 = unpk2(aN[i][1]);
    float xr[4] = {r0.x, r0.y, r1.x, r1.y};
    float xz[4] = {z0.x, z0.y, z1.x, z1.y};
    float xi[4] = {i0.x, i0.y, i1.x, i1.y};
    float xn[4] = {n0.x, n0.y, n1.x, n1.y};
    float o[4];
    #pragma unroll
    for (int e = 0; e < 4; ++e) {
      float r = __fdividef(1.f, 1.f + __expf(-xr[e]));
      float z = __fdividef(1.f, 1.f + __expf(-xz[e]));
      float n = tanhf(fmaf(r, xn[e], xi[e]));
      float hold = (t > 0) ? s.hs[b0 + i][jt * 64 + c4 + e] : 0.f;
      o[e] = act ? fmaf(z, hold - n, n) : hold;
    }
    *reinterpret_cast<float4*>(&g_h[po][g][bt * TB + b0 + i][jt * 64 + c4]) =
        make_float4(o[0], o[1], o[2], o[3]);
  }
}

// ---------------- concat [state(:,0,:), action, h] ----------------
__global__ void k_concat(const float* __restrict__ state, const float* __restrict__ action) {
  int b = blockIdx.x, br = blockIdx.y;
  int p = g_invpos[b];
  int fp = g_finparp[p];
  for (int c = threadIdx.x; c < 272; c += blockDim.x) {
    float v;
    if (c < ND)       v = state[(size_t)b * NT * ND + c];
    else if (c == ND) v = action[b];
    else              v = g_h[fp][br][p][c - 16];
    g_xin[br][b][c] = v;
  }
}

// ---------------- FFMA2 tiled GEMM ----------------
template<bool RELU>
__global__ void __launch_bounds__(256)
k_gemm2(const float* __restrict__ A, const float* __restrict__ W,
        const float* __restrict__ bias, float* __restrict__ C,
        int K, int N)
{
  __shared__ float As[16][132];
  __shared__ float Ws[16][68];
  const int bm = blockIdx.x * 128;
  const int bn = blockIdx.y * 64;
  const int tid = threadIdx.x;
  const int mg = tid >> 4;
  const int ng = tid & 15;
  const int m0 = mg * 8;
  const int n0 = ng * 4;

  u64 acc[4][4];
  #pragma unroll
  for (int i = 0; i < 4; ++i)
    #pragma unroll
    for (int j = 0; j < 4; ++j) acc[i][j] = 0ull;

  for (int k0 = 0; k0 < K; k0 += 16) {
    #pragma unroll
    for (int e = 0; e < 2; ++e) {
      int idx = e * 256 + tid;
      int r = idx >> 2, c = idx & 3;
      float4 v = *reinterpret_cast<const float4*>(&A[(size_t)(bm + r) * K + k0 + c * 4]);
      As[c * 4 + 0][r] = v.x; As[c * 4 + 1][r] = v.y;
      As[c * 4 + 2][r] = v.z; As[c * 4 + 3][r] = v.w;
    }
    {
      int r = tid >> 2, c = tid & 3;
      float4 v = *reinterpret_cast<const float4*>(&W[(size_t)(bn + r) * K + k0 + c * 4]);
      Ws[c * 4 + 0][r] = v.x; Ws[c * 4 + 1][r] = v.y;
      Ws[c * 4 + 2][r] = v.z; Ws[c * 4 + 3][r] = v.w;
    }
    __syncthreads();
    #pragma unroll
    for (int k = 0; k < 16; ++k) {
      ulonglong2 a01 = *reinterpret_cast<const ulonglong2*>(&As[k][m0]);
      ulonglong2 a23 = *reinterpret_cast<const ulonglong2*>(&As[k][m0 + 4]);
      float4 wv = *reinterpret_cast<const float4*>(&Ws[k][n0]);
      u64 w2[4];
      w2[0] = splat2(wv.x); w2[1] = splat2(wv.y);
      w2[2] = splat2(wv.z); w2[3] = splat2(wv.w);
      #pragma unroll
      for (int n = 0; n < 4; ++n) {
        ffma2(acc[0][n], a01.x, w2[n]);
        ffma2(acc[1][n], a01.y, w2[n]);
        ffma2(acc[2][n], a23.x, w2[n]);
        ffma2(acc[3][n], a23.y, w2[n]);
      }
    }
    __syncthreads();
  }

  float bs[4];
  #pragma unroll
  for (int n = 0; n < 4; ++n) bs[n] = bias[bn + n0 + n];

  #pragma unroll
  for (int p = 0; p < 4; ++p) {
    float2 v0 = unpk2(acc[p][0]);
    float2 v1 = unpk2(acc[p][1]);
    float2 v2 = unpk2(acc[p][2]);
    float2 v3 = unpk2(acc[p][3]);
    int row = bm + m0 + p * 2;
    float4 lo = make_float4(v0.x + bs[0], v1.x + bs[1], v2.x + bs[2], v3.x + bs[3]);
    float4 hi = make_float4(v0.y + bs[0], v1.y + bs[1], v2.y + bs[2], v3.y + bs[3]);
    if (RELU) {
      lo.x = fmaxf(lo.x, 0.f); lo.y = fmaxf(lo.y, 0.f);
      lo.z = fmaxf(lo.z, 0.f); lo.w = fmaxf(lo.w, 0.f);
      hi.x = fmaxf(hi.x, 0.f); hi.y = fmaxf(hi.y, 0.f);
      hi.z = fmaxf(hi.z, 0.f); hi.w = fmaxf(hi.w, 0.f);
    }
    *reinterpret_cast<float4*>(&C[(size_t)row * N + bn + n0]) = lo;
    *reinterpret_cast<float4*>(&C[(size_t)(row + 1) * N + bn + n0]) = hi;
  }
}

// ---------------- q head ----------------
__global__ void k_q(const float* __restrict__ A, const float* __restrict__ qw,
                    const float* __restrict__ qb, float* __restrict__ out)
{
  __shared__ float red[64];
  int b = blockIdx.x;
  float sum = 0.f;
  for (int c = threadIdx.x; c < 256; c += 64) sum += A[(size_t)b * 256 + c] * qw[c];
  red[threadIdx.x] = sum;
  __syncthreads();
  if (threadIdx.x < 32) {
    float v = red[threadIdx.x] + red[threadIdx.x + 32];
    #pragma unroll
    for (int o = 16; o; o >>= 1) v += __shfl_down_sync(0xffffffffu, v, o);
    if (threadIdx.x == 0) out[b] = v + qb[0];
  }
}

// ---------------- launch ----------------
extern "C" void kernel_launch(void* const* d_in, const int* in_sizes, int n_in,
                              void* d_out, int out_size)
{
  const float* state   = (const float*)d_in[0];
  const float* action  = (const float*)d_in[1];
  const int*   lengths = (const int*)d_in[2];

  const float* gWih[2]; const float* gWhh[2];
  const float* gbih[2]; const float* gbhh[2];
  const float* fcw[2][5]; const float* fcb[2][5];
  for (int br = 0; br < 2; ++br) {
    int base = 3 + br * 14;
    gWih[br] = (const float*)d_in[base + 0];
    gWhh[br] = (const float*)d_in[base + 1];
    gbih[br] = (const float*)d_in[base + 2];
    gbhh[br] = (const float*)d_in[base + 3];
    for (int l = 0; l < 5; ++l) {
      fcw[br][l] = (const float*)d_in[base + 4 + 2 * l];
      fcb[br][l] = (const float*)d_in[base + 5 + 2 * l];
    }
  }

  float *p_xin, *p_a1, *p_a2, *p_a3, *p_a4;
  cudaGetSymbolAddress((void**)&p_xin, g_xin);
  cudaGetSymbolAddress((void**)&p_a1, g_a1);
  cudaGetSymbolAddress((void**)&p_a2, g_a2);
  cudaGetSymbolAddress((void**)&p_a3, g_a3);
  cudaGetSymbolAddress((void**)&p_a4, g_a4);

  cudaFuncSetAttribute(k_gru_step, cudaFuncAttributeMaxDynamicSharedMemorySize,
                       (int)sizeof(GruS));

  // prep
  k_sort<<<1, 1024>>>(lengths);
  k_prep<<<(WHH_N + 8 * 3136 + 255) / 256, 256>>>(gWhh[0], gWhh[1],
                                                  gWih[0], gbih[0], gbhh[0],
                                                  gWih[1], gbih[1], gbhh[1]);

  // recurrent steps
  for (int t = 0; t < NT; ++t) {
    k_gru_step<<<dim3(NBT, 4, 2), THR, sizeof(GruS)>>>(state, t);
  }

  k_concat<<<dim3(NB, 2), 128>>>(state, action);

  float* outp = (float*)d_out;
  for (int br = 0; br < 2; ++br) {
    float* xin = p_xin + (size_t)br * NB * 272;
    float* a1  = p_a1  + (size_t)br * NB * 1024;
    float* a2  = p_a2  + (size_t)br * NB * 1024;
    float* a3  = p_a3  + (size_t)br * NB * 512;
    float* a4  = p_a4  + (size_t)br * NB * 256;
    k_gemm2<true><<<dim3(16, 16), 256>>>(xin, fcw[br][0], fcb[br][0], a1, 272, 1024);
    k_gemm2<true><<<dim3(16, 16), 256>>>(a1,  fcw[br][1], fcb[br][1], a2, 1024, 1024);
    k_gemm2<true><<<dim3(16,  8), 256>>>(a2,  fcw[br][2], fcb[br][2], a3, 1024, 512);
    k_gemm2<true><<<dim3(16,  4), 256>>>(a3,  fcw[br][3], fcb[br][3], a4, 512, 256);
    k_q<<<NB, 64>>>(a4, fcw[br][4], fcb[br][4], outp + (size_t)br * NB);
  }
}

// round 8
// speedup vs baseline: 1.2945x; 1.2945x over previous
#include <cuda_runtime.h>
#include <math.h>

#define NB 2048
#define NT 64
#define ND 15
#define NH 256
#define TB 64        // batch rows per GRU CTA (sorted tile)
#define NBT 32       // NB / TB
#define THR 128
#define WHH_N (2 * 4 * 256 * 192)

typedef unsigned long long u64;

// ---------------- f32x2 packed-FMA helpers ----------------
__device__ __forceinline__ void ffma2(u64& d, u64 a, u64 b) {
  asm("fma.rn.f32x2 %0, %1, %2, %3;" : "=l"(d) : "l"(a), "l"(b), "l"(d));
}
__device__ __forceinline__ u64 splat2(float w) {
  u64 d; asm("mov.b64 %0, {%1, %1};" : "=l"(d) : "f"(w)); return d;
}
__device__ __forceinline__ float2 unpk2(u64 v) {
  float2 r; asm("mov.b64 {%0, %1}, %2;" : "=f"(r.x), "=f"(r.y) : "l"(v)); return r;
}

// ---------------- mbarrier / bulk-copy helpers ----------------
__device__ __forceinline__ unsigned smem_u32(const void* p) {
  unsigned a;
  asm("{ .reg .u64 t; cvta.to.shared.u64 t, %1; cvt.u32.u64 %0, t; }" : "=r"(a) : "l"(p));
  return a;
}
__device__ __forceinline__ void mbar_init(unsigned mbar, unsigned cnt) {
  asm volatile("mbarrier.init.shared.b64 [%0], %1;" :: "r"(mbar), "r"(cnt) : "memory");
}
__device__ __forceinline__ void mbar_expect(unsigned mbar, unsigned bytes) {
  asm volatile("mbarrier.arrive.expect_tx.shared.b64 _, [%0], %1;"
               :: "r"(mbar), "r"(bytes) : "memory");
}
__device__ __forceinline__ void bulk_g2s(unsigned dst, const void* src,
                                         unsigned bytes, unsigned mbar) {
  asm volatile(
      "cp.async.bulk.shared::cta.global.mbarrier::complete_tx::bytes [%0], [%1], %2, [%3];"
      :: "r"(dst), "l"(src), "r"(bytes), "r"(mbar) : "memory");
}
__device__ __forceinline__ void mbar_wait(unsigned mbar, unsigned parity) {
  asm volatile(
      "{\n\t.reg .pred P;\n\t"
      "W%=:\n\t"
      "mbarrier.try_wait.parity.acquire.cta.shared::cta.b64 P, [%0], %1, 0x989680;\n\t"
      "@P bra.uni D%=;\n\t"
      "bra.uni W%=;\n\t"
      "D%=:\n\t}"
      :: "r"(mbar), "r"(parity) : "memory");
}

// ---------------- device scratch ----------------
__device__ float g_h[2][2][NB][NH];          // [parity][gru][sorted_pos][h]
__device__ float g_whhB[WHH_N];              // [g][jt][k][gate*64+c]
__device__ float g_wblk[8][3136];            // [g*4+jt]{ wihT[15][192], cbA[192], cbHn[64] }
__device__ float g_xin[2][NB][272];
__device__ float g_a1[2][NB][1024];
__device__ float g_a2[2][NB][1024];
__device__ float g_a3[2][NB][512];
__device__ float g_a4[2][NB][256];
__device__ int   g_perm[NB];
__device__ int   g_off[66];
__device__ int   g_hist[66];
__device__ int   g_tilemax[NBT];
__device__ int   g_invpos[NB];
__device__ int   g_finparp[NB];
__device__ int   g_lsort[NB];

// ---------------- fused length sort (single block) ----------------
__global__ void k_sort(const int* __restrict__ lengths) {
  int tid = threadIdx.x;
  if (tid < 66) g_hist[tid] = 0;
  __syncthreads();
  for (int b = tid; b < NB; b += 1024) atomicAdd(&g_hist[lengths[b]], 1);
  __syncthreads();
  if (tid == 0) {
    int s = 0;
    for (int l = 0; l < 66; ++l) { g_off[l] = s; s += g_hist[l]; }
  }
  __syncthreads();
  for (int b = tid; b < NB; b += 1024) {
    int p = atomicAdd(&g_off[lengths[b]], 1);
    g_perm[p] = b;
  }
  __syncthreads();
  if (tid < NBT) g_tilemax[tid] = lengths[g_perm[tid * TB + TB - 1]];
  __syncthreads();
  for (int p = tid; p < NB; p += 1024) {
    int b = g_perm[p];
    g_invpos[b] = p;
    g_finparp[p] = g_tilemax[p >> 6] & 1;
    g_lsort[p] = lengths[b];
  }
}

// ---------------- fused weight prep ----------------
__global__ void k_prep(const float* __restrict__ Whh0, const float* __restrict__ Whh1,
                       const float* __restrict__ Wih0, const float* __restrict__ bih0,
                       const float* __restrict__ bhh0,
                       const float* __restrict__ Wih1, const float* __restrict__ bih1,
                       const float* __restrict__ bhh1) {
  int i = blockIdx.x * blockDim.x + threadIdx.x;
  if (i < WHH_N) {
    int c  = i % 192;
    int k  = (i / 192) % 256;
    int jt = (i / (192 * 256)) & 3;
    int g  = i / (192 * 256 * 4);
    const float* W = g ? Whh1 : Whh0;
    int gg = c >> 6, cc = c & 63;
    g_whhB[i] = W[(size_t)(gg * 256 + jt * 64 + cc) * 256 + k];
    return;
  }
  int j = i - WHH_N;
  if (j >= 8 * 3136) return;
  int o  = j % 3136;
  int jt = (j / 3136) & 3;
  int g  = j / (3136 * 4);
  const float* Wih = g ? Wih1 : Wih0;
  const float* bih = g ? bih1 : bih0;
  const float* bhh = g ? bhh1 : bhh0;
  float v;
  if (o < 2880) {
    int k = o / 192, c = o % 192;
    int gg = c >> 6, cc = c & 63;
    v = Wih[(size_t)(gg * 256 + jt * 64 + cc) * ND + k];
  } else if (o < 3072) {
    int c = o - 2880;
    int gg = c >> 6, cc = c & 63;
    int row = gg * 256 + jt * 64 + cc;
    v = (gg < 2) ? (bih[row] + bhh[row]) : bih[row];
  } else {
    v = bhh[512 + jt * 64 + (o - 3072)];
  }
  g_wblk[g * 4 + jt][o] = v;
}

// ---------------- GRU step kernel (LDG-direct weights, 8b x 4c per thread) ----------------
struct GruS {
  float hs[TB][256];       // 65536 B (one bulk copy)
  u64   aIsp[THR][8][2];   // 16384 B: parked input-gate n accumulators
  float xs[TB][ND];
  int   ls[TB];
  u64   mb[2];
};

__global__ void __launch_bounds__(THR, 2)
k_gru_step(const float* __restrict__ state, int t)
{
  extern __shared__ char sraw[];
  GruS& s = *reinterpret_cast<GruS*>(sraw);
  const int bt = blockIdx.x, jt = blockIdx.y, g = blockIdx.z;
  const int tid = threadIdx.x;
  const int pi = t & 1, po = pi ^ 1;

  if (t >= g_tilemax[bt]) return;   // frozen tile

  const unsigned mb_h = smem_u32(&s.mb[0]);
  const int gjt = g * 4 + jt;
  const float* __restrict__ wp = g_whhB + (size_t)gjt * 256 * 192;
  const float* __restrict__ wi = &g_wblk[gjt][0];

  if (tid == 0) mbar_init(mb_h, 1);
  __syncthreads();
  if (tid == 0 && t > 0) {
    mbar_expect(mb_h, 65536u);
    bulk_g2s(smem_u32(&s.hs[0][0]), &g_h[pi][g][bt * TB][0], 65536u, mb_h);
  }

  // x gather + lengths (overlaps h TMA flight)
  for (int i = tid; i < TB * ND; i += THR) {
    int b = i / ND, c = i % ND;
    s.xs[b][c] = state[((size_t)g_perm[bt * TB + b] * NT + t) * ND + c];
  }
  if (tid < TB) s.ls[tid] = g_lsort[bt * TB + tid];
  __syncthreads();

  const int cg = tid & 15;   // 16 col groups x 4 cols
  const int bg = tid >> 4;   // 8 batch groups x 8 rows
  const int b0 = bg * 8;
  const int c4 = cg * 4;

  // accumulators: [batch row][col pair] packed f32x2 (aI parked in smem for the loop)
  u64 aR[8][2], aZ[8][2], aN[8][2];
  {
    ulonglong2 bR = *reinterpret_cast<const ulonglong2*>(wi + 2880 + c4);
    ulonglong2 bZ = *reinterpret_cast<const ulonglong2*>(wi + 2944 + c4);
    ulonglong2 bN = *reinterpret_cast<const ulonglong2*>(wi + 3072 + c4);
    #pragma unroll
    for (int i = 0; i < 8; ++i) {
      aR[i][0] = bR.x; aR[i][1] = bR.y;
      aZ[i][0] = bZ.x; aZ[i][1] = bZ.y;
      aN[i][0] = bN.x; aN[i][1] = bN.y;
    }
  }
  // input-gate n-term accumulators live briefly in aI then go to smem
  {
    u64 aI[8][2];
    ulonglong2 bI = *reinterpret_cast<const ulonglong2*>(wi + 3008 + c4);
    #pragma unroll
    for (int i = 0; i < 8; ++i) { aI[i][0] = bI.x; aI[i][1] = bI.y; }
    #pragma unroll
    for (int k = 0; k < ND; ++k) {
      const float* row = wi + k * 192;
      ulonglong2 wr = *reinterpret_cast<const ulonglong2*>(row + c4);
      ulonglong2 wz = *reinterpret_cast<const ulonglong2*>(row + 64 + c4);
      ulonglong2 wn = *reinterpret_cast<const ulonglong2*>(row + 128 + c4);
      #pragma unroll
      for (int i = 0; i < 8; ++i) {
        u64 xv = splat2(s.xs[b0 + i][k]);
        ffma2(aR[i][0], xv, wr.x); ffma2(aR[i][1], xv, wr.y);
        ffma2(aZ[i][0], xv, wz.x); ffma2(aZ[i][1], xv, wz.y);
        ffma2(aI[i][0], xv, wn.x); ffma2(aI[i][1], xv, wn.y);
      }
    }
    #pragma unroll
    for (int i = 0; i < 8; ++i) {
      s.aIsp[tid][i][0] = aI[i][0];
      s.aIsp[tid][i][1] = aI[i][1];
    }
  }

  // recurrent contribution (K = 256): LDG->regs, distance-4 pipeline (4 buffer sets)
  if (t > 0) {
    mbar_wait(mb_h, 0);
    ulonglong2 fr[4], fz[4], fn[4];
    const float* rowp = wp;
    #pragma unroll
    for (int p = 0; p < 4; ++p) {
      fr[p] = *reinterpret_cast<const ulonglong2*>(rowp + c4);
      fz[p] = *reinterpret_cast<const ulonglong2*>(rowp + 64 + c4);
      fn[p] = *reinterpret_cast<const ulonglong2*>(rowp + 128 + c4);
      rowp += 192;
    }
    // rowp now at row 4 = prefetch target for kk=0
    for (int kc = 0; kc < 256; kc += 4) {
      #pragma unroll
      for (int u = 0; u < 4; ++u) {
        const int kk = kc + u;
        ulonglong2 wr = fr[u], wz = fz[u], wn = fn[u];
        const float* pf = (kk + 4 < 256) ? rowp : (wp + 255 * 192);
        fr[u] = *reinterpret_cast<const ulonglong2*>(pf + c4);
        fz[u] = *reinterpret_cast<const ulonglong2*>(pf + 64 + c4);
        fn[u] = *reinterpret_cast<const ulonglong2*>(pf + 128 + c4);
        rowp += 192;
        #pragma unroll
        for (int i = 0; i < 8; ++i) {
          u64 hv = splat2(s.hs[b0 + i][kk]);
          ffma2(aR[i][0], hv, wr.x); ffma2(aR[i][1], hv, wr.y);
          ffma2(aZ[i][0], hv, wz.x); ffma2(aZ[i][1], hv, wz.y);
          ffma2(aN[i][0], hv, wn.x); ffma2(aN[i][1], hv, wn.y);
        }
      }
    }
  }

  // gates + masked update + write
  #pragma unroll
  for (int i = 0; i < 8; ++i) {
    bool act = (t < s.ls[b0 + i]);
    float2 r0 = unpk2(aR[i][0]), r1 = unpk2(aR[i][1]);
    float2 z0 = unpk2(aZ[i][0]), z1 = unpk2(aZ[i][1]);
    float2 i0 = unpk2(s.aIsp[tid][i][0]), i1 = unpk2(s.aIsp[tid][i][1]);
    float2 n0 = unpk2(aN[i][0]), n1 = unpk2(aN[i][1]);
    float xr[4] = {r0.x, r0.y, r1.x, r1.y};
    float xz[4] = {z0.x, z0.y, z1.x, z1.y};
    float xi[4] = {i0.x, i0.y, i1.x, i1.y};
    float xn[4] = {n0.x, n0.y, n1.x, n1.y};
    float o[4];
    #pragma unroll
    for (int e = 0; e < 4; ++e) {
      float r = __fdividef(1.f, 1.f + __expf(-xr[e]));
      float z = __fdividef(1.f, 1.f + __expf(-xz[e]));
      float n = tanhf(fmaf(r, xn[e], xi[e]));
      float hold = (t > 0) ? s.hs[b0 + i][jt * 64 + c4 + e] : 0.f;
      o[e] = act ? fmaf(z, hold - n, n) : hold;
    }
    *reinterpret_cast<float4*>(&g_h[po][g][bt * TB + b0 + i][jt * 64 + c4]) =
        make_float4(o[0], o[1], o[2], o[3]);
  }
}

// ---------------- concat [state(:,0,:), action, h] ----------------
__global__ void k_concat(const float* __restrict__ state, const float* __restrict__ action) {
  int b = blockIdx.x, br = blockIdx.y;
  int p = g_invpos[b];
  int fp = g_finparp[p];
  for (int c = threadIdx.x; c < 272; c += blockDim.x) {
    float v;
    if (c < ND)       v = state[(size_t)b * NT * ND + c];
    else if (c == ND) v = action[b];
    else              v = g_h[fp][br][p][c - 16];
    g_xin[br][b][c] = v;
  }
}

// ---------------- FFMA2 tiled GEMM ----------------
template<bool RELU>
__global__ void __launch_bounds__(256)
k_gemm2(const float* __restrict__ A, const float* __restrict__ W,
        const float* __restrict__ bias, float* __restrict__ C,
        int K, int N)
{
  __shared__ float As[16][132];
  __shared__ float Ws[16][68];
  const int bm = blockIdx.x * 128;
  const int bn = blockIdx.y * 64;
  const int tid = threadIdx.x;
  const int mg = tid >> 4;
  const int ng = tid & 15;
  const int m0 = mg * 8;
  const int n0 = ng * 4;

  u64 acc[4][4];
  #pragma unroll
  for (int i = 0; i < 4; ++i)
    #pragma unroll
    for (int j = 0; j < 4; ++j) acc[i][j] = 0ull;

  for (int k0 = 0; k0 < K; k0 += 16) {
    #pragma unroll
    for (int e = 0; e < 2; ++e) {
      int idx = e * 256 + tid;
      int r = idx >> 2, c = idx & 3;
      float4 v = *reinterpret_cast<const float4*>(&A[(size_t)(bm + r) * K + k0 + c * 4]);
      As[c * 4 + 0][r] = v.x; As[c * 4 + 1][r] = v.y;
      As[c * 4 + 2][r] = v.z; As[c * 4 + 3][r] = v.w;
    }
    {
      int r = tid >> 2, c = tid & 3;
      float4 v = *reinterpret_cast<const float4*>(&W[(size_t)(bn + r) * K + k0 + c * 4]);
      Ws[c * 4 + 0][r] = v.x; Ws[c * 4 + 1][r] = v.y;
      Ws[c * 4 + 2][r] = v.z; Ws[c * 4 + 3][r] = v.w;
    }
    __syncthreads();
    #pragma unroll
    for (int k = 0; k < 16; ++k) {
      ulonglong2 a01 = *reinterpret_cast<const ulonglong2*>(&As[k][m0]);
      ulonglong2 a23 = *reinterpret_cast<const ulonglong2*>(&As[k][m0 + 4]);
      float4 wv = *reinterpret_cast<const float4*>(&Ws[k][n0]);
      u64 w2[4];
      w2[0] = splat2(wv.x); w2[1] = splat2(wv.y);
      w2[2] = splat2(wv.z); w2[3] = splat2(wv.w);
      #pragma unroll
      for (int n = 0; n < 4; ++n) {
        ffma2(acc[0][n], a01.x, w2[n]);
        ffma2(acc[1][n], a01.y, w2[n]);
        ffma2(acc[2][n], a23.x, w2[n]);
        ffma2(acc[3][n], a23.y, w2[n]);
      }
    }
    __syncthreads();
  }

  float bs[4];
  #pragma unroll
  for (int n = 0; n < 4; ++n) bs[n] = bias[bn + n0 + n];

  #pragma unroll
  for (int p = 0; p < 4; ++p) {
    float2 v0 = unpk2(acc[p][0]);
    float2 v1 = unpk2(acc[p][1]);
    float2 v2 = unpk2(acc[p][2]);
    float2 v3 = unpk2(acc[p][3]);
    int row = bm + m0 + p * 2;
    float4 lo = make_float4(v0.x + bs[0], v1.x + bs[1], v2.x + bs[2], v3.x + bs[3]);
    float4 hi = make_float4(v0.y + bs[0], v1.y + bs[1], v2.y + bs[2], v3.y + bs[3]);
    if (RELU) {
      lo.x = fmaxf(lo.x, 0.f); lo.y = fmaxf(lo.y, 0.f);
      lo.z = fmaxf(lo.z, 0.f); lo.w = fmaxf(lo.w, 0.f);
      hi.x = fmaxf(hi.x, 0.f); hi.y = fmaxf(hi.y, 0.f);
      hi.z = fmaxf(hi.z, 0.f); hi.w = fmaxf(hi.w, 0.f);
    }
    *reinterpret_cast<float4*>(&C[(size_t)row * N + bn + n0]) = lo;
    *reinterpret_cast<float4*>(&C[(size_t)(row + 1) * N + bn + n0]) = hi;
  }
}

// ---------------- q head ----------------
__global__ void k_q(const float* __restrict__ A, const float* __restrict__ qw,
                    const float* __restrict__ qb, float* __restrict__ out)
{
  __shared__ float red[64];
  int b = blockIdx.x;
  float sum = 0.f;
  for (int c = threadIdx.x; c < 256; c += 64) sum += A[(size_t)b * 256 + c] * qw[c];
  red[threadIdx.x] = sum;
  __syncthreads();
  if (threadIdx.x < 32) {
    float v = red[threadIdx.x] + red[threadIdx.x + 32];
    #pragma unroll
    for (int o = 16; o; o >>= 1) v += __shfl_down_sync(0xffffffffu, v, o);
    if (threadIdx.x == 0) out[b] = v + qb[0];
  }
}

// ---------------- launch ----------------
extern "C" void kernel_launch(void* const* d_in, const int* in_sizes, int n_in,
                              void* d_out, int out_size)
{
  const float* state   = (const float*)d_in[0];
  const float* action  = (const float*)d_in[1];
  const int*   lengths = (const int*)d_in[2];

  const float* gWih[2]; const float* gWhh[2];
  const float* gbih[2]; const float* gbhh[2];
  const float* fcw[2][5]; const float* fcb[2][5];
  for (int br = 0; br < 2; ++br) {
    int base = 3 + br * 14;
    gWih[br] = (const float*)d_in[base + 0];
    gWhh[br] = (const float*)d_in[base + 1];
    gbih[br] = (const float*)d_in[base + 2];
    gbhh[br] = (const float*)d_in[base + 3];
    for (int l = 0; l < 5; ++l) {
      fcw[br][l] = (const float*)d_in[base + 4 + 2 * l];
      fcb[br][l] = (const float*)d_in[base + 5 + 2 * l];
    }
  }

  float *p_xin, *p_a1, *p_a2, *p_a3, *p_a4;
  cudaGetSymbolAddress((void**)&p_xin, g_xin);
  cudaGetSymbolAddress((void**)&p_a1, g_a1);
  cudaGetSymbolAddress((void**)&p_a2, g_a2);
  cudaGetSymbolAddress((void**)&p_a3, g_a3);
  cudaGetSymbolAddress((void**)&p_a4, g_a4);

  cudaFuncSetAttribute(k_gru_step, cudaFuncAttributeMaxDynamicSharedMemorySize,
                       (int)sizeof(GruS));

  // prep
  k_sort<<<1, 1024>>>(lengths);
  k_prep<<<(WHH_N + 8 * 3136 + 255) / 256, 256>>>(gWhh[0], gWhh[1],
                                                  gWih[0], gbih[0], gbhh[0],
                                                  gWih[1], gbih[1], gbhh[1]);

  // recurrent steps
  for (int t = 0; t < NT; ++t) {
    k_gru_step<<<dim3(NBT, 4, 2), THR, sizeof(GruS)>>>(state, t);
  }

  k_concat<<<dim3(NB, 2), 128>>>(state, action);

  float* outp = (float*)d_out;
  for (int br = 0; br < 2; ++br) {
    float* xin = p_xin + (size_t)br * NB * 272;
    float* a1  = p_a1  + (size_t)br * NB * 1024;
    float* a2  = p_a2  + (size_t)br * NB * 1024;
    float* a3  = p_a3  + (size_t)br * NB * 512;
    float* a4  = p_a4  + (size_t)br * NB * 256;
    k_gemm2<true><<<dim3(16, 16), 256>>>(xin, fcw[br][0], fcb[br][0], a1, 272, 1024);
    k_gemm2<true><<<dim3(16, 16), 256>>>(a1,  fcw[br][1], fcb[br][1], a2, 1024, 1024);
    k_gemm2<true><<<dim3(16,  8), 256>>>(a2,  fcw[br][2], fcb[br][2], a3, 1024, 512);
    k_gemm2<true><<<dim3(16,  4), 256>>>(a3,  fcw[br][3], fcb[br][3], a4, 512, 256);
    k_q<<<NB, 64>>>(a4, fcw[br][4], fcb[br][4], outp + (size_t)br * NB);
  }
}

// round 9
// speedup vs baseline: 1.3559x; 1.0474x over previous
#include <cuda_runtime.h>
#include <math.h>

#define NB 2048
#define NT 64
#define ND 15
#define NH 256
#define TB 64        // batch rows per GRU CTA (sorted tile)
#define NBT 32       // NB / TB
#define THR 256
#define WHH_N (2 * 4 * 256 * 192)

typedef unsigned long long u64;

// ---------------- f32x2 packed-FMA helpers ----------------
__device__ __forceinline__ void ffma2(u64& d, u64 a, u64 b) {
  asm("fma.rn.f32x2 %0, %1, %2, %3;" : "=l"(d) : "l"(a), "l"(b), "l"(d));
}
__device__ __forceinline__ u64 splat2(float w) {
  u64 d; asm("mov.b64 %0, {%1, %1};" : "=l"(d) : "f"(w)); return d;
}
__device__ __forceinline__ float2 unpk2(u64 v) {
  float2 r; asm("mov.b64 {%0, %1}, %2;" : "=f"(r.x), "=f"(r.y) : "l"(v)); return r;
}

// ---------------- mbarrier / bulk-copy helpers ----------------
__device__ __forceinline__ unsigned smem_u32(const void* p) {
  unsigned a;
  asm("{ .reg .u64 t; cvta.to.shared.u64 t, %1; cvt.u32.u64 %0, t; }" : "=r"(a) : "l"(p));
  return a;
}
__device__ __forceinline__ void mbar_init(unsigned mbar, unsigned cnt) {
  asm volatile("mbarrier.init.shared.b64 [%0], %1;" :: "r"(mbar), "r"(cnt) : "memory");
}
__device__ __forceinline__ void mbar_expect(unsigned mbar, unsigned bytes) {
  asm volatile("mbarrier.arrive.expect_tx.shared.b64 _, [%0], %1;"
               :: "r"(mbar), "r"(bytes) : "memory");
}
__device__ __forceinline__ void bulk_g2s(unsigned dst, const void* src,
                                         unsigned bytes, unsigned mbar) {
  asm volatile(
      "cp.async.bulk.shared::cta.global.mbarrier::complete_tx::bytes [%0], [%1], %2, [%3];"
      :: "r"(dst), "l"(src), "r"(bytes), "r"(mbar) : "memory");
}
__device__ __forceinline__ void mbar_wait(unsigned mbar, unsigned parity) {
  asm volatile(
      "{\n\t.reg .pred P;\n\t"
      "W%=:\n\t"
      "mbarrier.try_wait.parity.acquire.cta.shared::cta.b64 P, [%0], %1, 0x989680;\n\t"
      "@P bra.uni D%=;\n\t"
      "bra.uni W%=;\n\t"
      "D%=:\n\t}"
      :: "r"(mbar), "r"(parity) : "memory");
}

// ---------------- device scratch ----------------
__device__ float g_h[2][2][NB][NH];          // [parity][gru][sorted_pos][h]
__device__ float g_whhB[WHH_N];              // [g][jt][k][gate*64+c]
__device__ float g_wblk[8][3136];            // [g*4+jt]{ wihT[15][192], cbA[192], cbHn[64] }
__device__ float g_xin[2][NB][272];
__device__ float g_a1[2][NB][1024];
__device__ float g_a2[2][NB][1024];
__device__ float g_a3[2][NB][512];
__device__ float g_a4[2][NB][256];
__device__ int   g_perm[NB];
__device__ int   g_off[66];
__device__ int   g_hist[66];
__device__ int   g_tilemax[NBT];
__device__ int   g_invpos[NB];
__device__ int   g_finparp[NB];
__device__ int   g_lsort[NB];

// ---------------- fused length sort (single block) ----------------
__global__ void k_sort(const int* __restrict__ lengths) {
  int tid = threadIdx.x;
  if (tid < 66) g_hist[tid] = 0;
  __syncthreads();
  for (int b = tid; b < NB; b += 1024) atomicAdd(&g_hist[lengths[b]], 1);
  __syncthreads();
  if (tid == 0) {
    int s = 0;
    for (int l = 0; l < 66; ++l) { g_off[l] = s; s += g_hist[l]; }
  }
  __syncthreads();
  for (int b = tid; b < NB; b += 1024) {
    int p = atomicAdd(&g_off[lengths[b]], 1);
    g_perm[p] = b;
  }
  __syncthreads();
  if (tid < NBT) g_tilemax[tid] = lengths[g_perm[tid * TB + TB - 1]];
  __syncthreads();
  for (int p = tid; p < NB; p += 1024) {
    int b = g_perm[p];
    g_invpos[b] = p;
    g_finparp[p] = g_tilemax[p >> 6] & 1;
    g_lsort[p] = lengths[b];
  }
}

// ---------------- fused weight prep ----------------
__global__ void k_prep(const float* __restrict__ Whh0, const float* __restrict__ Whh1,
                       const float* __restrict__ Wih0, const float* __restrict__ bih0,
                       const float* __restrict__ bhh0,
                       const float* __restrict__ Wih1, const float* __restrict__ bih1,
                       const float* __restrict__ bhh1) {
  int i = blockIdx.x * blockDim.x + threadIdx.x;
  if (i < WHH_N) {
    int c  = i % 192;
    int k  = (i / 192) % 256;
    int jt = (i / (192 * 256)) & 3;
    int g  = i / (192 * 256 * 4);
    const float* W = g ? Whh1 : Whh0;
    int gg = c >> 6, cc = c & 63;
    g_whhB[i] = W[(size_t)(gg * 256 + jt * 64 + cc) * 256 + k];
    return;
  }
  int j = i - WHH_N;
  if (j >= 8 * 3136) return;
  int o  = j % 3136;
  int jt = (j / 3136) & 3;
  int g  = j / (3136 * 4);
  const float* Wih = g ? Wih1 : Wih0;
  const float* bih = g ? bih1 : bih0;
  const float* bhh = g ? bhh1 : bhh0;
  float v;
  if (o < 2880) {
    int k = o / 192, c = o % 192;
    int gg = c >> 6, cc = c & 63;
    v = Wih[(size_t)(gg * 256 + jt * 64 + cc) * ND + k];
  } else if (o < 3072) {
    int c = o - 2880;
    int gg = c >> 6, cc = c & 63;
    int row = gg * 256 + jt * 64 + cc;
    v = (gg < 2) ? (bih[row] + bhh[row]) : bih[row];
  } else {
    v = bhh[512 + jt * 64 + (o - 3072)];
  }
  g_wblk[g * 4 + jt][o] = v;
}

// ---------------- GRU step kernel (LDG-direct weights, 4b x 4c per thread, 256 thr) ----------------
struct GruS {
  float hs[TB][256];   // 65536 B (one bulk copy)
  float xs[TB][ND];
  int   ls[TB];
  u64   mb[2];
};

__global__ void __launch_bounds__(THR, 2)
k_gru_step(const float* __restrict__ state, int t)
{
  extern __shared__ char sraw[];
  GruS& s = *reinterpret_cast<GruS*>(sraw);
  const int bt = blockIdx.x, jt = blockIdx.y, g = blockIdx.z;
  const int tid = threadIdx.x;
  const int pi = t & 1, po = pi ^ 1;

  if (t >= g_tilemax[bt]) return;   // frozen tile

  const unsigned mb_h = smem_u32(&s.mb[0]);
  const int gjt = g * 4 + jt;
  const float* __restrict__ wp = g_whhB + (size_t)gjt * 256 * 192;
  const float* __restrict__ wi = &g_wblk[gjt][0];

  if (tid == 0) mbar_init(mb_h, 1);
  __syncthreads();
  if (tid == 0 && t > 0) {
    mbar_expect(mb_h, 65536u);
    bulk_g2s(smem_u32(&s.hs[0][0]), &g_h[pi][g][bt * TB][0], 65536u, mb_h);
  }

  // x gather + lengths (overlaps h TMA flight)
  for (int i = tid; i < TB * ND; i += THR) {
    int b = i / ND, c = i % ND;
    s.xs[b][c] = state[((size_t)g_perm[bt * TB + b] * NT + t) * ND + c];
  }
  if (tid < TB) s.ls[tid] = g_lsort[bt * TB + tid];
  __syncthreads();

  const int cg = tid & 15;   // 16 col groups x 4 cols
  const int bg = tid >> 4;   // 16 row groups x 4 rows
  const int b0 = bg * 4;
  const int c4 = cg * 4;

  // accumulators: [batch row][col pair] packed f32x2
  u64 aR[4][2], aZ[4][2], aI[4][2], aN[4][2];
  {
    ulonglong2 bR = *reinterpret_cast<const ulonglong2*>(wi + 2880 + c4);
    ulonglong2 bZ = *reinterpret_cast<const ulonglong2*>(wi + 2944 + c4);
    ulonglong2 bI = *reinterpret_cast<const ulonglong2*>(wi + 3008 + c4);
    ulonglong2 bN = *reinterpret_cast<const ulonglong2*>(wi + 3072 + c4);
    #pragma unroll
    for (int i = 0; i < 4; ++i) {
      aR[i][0] = bR.x; aR[i][1] = bR.y;
      aZ[i][0] = bZ.x; aZ[i][1] = bZ.y;
      aI[i][0] = bI.x; aI[i][1] = bI.y;
      aN[i][0] = bN.x; aN[i][1] = bN.y;
    }
  }

  // input-gate contribution (K = 15)
  #pragma unroll
  for (int k = 0; k < ND; ++k) {
    const float* row = wi + k * 192;
    ulonglong2 wr = *reinterpret_cast<const ulonglong2*>(row + c4);
    ulonglong2 wz = *reinterpret_cast<const ulonglong2*>(row + 64 + c4);
    ulonglong2 wn = *reinterpret_cast<const ulonglong2*>(row + 128 + c4);
    #pragma unroll
    for (int i = 0; i < 4; ++i) {
      u64 xv = splat2(s.xs[b0 + i][k]);
      ffma2(aR[i][0], xv, wr.x); ffma2(aR[i][1], xv, wr.y);
      ffma2(aZ[i][0], xv, wz.x); ffma2(aZ[i][1], xv, wz.y);
      ffma2(aI[i][0], xv, wn.x); ffma2(aI[i][1], xv, wn.y);
    }
  }

  // recurrent contribution (K = 256): LDG->regs, distance-2 pipeline
  if (t > 0) {
    mbar_wait(mb_h, 0);
    ulonglong2 fr[2], fz[2], fn[2];
    const float* rowp = wp;
    #pragma unroll
    for (int p = 0; p < 2; ++p) {
      fr[p] = *reinterpret_cast<const ulonglong2*>(rowp + c4);
      fz[p] = *reinterpret_cast<const ulonglong2*>(rowp + 64 + c4);
      fn[p] = *reinterpret_cast<const ulonglong2*>(rowp + 128 + c4);
      rowp += 192;
    }
    for (int kc = 0; kc < 256; kc += 2) {
      #pragma unroll
      for (int u = 0; u < 2; ++u) {
        const int kk = kc + u;
        ulonglong2 wr = fr[u], wz = fz[u], wn = fn[u];
        const float* pf = (kk + 2 < 256) ? rowp : (wp + 255 * 192);
        fr[u] = *reinterpret_cast<const ulonglong2*>(pf + c4);
        fz[u] = *reinterpret_cast<const ulonglong2*>(pf + 64 + c4);
        fn[u] = *reinterpret_cast<const ulonglong2*>(pf + 128 + c4);
        rowp += 192;
        #pragma unroll
        for (int i = 0; i < 4; ++i) {
          u64 hv = splat2(s.hs[b0 + i][kk]);
          ffma2(aR[i][0], hv, wr.x); ffma2(aR[i][1], hv, wr.y);
          ffma2(aZ[i][0], hv, wz.x); ffma2(aZ[i][1], hv, wz.y);
          ffma2(aN[i][0], hv, wn.x); ffma2(aN[i][1], hv, wn.y);
        }
      }
    }
  }

  // gates + masked update + write
  #pragma unroll
  for (int i = 0; i < 4; ++i) {
    bool act = (t < s.ls[b0 + i]);
    float2 r0 = unpk2(aR[i][0]), r1 = unpk2(aR[i][1]);
    float2 z0 = unpk2(aZ[i][0]), z1 = unpk2(aZ[i][1]);
    float2 i0 = unpk2(aI[i][0]), i1 = unpk2(aI[i][1]);
    float2 n0 = unpk2(aN[i][0]), n1 = unpk2(aN[i][1]);
    float xr[4] = {r0.x, r0.y, r1.x, r1.y};
    float xz[4] = {z0.x, z0.y, z1.x, z1.y};
    float xi[4] = {i0.x, i0.y, i1.x, i1.y};
    float xn[4] = {n0.x, n0.y, n1.x, n1.y};
    float o[4];
    #pragma unroll
    for (int e = 0; e < 4; ++e) {
      float r = __fdividef(1.f, 1.f + __expf(-xr[e]));
      float z = __fdividef(1.f, 1.f + __expf(-xz[e]));
      float n = tanhf(fmaf(r, xn[e], xi[e]));
      float hold = (t > 0) ? s.hs[b0 + i][jt * 64 + c4 + e] : 0.f;
      o[e] = act ? fmaf(z, hold - n, n) : hold;
    }
    *reinterpret_cast<float4*>(&g_h[po][g][bt * TB + b0 + i][jt * 64 + c4]) =
        make_float4(o[0], o[1], o[2], o[3]);
  }
}

// ---------------- concat [state(:,0,:), action, h] ----------------
__global__ void k_concat(const float* __restrict__ state, const float* __restrict__ action) {
  int b = blockIdx.x, br = blockIdx.y;
  int p = g_invpos[b];
  int fp = g_finparp[p];
  for (int c = threadIdx.x; c < 272; c += blockDim.x) {
    float v;
    if (c < ND)       v = state[(size_t)b * NT * ND + c];
    else if (c == ND) v = action[b];
    else              v = g_h[fp][br][p][c - 16];
    g_xin[br][b][c] = v;
  }
}

// ---------------- FFMA2 tiled GEMM ----------------
template<bool RELU>
__global__ void __launch_bounds__(256)
k_gemm2(const float* __restrict__ A, const float* __restrict__ W,
        const float* __restrict__ bias, float* __restrict__ C,
        int K, int N)
{
  __shared__ float As[16][132];
  __shared__ float Ws[16][68];
  const int bm = blockIdx.x * 128;
  const int bn = blockIdx.y * 64;
  const int tid = threadIdx.x;
  const int mg = tid >> 4;
  const int ng = tid & 15;
  const int m0 = mg * 8;
  const int n0 = ng * 4;

  u64 acc[4][4];
  #pragma unroll
  for (int i = 0; i < 4; ++i)
    #pragma unroll
    for (int j = 0; j < 4; ++j) acc[i][j] = 0ull;

  for (int k0 = 0; k0 < K; k0 += 16) {
    #pragma unroll
    for (int e = 0; e < 2; ++e) {
      int idx = e * 256 + tid;
      int r = idx >> 2, c = idx & 3;
      float4 v = *reinterpret_cast<const float4*>(&A[(size_t)(bm + r) * K + k0 + c * 4]);
      As[c * 4 + 0][r] = v.x; As[c * 4 + 1][r] = v.y;
      As[c * 4 + 2][r] = v.z; As[c * 4 + 3][r] = v.w;
    }
    {
      int r = tid >> 2, c = tid & 3;
      float4 v = *reinterpret_cast<const float4*>(&W[(size_t)(bn + r) * K + k0 + c * 4]);
      Ws[c * 4 + 0][r] = v.x; Ws[c * 4 + 1][r] = v.y;
      Ws[c * 4 + 2][r] = v.z; Ws[c * 4 + 3][r] = v.w;
    }
    __syncthreads();
    #pragma unroll
    for (int k = 0; k < 16; ++k) {
      ulonglong2 a01 = *reinterpret_cast<const ulonglong2*>(&As[k][m0]);
      ulonglong2 a23 = *reinterpret_cast<const ulonglong2*>(&As[k][m0 + 4]);
      float4 wv = *reinterpret_cast<const float4*>(&Ws[k][n0]);
      u64 w2[4];
      w2[0] = splat2(wv.x); w2[1] = splat2(wv.y);
      w2[2] = splat2(wv.z); w2[3] = splat2(wv.w);
      #pragma unroll
      for (int n = 0; n < 4; ++n) {
        ffma2(acc[0][n], a01.x, w2[n]);
        ffma2(acc[1][n], a01.y, w2[n]);
        ffma2(acc[2][n], a23.x, w2[n]);
        ffma2(acc[3][n], a23.y, w2[n]);
      }
    }
    __syncthreads();
  }

  float bs[4];
  #pragma unroll
  for (int n = 0; n < 4; ++n) bs[n] = bias[bn + n0 + n];

  #pragma unroll
  for (int p = 0; p < 4; ++p) {
    float2 v0 = unpk2(acc[p][0]);
    float2 v1 = unpk2(acc[p][1]);
    float2 v2 = unpk2(acc[p][2]);
    float2 v3 = unpk2(acc[p][3]);
    int row = bm + m0 + p * 2;
    float4 lo = make_float4(v0.x + bs[0], v1.x + bs[1], v2.x + bs[2], v3.x + bs[3]);
    float4 hi = make_float4(v0.y + bs[0], v1.y + bs[1], v2.y + bs[2], v3.y + bs[3]);
    if (RELU) {
      lo.x = fmaxf(lo.x, 0.f); lo.y = fmaxf(lo.y, 0.f);
      lo.z = fmaxf(lo.z, 0.f); lo.w = fmaxf(lo.w, 0.f);
      hi.x = fmaxf(hi.x, 0.f); hi.y = fmaxf(hi.y, 0.f);
      hi.z = fmaxf(hi.z, 0.f); hi.w = fmaxf(hi.w, 0.f);
    }
    *reinterpret_cast<float4*>(&C[(size_t)row * N + bn + n0]) = lo;
    *reinterpret_cast<float4*>(&C[(size_t)(row + 1) * N + bn + n0]) = hi;
  }
}

// ---------------- q head ----------------
__global__ void k_q(const float* __restrict__ A, const float* __restrict__ qw,
                    const float* __restrict__ qb, float* __restrict__ out)
{
  __shared__ float red[64];
  int b = blockIdx.x;
  float sum = 0.f;
  for (int c = threadIdx.x; c < 256; c += 64) sum += A[(size_t)b * 256 + c] * qw[c];
  red[threadIdx.x] = sum;
  __syncthreads();
  if (threadIdx.x < 32) {
    float v = red[threadIdx.x] + red[threadIdx.x + 32];
    #pragma unroll
    for (int o = 16; o; o >>= 1) v += __shfl_down_sync(0xffffffffu, v, o);
    if (threadIdx.x == 0) out[b] = v + qb[0];
  }
}

// ---------------- launch ----------------
extern "C" void kernel_launch(void* const* d_in, const int* in_sizes, int n_in,
                              void* d_out, int out_size)
{
  const float* state   = (const float*)d_in[0];
  const float* action  = (const float*)d_in[1];
  const int*   lengths = (const int*)d_in[2];

  const float* gWih[2]; const float* gWhh[2];
  const float* gbih[2]; const float* gbhh[2];
  const float* fcw[2][5]; const float* fcb[2][5];
  for (int br = 0; br < 2; ++br) {
    int base = 3 + br * 14;
    gWih[br] = (const float*)d_in[base + 0];
    gWhh[br] = (const float*)d_in[base + 1];
    gbih[br] = (const float*)d_in[base + 2];
    gbhh[br] = (const float*)d_in[base + 3];
    for (int l = 0; l < 5; ++l) {
      fcw[br][l] = (const float*)d_in[base + 4 + 2 * l];
      fcb[br][l] = (const float*)d_in[base + 5 + 2 * l];
    }
  }

  float *p_xin, *p_a1, *p_a2, *p_a3, *p_a4;
  cudaGetSymbolAddress((void**)&p_xin, g_xin);
  cudaGetSymbolAddress((void**)&p_a1, g_a1);
  cudaGetSymbolAddress((void**)&p_a2, g_a2);
  cudaGetSymbolAddress((void**)&p_a3, g_a3);
  cudaGetSymbolAddress((void**)&p_a4, g_a4);

  cudaFuncSetAttribute(k_gru_step, cudaFuncAttributeMaxDynamicSharedMemorySize,
                       (int)sizeof(GruS));

  // prep
  k_sort<<<1, 1024>>>(lengths);
  k_prep<<<(WHH_N + 8 * 3136 + 255) / 256, 256>>>(gWhh[0], gWhh[1],
                                                  gWih[0], gbih[0], gbhh[0],
                                                  gWih[1], gbih[1], gbhh[1]);

  // recurrent steps
  for (int t = 0; t < NT; ++t) {
    k_gru_step<<<dim3(NBT, 4, 2), THR, sizeof(GruS)>>>(state, t);
  }

  k_concat<<<dim3(NB, 2), 128>>>(state, action);

  float* outp = (float*)d_out;
  for (int br = 0; br < 2; ++br) {
    float* xin = p_xin + (size_t)br * NB * 272;
    float* a1  = p_a1  + (size_t)br * NB * 1024;
    float* a2  = p_a2  + (size_t)br * NB * 1024;
    float* a3  = p_a3  + (size_t)br * NB * 512;
    float* a4  = p_a4  + (size_t)br * NB * 256;
    k_gemm2<true><<<dim3(16, 16), 256>>>(xin, fcw[br][0], fcb[br][0], a1, 272, 1024);
    k_gemm2<true><<<dim3(16, 16), 256>>>(a1,  fcw[br][1], fcb[br][1], a2, 1024, 1024);
    k_gemm2<true><<<dim3(16,  8), 256>>>(a2,  fcw[br][2], fcb[br][2], a3, 1024, 512);
    k_gemm2<true><<<dim3(16,  4), 256>>>(a3,  fcw[br][3], fcb[br][3], a4, 512, 256);
    k_q<<<NB, 64>>>(a4, fcw[br][4], fcb[br][4], outp + (size_t)br * NB);
  }
}

// round 10
// speedup vs baseline: 2.2473x; 1.6575x over previous
#include <cuda_runtime.h>
#include <math.h>

#define NB 2048
#define NT 64
#define ND 15
#define NH 256
#define TB 64
#define NBT 32       // NB / TB
#define THR 256
#define NKT 17       // k-tiles: 16 h-tiles + 1 (x|1) tile  (K = 272)
#define BPACK_N (2 * 4 * NKT * 32 * 32 * 2)   // [g][jt][kt][ntile][lane][2]

typedef unsigned long long u64;
typedef unsigned u32;

// ---------------- bf16 helpers ----------------
__device__ __forceinline__ u32 pack_bf16x2(float e, float o) {   // low half = e
  u32 r; asm("cvt.rn.bf16x2.f32 %0, %1, %2;" : "=r"(r) : "f"(o), "f"(e)); return r;
}
__device__ __forceinline__ float bf16_lo_f(u32 v) { return __uint_as_float(v << 16); }
__device__ __forceinline__ float bf16_hi_f(u32 v) { return __uint_as_float(v & 0xffff0000u); }
__device__ __forceinline__ void split2(float v, float& hi, float& lo) {
  u32 h; asm("cvt.rn.bf16x2.f32 %0, %1, %2;" : "=r"(h) : "f"(0.f), "f"(v));
  hi = __uint_as_float(h << 16);
  lo = v - hi;
}

// ---------------- mma m16n8k16 bf16 ----------------
__device__ __forceinline__ void mma_bf16(float* d, const u32* a, u32 b0, u32 b1) {
  asm("mma.sync.aligned.m16n8k16.row.col.f32.bf16.bf16.f32 "
      "{%0,%1,%2,%3}, {%4,%5,%6,%7}, {%8,%9}, {%0,%1,%2,%3};"
      : "+f"(d[0]), "+f"(d[1]), "+f"(d[2]), "+f"(d[3])
      : "r"(a[0]), "r"(a[1]), "r"(a[2]), "r"(a[3]), "r"(b0), "r"(b1));
}

// ---------------- f32x2 packed-FMA helpers (MLP) ----------------
__device__ __forceinline__ void ffma2(u64& d, u64 a, u64 b) {
  asm("fma.rn.f32x2 %0, %1, %2, %3;" : "=l"(d) : "l"(a), "l"(b), "l"(d));
}
__device__ __forceinline__ u64 splat2(float w) {
  u64 d; asm("mov.b64 %0, {%1, %1};" : "=l"(d) : "f"(w)); return d;
}
__device__ __forceinline__ float2 unpk2(u64 v) {
  float2 r; asm("mov.b64 {%0, %1}, %2;" : "=f"(r.x), "=f"(r.y) : "l"(v)); return r;
}

// ---------------- mbarrier / bulk-copy ----------------
__device__ __forceinline__ unsigned smem_u32p(const void* p) {
  unsigned a;
  asm("{ .reg .u64 t; cvta.to.shared.u64 t, %1; cvt.u32.u64 %0, t; }" : "=r"(a) : "l"(p));
  return a;
}
__device__ __forceinline__ void mbar_init(unsigned mbar, unsigned cnt) {
  asm volatile("mbarrier.init.shared.b64 [%0], %1;" :: "r"(mbar), "r"(cnt) : "memory");
}
__device__ __forceinline__ void mbar_expect(unsigned mbar, unsigned bytes) {
  asm volatile("mbarrier.arrive.expect_tx.shared.b64 _, [%0], %1;"
               :: "r"(mbar), "r"(bytes) : "memory");
}
__device__ __forceinline__ void bulk_g2s(unsigned dst, const void* src,
                                         unsigned bytes, unsigned mbar) {
  asm volatile(
      "cp.async.bulk.shared::cta.global.mbarrier::complete_tx::bytes [%0], [%1], %2, [%3];"
      :: "r"(dst), "l"(src), "r"(bytes), "r"(mbar) : "memory");
}
__device__ __forceinline__ void mbar_wait(unsigned mbar, unsigned parity) {
  asm volatile(
      "{\n\t.reg .pred P;\n\t"
      "W%=:\n\t"
      "mbarrier.try_wait.parity.acquire.cta.shared::cta.b64 P, [%0], %1, 0x989680;\n\t"
      "@P bra.uni D%=;\n\t"
      "bra.uni W%=;\n\t"
      "D%=:\n\t}"
      :: "r"(mbar), "r"(parity) : "memory");
}

// ---------------- device scratch ----------------
__device__ u32   g_hbh[2][2][NB][132];   // [parity][gru][sorted row][k-pair] bf16x2 hi
__device__ u32   g_hbl[2][2][NB][132];   // lo
__device__ u32   g_wBhi[BPACK_N];        // pre-packed B fragments (hi)
__device__ u32   g_wBlo[BPACK_N];        // (lo)
__device__ float g_xin[2][NB][272];
__device__ float g_a1[2][NB][1024];
__device__ float g_a2[2][NB][1024];
__device__ float g_a3[2][NB][512];
__device__ float g_a4[2][NB][256];
__device__ int   g_perm[NB];
__device__ int   g_off[66];
__device__ int   g_hist[66];
__device__ int   g_tilemax[NBT];
__device__ int   g_invpos[NB];
__device__ int   g_finparp[NB];
__device__ int   g_lsort[NB];

// ---------------- fused length sort ----------------
__global__ void k_sort(const int* __restrict__ lengths) {
  int tid = threadIdx.x;
  if (tid < 66) g_hist[tid] = 0;
  __syncthreads();
  for (int b = tid; b < NB; b += 1024) atomicAdd(&g_hist[lengths[b]], 1);
  __syncthreads();
  if (tid == 0) {
    int s = 0;
    for (int l = 0; l < 66; ++l) { g_off[l] = s; s += g_hist[l]; }
  }
  __syncthreads();
  for (int b = tid; b < NB; b += 1024) {
    int p = atomicAdd(&g_off[lengths[b]], 1);
    g_perm[p] = b;
  }
  __syncthreads();
  if (tid < NBT) g_tilemax[tid] = lengths[g_perm[tid * TB + TB - 1]];
  __syncthreads();
  for (int p = tid; p < NB; p += 1024) {
    int b = g_perm[p];
    g_invpos[b] = p;
    g_finparp[p] = g_tilemax[p >> 6] & 1;
    g_lsort[p] = lengths[b];
  }
}

// ---------------- B-value oracle (fp32) ----------------
__device__ float bval(const float* Whh, const float* Wih,
                      const float* bih, const float* bhh,
                      int jt, int n, int k) {
  int gate = n >> 6;              // 0:r 1:z 2:hn 3:in
  int j = jt * 64 + (n & 63);
  if (k < 256) {
    if (gate == 0) return Whh[(size_t)j * 256 + k];
    if (gate == 1) return Whh[(size_t)(256 + j) * 256 + k];
    if (gate == 2) return Whh[(size_t)(512 + j) * 256 + k];
    return 0.f;
  } else if (k < 271) {
    int i = k - 256;
    if (gate == 0) return Wih[(size_t)j * ND + i];
    if (gate == 1) return Wih[(size_t)(256 + j) * ND + i];
    if (gate == 2) return 0.f;
    return Wih[(size_t)(512 + j) * ND + i];
  } else {
    if (gate == 0) return bih[j] + bhh[j];
    if (gate == 1) return bih[256 + j] + bhh[256 + j];
    if (gate == 2) return bhh[512 + j];
    return bih[512 + j];
  }
}

// ---------------- prep: pack B into per-lane mma fragment images ----------------
// index = ((((g*4+jt)*17 + kt)*32 + nt)*32 + lane)*2 + reg
__global__ void k_prep(const float* __restrict__ Whh0, const float* __restrict__ Whh1,
                       const float* __restrict__ Wih0, const float* __restrict__ bih0,
                       const float* __restrict__ bhh0,
                       const float* __restrict__ Wih1, const float* __restrict__ bih1,
                       const float* __restrict__ bhh1) {
  int i = blockIdx.x * blockDim.x + threadIdx.x;
  if (i >= 2 * 4 * NKT * 32 * 32) return;
  int lane = i & 31;
  int nt   = (i >> 5) & 31;
  int kt   = (i >> 10) % NKT;
  int jt   = (i / (1024 * NKT)) & 3;
  int g    = i / (1024 * NKT * 4);
  const float* Whh = g ? Whh1 : Whh0;
  const float* Wih = g ? Wih1 : Wih0;
  const float* bih = g ? bih1 : bih0;
  const float* bhh = g ? bhh1 : bhh0;
  int n = nt * 8 + (lane >> 2);
  #pragma unroll
  for (int reg = 0; reg < 2; ++reg) {
    int k0 = kt * 16 + 2 * (lane & 3) + reg * 8;
    float v0 = bval(Whh, Wih, bih, bhh, jt, n, k0);
    float v1 = bval(Whh, Wih, bih, bhh, jt, n, k0 + 1);
    float h0, l0, h1, l1;
    split2(v0, h0, l0); split2(v1, h1, l1);
    size_t idx = ((size_t)i) * 2 + reg;
    g_wBhi[idx] = pack_bf16x2(h0, h1);
    g_wBlo[idx] = pack_bf16x2(l0, l1);
  }
}

// ---------------- GRU step kernel: tensor-core GEMM + gate epilogue ----------------
struct GruS {
  u32 hsbh[TB][132];   // 33792 B
  u32 hsbl[TB][132];   // 33792 B
  u32 xsbh[TB][9];     // x|1.0 slots (8 pairs used, stride 9)
  u32 xsbl[TB][9];
  int ls[TB];
  u64 mb[2];
};

__global__ void __launch_bounds__(THR, 2)
k_gru_step(const float* __restrict__ state, int t)
{
  extern __shared__ char sraw[];
  GruS& s = *reinterpret_cast<GruS*>(sraw);
  const int bt = blockIdx.x, jt = blockIdx.y, g = blockIdx.z;
  const int tid = threadIdx.x;
  const int pi = t & 1, po = pi ^ 1;

  if (t >= g_tilemax[bt]) return;

  const unsigned mb = smem_u32p(&s.mb[0]);
  const int gjt = g * 4 + jt;

  if (tid == 0) mbar_init(mb, 1);
  __syncthreads();
  if (tid == 0 && t > 0) {
    mbar_expect(mb, 2u * 33792u);
    bulk_g2s(smem_u32p(&s.hsbh[0][0]), &g_hbh[pi][g][bt * TB][0], 33792u, mb);
    bulk_g2s(smem_u32p(&s.hsbl[0][0]), &g_hbl[pi][g][bt * TB][0], 33792u, mb);
  }

  // x gather -> bf16 hi/lo pairs; slot 7 = (x14, 1.0) [bias row rides k=271]
  for (int i = tid; i < TB * 8; i += THR) {
    int r = i >> 3, p = i & 7;
    const float* xp = state + (size_t)g_perm[bt * TB + r] * (NT * ND) + (size_t)t * ND;
    float v0 = xp[2 * p];
    float v1 = (p == 7) ? 1.0f : xp[2 * p + 1];
    float h0, l0, h1, l1;
    split2(v0, h0, l0); split2(v1, h1, l1);
    s.xsbh[r][p] = pack_bf16x2(h0, h1);
    s.xsbl[r][p] = pack_bf16x2(l0, l1);
  }
  if (tid < TB) s.ls[tid] = g_lsort[bt * TB + tid];
  __syncthreads();
  if (t > 0) mbar_wait(mb, 0);

  const int w = tid >> 5, lane = tid & 31;
  const int m0 = (w & 3) * 16, jhalf = w >> 2;
  const int rA = m0 + (lane >> 2);
  const int cA = lane & 3;

  float acc[4][4][4];
  #pragma unroll
  for (int a = 0; a < 4; ++a)
    #pragma unroll
    for (int b = 0; b < 4; ++b)
      #pragma unroll
      for (int c = 0; c < 4; ++c) acc[a][b][c] = 0.f;

  const int kt0 = (t > 0) ? 0 : 16;
  for (int kt = kt0; kt < NKT; ++kt) {
    u32 ah[4], al[4];
    if (kt < 16) {
      int cb = kt * 8 + cA;
      ah[0] = s.hsbh[rA][cb];     ah[1] = s.hsbh[rA + 8][cb];
      ah[2] = s.hsbh[rA][cb + 4]; ah[3] = s.hsbh[rA + 8][cb + 4];
      al[0] = s.hsbl[rA][cb];     al[1] = s.hsbl[rA + 8][cb];
      al[2] = s.hsbl[rA][cb + 4]; al[3] = s.hsbl[rA + 8][cb + 4];
    } else {
      ah[0] = s.xsbh[rA][cA];     ah[1] = s.xsbh[rA + 8][cA];
      ah[2] = s.xsbh[rA][cA + 4]; ah[3] = s.xsbh[rA + 8][cA + 4];
      al[0] = s.xsbl[rA][cA];     al[1] = s.xsbl[rA + 8][cA];
      al[2] = s.xsbl[rA][cA + 4]; al[3] = s.xsbl[rA + 8][cA + 4];
    }
    const bool lastkt = (kt == 16);
    #pragma unroll
    for (int g4 = 0; g4 < 4; ++g4) {
      if (g4 == 3 && !lastkt) continue;   // i_n block: only the x-ktile is nonzero
      #pragma unroll
      for (int q = 0; q < 4; ++q) {
        int ntg = g4 * 8 + jhalf * 4 + q;
        size_t bidx = ((((size_t)(gjt * NKT + kt)) * 32 + ntg) * 32 + lane) * 2;
        uint2 vh = *reinterpret_cast<const uint2*>(&g_wBhi[bidx]);
        uint2 vl = *reinterpret_cast<const uint2*>(&g_wBlo[bidx]);
        mma_bf16(acc[g4][q], ah, vh.x, vh.y);   // hi*hi
        mma_bf16(acc[g4][q], al, vh.x, vh.y);   // lo*hi
        mma_bf16(acc[g4][q], ah, vl.x, vl.y);   // hi*lo
      }
    }
  }

  // gates + masked update + write (bf16 hi/lo pairs)
  #pragma unroll
  for (int q = 0; q < 4; ++q) {
    #pragma unroll
    for (int half = 0; half < 2; ++half) {
      int rl = m0 + (lane >> 2) + half * 8;
      bool act = (t < s.ls[rl]);
      int jloc = jhalf * 32 + q * 8 + 2 * (lane & 3);
      int jg = jt * 64 + jloc;           // even
      float hold0 = 0.f, hold1 = 0.f;
      if (t > 0) {
        u32 vh = s.hsbh[rl][jg >> 1];
        u32 vl = s.hsbl[rl][jg >> 1];
        hold0 = bf16_lo_f(vh) + bf16_lo_f(vl);
        hold1 = bf16_hi_f(vh) + bf16_hi_f(vl);
      }
      float hn[2];
      #pragma unroll
      for (int e = 0; e < 2; ++e) {
        float xr = acc[0][q][half * 2 + e];
        float xz = acc[1][q][half * 2 + e];
        float xhn = acc[2][q][half * 2 + e];
        float xin = acc[3][q][half * 2 + e];
        float hold = e ? hold1 : hold0;
        if (act) {
          float r = __fdividef(1.f, 1.f + __expf(-xr));
          float z = __fdividef(1.f, 1.f + __expf(-xz));
          float n = tanhf(fmaf(r, xhn, xin));
          hn[e] = fmaf(z, hold - n, n);
        } else {
          hn[e] = hold;
        }
      }
      float h0, l0, h1, l1;
      split2(hn[0], h0, l0); split2(hn[1], h1, l1);
      int grow = bt * TB + rl;
      g_hbh[po][g][grow][jg >> 1] = pack_bf16x2(h0, h1);
      g_hbl[po][g][grow][jg >> 1] = pack_bf16x2(l0, l1);
    }
  }
}

// ---------------- concat [state(:,0,:), action, h] ----------------
__global__ void k_concat(const float* __restrict__ state, const float* __restrict__ action) {
  int b = blockIdx.x, br = blockIdx.y;
  int p = g_invpos[b];
  int fp = g_finparp[p];
  for (int c = threadIdx.x; c < 272; c += blockDim.x) {
    float v;
    if (c < ND)       v = state[(size_t)b * NT * ND + c];
    else if (c == ND) v = action[b];
    else {
      int j = c - 16;
      u32 vh = g_hbh[fp][br][p][j >> 1];
      u32 vl = g_hbl[fp][br][p][j >> 1];
      v = (j & 1) ? (bf16_hi_f(vh) + bf16_hi_f(vl)) : (bf16_lo_f(vh) + bf16_lo_f(vl));
    }
    g_xin[br][b][c] = v;
  }
}

// ---------------- FFMA2 tiled GEMM (MLP) ----------------
template<bool RELU>
__global__ void __launch_bounds__(256)
k_gemm2(const float* __restrict__ A, const float* __restrict__ W,
        const float* __restrict__ bias, float* __restrict__ C,
        int K, int N)
{
  __shared__ float As[16][132];
  __shared__ float Ws[16][68];
  const int bm = blockIdx.x * 128;
  const int bn = blockIdx.y * 64;
  const int tid = threadIdx.x;
  const int mg = tid >> 4;
  const int ng = tid & 15;
  const int m0 = mg * 8;
  const int n0 = ng * 4;

  u64 acc[4][4];
  #pragma unroll
  for (int i = 0; i < 4; ++i)
    #pragma unroll
    for (int j = 0; j < 4; ++j) acc[i][j] = 0ull;

  for (int k0 = 0; k0 < K; k0 += 16) {
    #pragma unroll
    for (int e = 0; e < 2; ++e) {
      int idx = e * 256 + tid;
      int r = idx >> 2, c = idx & 3;
      float4 v = *reinterpret_cast<const float4*>(&A[(size_t)(bm + r) * K + k0 + c * 4]);
      As[c * 4 + 0][r] = v.x; As[c * 4 + 1][r] = v.y;
      As[c * 4 + 2][r] = v.z; As[c * 4 + 3][r] = v.w;
    }
    {
      int r = tid >> 2, c = tid & 3;
      float4 v = *reinterpret_cast<const float4*>(&W[(size_t)(bn + r) * K + k0 + c * 4]);
      Ws[c * 4 + 0][r] = v.x; Ws[c * 4 + 1][r] = v.y;
      Ws[c * 4 + 2][r] = v.z; Ws[c * 4 + 3][r] = v.w;
    }
    __syncthreads();
    #pragma unroll
    for (int k = 0; k < 16; ++k) {
      ulonglong2 a01 = *reinterpret_cast<const ulonglong2*>(&As[k][m0]);
      ulonglong2 a23 = *reinterpret_cast<const ulonglong2*>(&As[k][m0 + 4]);
      float4 wv = *reinterpret_cast<const float4*>(&Ws[k][n0]);
      u64 w2[4];
      w2[0] = splat2(wv.x); w2[1] = splat2(wv.y);
      w2[2] = splat2(wv.z); w2[3] = splat2(wv.w);
      #pragma unroll
      for (int n = 0; n < 4; ++n) {
        ffma2(acc[0][n], a01.x, w2[n]);
        ffma2(acc[1][n], a01.y, w2[n]);
        ffma2(acc[2][n], a23.x, w2[n]);
        ffma2(acc[3][n], a23.y, w2[n]);
      }
    }
    __syncthreads();
  }

  float bs[4];
  #pragma unroll
  for (int n = 0; n < 4; ++n) bs[n] = bias[bn + n0 + n];

  #pragma unroll
  for (int p = 0; p < 4; ++p) {
    float2 v0 = unpk2(acc[p][0]);
    float2 v1 = unpk2(acc[p][1]);
    float2 v2 = unpk2(acc[p][2]);
    float2 v3 = unpk2(acc[p][3]);
    int row = bm + m0 + p * 2;
    float4 lo = make_float4(v0.x + bs[0], v1.x + bs[1], v2.x + bs[2], v3.x + bs[3]);
    float4 hi = make_float4(v0.y + bs[0], v1.y + bs[1], v2.y + bs[2], v3.y + bs[3]);
    if (RELU) {
      lo.x = fmaxf(lo.x, 0.f); lo.y = fmaxf(lo.y, 0.f);
      lo.z = fmaxf(lo.z, 0.f); lo.w = fmaxf(lo.w, 0.f);
      hi.x = fmaxf(hi.x, 0.f); hi.y = fmaxf(hi.y, 0.f);
      hi.z = fmaxf(hi.z, 0.f); hi.w = fmaxf(hi.w, 0.f);
    }
    *reinterpret_cast<float4*>(&C[(size_t)row * N + bn + n0]) = lo;
    *reinterpret_cast<float4*>(&C[(size_t)(row + 1) * N + bn + n0]) = hi;
  }
}

// ---------------- q head ----------------
__global__ void k_q(const float* __restrict__ A, const float* __restrict__ qw,
                    const float* __restrict__ qb, float* __restrict__ out)
{
  __shared__ float red[64];
  int b = blockIdx.x;
  float sum = 0.f;
  for (int c = threadIdx.x; c < 256; c += 64) sum += A[(size_t)b * 256 + c] * qw[c];
  red[threadIdx.x] = sum;
  __syncthreads();
  if (threadIdx.x < 32) {
    float v = red[threadIdx.x] + red[threadIdx.x + 32];
    #pragma unroll
    for (int o = 16; o; o >>= 1) v += __shfl_down_sync(0xffffffffu, v, o);
    if (threadIdx.x == 0) out[b] = v + qb[0];
  }
}

// ---------------- launch ----------------
extern "C" void kernel_launch(void* const* d_in, const int* in_sizes, int n_in,
                              void* d_out, int out_size)
{
  const float* state   = (const float*)d_in[0];
  const float* action  = (const float*)d_in[1];
  const int*   lengths = (const int*)d_in[2];

  const float* gWih[2]; const float* gWhh[2];
  const float* gbih[2]; const float* gbhh[2];
  const float* fcw[2][5]; const float* fcb[2][5];
  for (int br = 0; br < 2; ++br) {
    int base = 3 + br * 14;
    gWih[br] = (const float*)d_in[base + 0];
    gWhh[br] = (const float*)d_in[base + 1];
    gbih[br] = (const float*)d_in[base + 2];
    gbhh[br] = (const float*)d_in[base + 3];
    for (int l = 0; l < 5; ++l) {
      fcw[br][l] = (const float*)d_in[base + 4 + 2 * l];
      fcb[br][l] = (const float*)d_in[base + 5 + 2 * l];
    }
  }

  float *p_xin, *p_a1, *p_a2, *p_a3, *p_a4;
  cudaGetSymbolAddress((void**)&p_xin, g_xin);
  cudaGetSymbolAddress((void**)&p_a1, g_a1);
  cudaGetSymbolAddress((void**)&p_a2, g_a2);
  cudaGetSymbolAddress((void**)&p_a3, g_a3);
  cudaGetSymbolAddress((void**)&p_a4, g_a4);

  cudaFuncSetAttribute(k_gru_step, cudaFuncAttributeMaxDynamicSharedMemorySize,
                       (int)sizeof(GruS));

  // prep
  k_sort<<<1, 1024>>>(lengths);
  k_prep<<<(2 * 4 * NKT * 32 * 32 + 255) / 256, 256>>>(gWhh[0], gWhh[1],
                                                       gWih[0], gbih[0], gbhh[0],
                                                       gWih[1], gbih[1], gbhh[1]);

  // recurrent steps
  for (int t = 0; t < NT; ++t) {
    k_gru_step<<<dim3(NBT, 4, 2), THR, sizeof(GruS)>>>(state, t);
  }

  k_concat<<<dim3(NB, 2), 128>>>(state, action);

  float* outp = (float*)d_out;
  for (int br = 0; br < 2; ++br) {
    float* xin = p_xin + (size_t)br * NB * 272;
    float* a1  = p_a1  + (size_t)br * NB * 1024;
    float* a2  = p_a2  + (size_t)br * NB * 1024;
    float* a3  = p_a3  + (size_t)br * NB * 512;
    float* a4  = p_a4  + (size_t)br * NB * 256;
    k_gemm2<true><<<dim3(16, 16), 256>>>(xin, fcw[br][0], fcb[br][0], a1, 272, 1024);
    k_gemm2<true><<<dim3(16, 16), 256>>>(a1,  fcw[br][1], fcb[br][1], a2, 1024, 1024);
    k_gemm2<true><<<dim3(16,  8), 256>>>(a2,  fcw[br][2], fcb[br][2], a3, 1024, 512);
    k_gemm2<true><<<dim3(16,  4), 256>>>(a3,  fcw[br][3], fcb[br][3], a4, 512, 256);
    k_q<<<NB, 64>>>(a4, fcw[br][4], fcb[br][4], outp + (size_t)br * NB);
  }
}

// round 11
// speedup vs baseline: 2.8703x; 1.2772x over previous
#include <cuda_runtime.h>
#include <math.h>

#define NB 2048
#define NT 64
#define ND 15
#define NH 256
#define TB 64
#define NBT 32       // NB / TB
#define THR 256
#define NKT 17       // k-tiles: 16 h-tiles + 1 (x|1) tile  (K = 272)

typedef unsigned long long u64;
typedef unsigned u32;

// ---------------- bf16 helpers ----------------
__device__ __forceinline__ u32 pack_bf16x2(float e, float o) {   // low half = e
  u32 r; asm("cvt.rn.bf16x2.f32 %0, %1, %2;" : "=r"(r) : "f"(o), "f"(e)); return r;
}
__device__ __forceinline__ float bf16_lo_f(u32 v) { return __uint_as_float(v << 16); }
__device__ __forceinline__ float bf16_hi_f(u32 v) { return __uint_as_float(v & 0xffff0000u); }
__device__ __forceinline__ void split2(float v, float& hi, float& lo) {
  u32 h; asm("cvt.rn.bf16x2.f32 %0, %1, %2;" : "=r"(h) : "f"(0.f), "f"(v));
  hi = __uint_as_float(h << 16);
  lo = v - hi;
}

// ---------------- mma m16n8k16 bf16 ----------------
__device__ __forceinline__ void mma_bf16(float* d, const u32* a, u32 b0, u32 b1) {
  asm("mma.sync.aligned.m16n8k16.row.col.f32.bf16.bf16.f32 "
      "{%0,%1,%2,%3}, {%4,%5,%6,%7}, {%8,%9}, {%0,%1,%2,%3};"
      : "+f"(d[0]), "+f"(d[1]), "+f"(d[2]), "+f"(d[3])
      : "r"(a[0]), "r"(a[1]), "r"(a[2]), "r"(a[3]), "r"(b0), "r"(b1));
}

// ---------------- f32x2 packed-FMA helpers (MLP) ----------------
__device__ __forceinline__ void ffma2(u64& d, u64 a, u64 b) {
  asm("fma.rn.f32x2 %0, %1, %2, %3;" : "=l"(d) : "l"(a), "l"(b), "l"(d));
}
__device__ __forceinline__ u64 splat2(float w) {
  u64 d; asm("mov.b64 %0, {%1, %1};" : "=l"(d) : "f"(w)); return d;
}
__device__ __forceinline__ float2 unpk2(u64 v) {
  float2 r; asm("mov.b64 {%0, %1}, %2;" : "=f"(r.x), "=f"(r.y) : "l"(v)); return r;
}

// ---------------- mbarrier / bulk-copy ----------------
__device__ __forceinline__ unsigned smem_u32p(const void* p) {
  unsigned a;
  asm("{ .reg .u64 t; cvta.to.shared.u64 t, %1; cvt.u32.u64 %0, t; }" : "=r"(a) : "l"(p));
  return a;
}
__device__ __forceinline__ void mbar_init(unsigned mbar, unsigned cnt) {
  asm volatile("mbarrier.init.shared.b64 [%0], %1;" :: "r"(mbar), "r"(cnt) : "memory");
}
__device__ __forceinline__ void mbar_expect(unsigned mbar, unsigned bytes) {
  asm volatile("mbarrier.arrive.expect_tx.shared.b64 _, [%0], %1;"
               :: "r"(mbar), "r"(bytes) : "memory");
}
__device__ __forceinline__ void bulk_g2s(unsigned dst, const void* src,
                                         unsigned bytes, unsigned mbar) {
  asm volatile(
      "cp.async.bulk.shared::cta.global.mbarrier::complete_tx::bytes [%0], [%1], %2, [%3];"
      :: "r"(dst), "l"(src), "r"(bytes), "r"(mbar) : "memory");
}
__device__ __forceinline__ void mbar_wait(unsigned mbar, unsigned parity) {
  asm volatile(
      "{\n\t.reg .pred P;\n\t"
      "W%=:\n\t"
      "mbarrier.try_wait.parity.acquire.cta.shared::cta.b64 P, [%0], %1, 0x989680;\n\t"
      "@P bra.uni D%=;\n\t"
      "bra.uni W%=;\n\t"
      "D%=:\n\t}"
      :: "r"(mbar), "r"(parity) : "memory");
}

// ---------------- device scratch ----------------
__device__ u32   g_hbh[2][2][NB][132];   // [parity][gru][sorted row][k-pair] bf16x2 hi
__device__ u32   g_hbl[2][2][NB][132];   // lo
__device__ uint4 g_wB4[2 * 4 * NKT * 32 * 32];  // interleaved (hi0,hi1,lo0,lo1) fragments
__device__ float g_xin[2][NB][272];
__device__ float g_a1[2][NB][1024];
__device__ float g_a2[2][NB][1024];
__device__ float g_a3[2][NB][512];
__device__ float g_a4[2][NB][256];
__device__ int   g_perm[NB];
__device__ int   g_off[66];
__device__ int   g_hist[66];
__device__ int   g_tilemax[NBT];
__device__ int   g_invpos[NB];
__device__ int   g_finparp[NB];
__device__ int   g_lsort[NB];

// ---------------- fused length sort ----------------
__global__ void k_sort(const int* __restrict__ lengths) {
  int tid = threadIdx.x;
  if (tid < 66) g_hist[tid] = 0;
  __syncthreads();
  for (int b = tid; b < NB; b += 1024) atomicAdd(&g_hist[lengths[b]], 1);
  __syncthreads();
  if (tid == 0) {
    int s = 0;
    for (int l = 0; l < 66; ++l) { g_off[l] = s; s += g_hist[l]; }
  }
  __syncthreads();
  for (int b = tid; b < NB; b += 1024) {
    int p = atomicAdd(&g_off[lengths[b]], 1);
    g_perm[p] = b;
  }
  __syncthreads();
  if (tid < NBT) g_tilemax[tid] = lengths[g_perm[tid * TB + TB - 1]];
  __syncthreads();
  for (int p = tid; p < NB; p += 1024) {
    int b = g_perm[p];
    g_invpos[b] = p;
    g_finparp[p] = g_tilemax[p >> 6] & 1;
    g_lsort[p] = lengths[b];
  }
}

// ---------------- B-value oracle (fp32) ----------------
__device__ float bval(const float* Whh, const float* Wih,
                      const float* bih, const float* bhh,
                      int jt, int n, int k) {
  int gate = n >> 6;              // 0:r 1:z 2:hn 3:in
  int j = jt * 64 + (n & 63);
  if (k < 256) {
    if (gate == 0) return Whh[(size_t)j * 256 + k];
    if (gate == 1) return Whh[(size_t)(256 + j) * 256 + k];
    if (gate == 2) return Whh[(size_t)(512 + j) * 256 + k];
    return 0.f;
  } else if (k < 271) {
    int i = k - 256;
    if (gate == 0) return Wih[(size_t)j * ND + i];
    if (gate == 1) return Wih[(size_t)(256 + j) * ND + i];
    if (gate == 2) return 0.f;
    return Wih[(size_t)(512 + j) * ND + i];
  } else {
    if (gate == 0) return bih[j] + bhh[j];
    if (gate == 1) return bih[256 + j] + bhh[256 + j];
    if (gate == 2) return bhh[512 + j];
    return bih[512 + j];
  }
}

// ---------------- prep: pack B into interleaved per-lane mma fragment images ----------------
// index = (((g*4+jt)*17 + kt)*32 + nt)*32 + lane  -> uint4{hi_r0, hi_r1, lo_r0, lo_r1}
__global__ void k_prep(const float* __restrict__ Whh0, const float* __restrict__ Whh1,
                       const float* __restrict__ Wih0, const float* __restrict__ bih0,
                       const float* __restrict__ bhh0,
                       const float* __restrict__ Wih1, const float* __restrict__ bih1,
                       const float* __restrict__ bhh1) {
  int i = blockIdx.x * blockDim.x + threadIdx.x;
  if (i >= 2 * 4 * NKT * 32 * 32) return;
  int lane = i & 31;
  int nt   = (i >> 5) & 31;
  int kt   = (i >> 10) % NKT;
  int jt   = (i / (1024 * NKT)) & 3;
  int g    = i / (1024 * NKT * 4);
  const float* Whh = g ? Whh1 : Whh0;
  const float* Wih = g ? Wih1 : Wih0;
  const float* bih = g ? bih1 : bih0;
  const float* bhh = g ? bhh1 : bhh0;
  int n = nt * 8 + (lane >> 2);
  u32 out[4];
  #pragma unroll
  for (int reg = 0; reg < 2; ++reg) {
    int k0 = kt * 16 + 2 * (lane & 3) + reg * 8;
    float v0 = bval(Whh, Wih, bih, bhh, jt, n, k0);
    float v1 = bval(Whh, Wih, bih, bhh, jt, n, k0 + 1);
    float h0, l0, h1, l1;
    split2(v0, h0, l0); split2(v1, h1, l1);
    out[reg]     = pack_bf16x2(h0, h1);
    out[2 + reg] = pack_bf16x2(l0, l1);
  }
  g_wB4[i] = make_uint4(out[0], out[1], out[2], out[3]);
}

// ---------------- GRU step kernel: tensor-core GEMM + gate epilogue ----------------
struct GruS {
  u32 hsbh[TB][132];
  u32 hsbl[TB][132];
  u32 xsbh[TB][9];
  u32 xsbl[TB][9];
  int ls[TB];
  u64 mb[2];
};

#define MMA3(g4, q, off)                                            \
  {                                                                 \
    uint4 v = pkt[(off)];                                           \
    mma_bf16(acc[g4][q], ah, v.x, v.y);                             \
    mma_bf16(acc[g4][q], al, v.x, v.y);                             \
    mma_bf16(acc[g4][q], ah, v.z, v.w);                             \
  }

__global__ void __launch_bounds__(THR, 2)
k_gru_step(const float* __restrict__ state, int t)
{
  extern __shared__ char sraw[];
  GruS& s = *reinterpret_cast<GruS*>(sraw);
  const int bt = blockIdx.x, jt = blockIdx.y, g = blockIdx.z;
  const int tid = threadIdx.x;
  const int pi = t & 1, po = pi ^ 1;

  if (t >= g_tilemax[bt]) return;

  const unsigned mb = smem_u32p(&s.mb[0]);
  const int gjt = g * 4 + jt;

  if (tid == 0) mbar_init(mb, 1);
  __syncthreads();
  if (tid == 0 && t > 0) {
    mbar_expect(mb, 2u * 33792u);
    bulk_g2s(smem_u32p(&s.hsbh[0][0]), &g_hbh[pi][g][bt * TB][0], 33792u, mb);
    bulk_g2s(smem_u32p(&s.hsbl[0][0]), &g_hbl[pi][g][bt * TB][0], 33792u, mb);
  }

  // x gather -> bf16 hi/lo pairs; slot 7 = (x14, 1.0) [bias row rides k=271]
  for (int i = tid; i < TB * 8; i += THR) {
    int r = i >> 3, p = i & 7;
    const float* xp = state + (size_t)g_perm[bt * TB + r] * (NT * ND) + (size_t)t * ND;
    float v0 = xp[2 * p];
    float v1 = (p == 7) ? 1.0f : xp[2 * p + 1];
    float h0, l0, h1, l1;
    split2(v0, h0, l0); split2(v1, h1, l1);
    s.xsbh[r][p] = pack_bf16x2(h0, h1);
    s.xsbl[r][p] = pack_bf16x2(l0, l1);
  }
  if (tid < TB) s.ls[tid] = g_lsort[bt * TB + tid];
  __syncthreads();
  if (t > 0) mbar_wait(mb, 0);

  const int w = tid >> 5, lane = tid & 31;
  const int m0 = (w & 3) * 16, jhalf = w >> 2;
  const int rA = m0 + (lane >> 2);
  const int cA = lane & 3;

  // warp-constant fragment base: fold gjt, jhalf, lane into the pointer once
  const uint4* __restrict__ wb =
      g_wB4 + (((size_t)gjt * NKT) * 32 + jhalf * 4) * 32 + lane;

  float acc[4][4][4];
  #pragma unroll
  for (int a = 0; a < 4; ++a)
    #pragma unroll
    for (int b = 0; b < 4; ++b)
      #pragma unroll
      for (int c = 0; c < 4; ++c) acc[a][b][c] = 0.f;

  u32 ah[4], al[4];

  if (t > 0) {
    #pragma unroll 4
    for (int kt = 0; kt < 16; ++kt) {
      int cb = kt * 8 + cA;
      ah[0] = s.hsbh[rA][cb];     ah[1] = s.hsbh[rA + 8][cb];
      ah[2] = s.hsbh[rA][cb + 4]; ah[3] = s.hsbh[rA + 8][cb + 4];
      al[0] = s.hsbl[rA][cb];     al[1] = s.hsbl[rA + 8][cb];
      al[2] = s.hsbl[rA][cb + 4]; al[3] = s.hsbl[rA + 8][cb + 4];
      const uint4* __restrict__ pkt = wb + kt * 1024;
      // g4 = 0,1,2 (r, z, h_n); offsets are compile-time immediates
      MMA3(0, 0, 0 * 32)   MMA3(0, 1, 1 * 32)   MMA3(0, 2, 2 * 32)   MMA3(0, 3, 3 * 32)
      MMA3(1, 0, 8 * 32)   MMA3(1, 1, 9 * 32)   MMA3(1, 2, 10 * 32)  MMA3(1, 3, 11 * 32)
      MMA3(2, 0, 16 * 32)  MMA3(2, 1, 17 * 32)  MMA3(2, 2, 18 * 32)  MMA3(2, 3, 19 * 32)
    }
  }
  // x | bias k-tile (kt = 16): all four gate blocks
  {
    ah[0] = s.xsbh[rA][cA];     ah[1] = s.xsbh[rA + 8][cA];
    ah[2] = s.xsbh[rA][cA + 4]; ah[3] = s.xsbh[rA + 8][cA + 4];
    al[0] = s.xsbl[rA][cA];     al[1] = s.xsbl[rA + 8][cA];
    al[2] = s.xsbl[rA][cA + 4]; al[3] = s.xsbl[rA + 8][cA + 4];
    const uint4* __restrict__ pkt = wb + 16 * 1024;
    MMA3(0, 0, 0 * 32)   MMA3(0, 1, 1 * 32)   MMA3(0, 2, 2 * 32)   MMA3(0, 3, 3 * 32)
    MMA3(1, 0, 8 * 32)   MMA3(1, 1, 9 * 32)   MMA3(1, 2, 10 * 32)  MMA3(1, 3, 11 * 32)
    MMA3(2, 0, 16 * 32)  MMA3(2, 1, 17 * 32)  MMA3(2, 2, 18 * 32)  MMA3(2, 3, 19 * 32)
    MMA3(3, 0, 24 * 32)  MMA3(3, 1, 25 * 32)  MMA3(3, 2, 26 * 32)  MMA3(3, 3, 27 * 32)
  }

  // gates + masked update + write (bf16 hi/lo pairs)
  #pragma unroll
  for (int q = 0; q < 4; ++q) {
    #pragma unroll
    for (int half = 0; half < 2; ++half) {
      int rl = m0 + (lane >> 2) + half * 8;
      bool act = (t < s.ls[rl]);
      int jloc = jhalf * 32 + q * 8 + 2 * (lane & 3);
      int jg = jt * 64 + jloc;           // even
      float hold0 = 0.f, hold1 = 0.f;
      if (t > 0) {
        u32 vh = s.hsbh[rl][jg >> 1];
        u32 vl = s.hsbl[rl][jg >> 1];
        hold0 = bf16_lo_f(vh) + bf16_lo_f(vl);
        hold1 = bf16_hi_f(vh) + bf16_hi_f(vl);
      }
      float hn[2];
      #pragma unroll
      for (int e = 0; e < 2; ++e) {
        float xr = acc[0][q][half * 2 + e];
        float xz = acc[1][q][half * 2 + e];
        float xhn = acc[2][q][half * 2 + e];
        float xin = acc[3][q][half * 2 + e];
        float hold = e ? hold1 : hold0;
        if (act) {
          float r = __fdividef(1.f, 1.f + __expf(-xr));
          float z = __fdividef(1.f, 1.f + __expf(-xz));
          float n = tanhf(fmaf(r, xhn, xin));
          hn[e] = fmaf(z, hold - n, n);
        } else {
          hn[e] = hold;
        }
      }
      float h0, l0, h1, l1;
      split2(hn[0], h0, l0); split2(hn[1], h1, l1);
      int grow = bt * TB + rl;
      g_hbh[po][g][grow][jg >> 1] = pack_bf16x2(h0, h1);
      g_hbl[po][g][grow][jg >> 1] = pack_bf16x2(l0, l1);
    }
  }
}

// ---------------- concat [state(:,0,:), action, h] ----------------
__global__ void k_concat(const float* __restrict__ state, const float* __restrict__ action) {
  int b = blockIdx.x, br = blockIdx.y;
  int p = g_invpos[b];
  int fp = g_finparp[p];
  for (int c = threadIdx.x; c < 272; c += blockDim.x) {
    float v;
    if (c < ND)       v = state[(size_t)b * NT * ND + c];
    else if (c == ND) v = action[b];
    else {
      int j = c - 16;
      u32 vh = g_hbh[fp][br][p][j >> 1];
      u32 vl = g_hbl[fp][br][p][j >> 1];
      v = (j & 1) ? (bf16_hi_f(vh) + bf16_hi_f(vl)) : (bf16_lo_f(vh) + bf16_lo_f(vl));
    }
    g_xin[br][b][c] = v;
  }
}

// ---------------- FFMA2 tiled GEMM (MLP) ----------------
template<bool RELU>
__global__ void __launch_bounds__(256)
k_gemm2(const float* __restrict__ A, const float* __restrict__ W,
        const float* __restrict__ bias, float* __restrict__ C,
        int K, int N)
{
  __shared__ float As[16][132];
  __shared__ float Ws[16][68];
  const int bm = blockIdx.x * 128;
  const int bn = blockIdx.y * 64;
  const int tid = threadIdx.x;
  const int mg = tid >> 4;
  const int ng = tid & 15;
  const int m0 = mg * 8;
  const int n0 = ng * 4;

  u64 acc[4][4];
  #pragma unroll
  for (int i = 0; i < 4; ++i)
    #pragma unroll
    for (int j = 0; j < 4; ++j) acc[i][j] = 0ull;

  for (int k0 = 0; k0 < K; k0 += 16) {
    #pragma unroll
    for (int e = 0; e < 2; ++e) {
      int idx = e * 256 + tid;
      int r = idx >> 2, c = idx & 3;
      float4 v = *reinterpret_cast<const float4*>(&A[(size_t)(bm + r) * K + k0 + c * 4]);
      As[c * 4 + 0][r] = v.x; As[c * 4 + 1][r] = v.y;
      As[c * 4 + 2][r] = v.z; As[c * 4 + 3][r] = v.w;
    }
    {
      int r = tid >> 2, c = tid & 3;
      float4 v = *reinterpret_cast<const float4*>(&W[(size_t)(bn + r) * K + k0 + c * 4]);
      Ws[c * 4 + 0][r] = v.x; Ws[c * 4 + 1][r] = v.y;
      Ws[c * 4 + 2][r] = v.z; Ws[c * 4 + 3][r] = v.w;
    }
    __syncthreads();
    #pragma unroll
    for (int k = 0; k < 16; ++k) {
      ulonglong2 a01 = *reinterpret_cast<const ulonglong2*>(&As[k][m0]);
      ulonglong2 a23 = *reinterpret_cast<const ulonglong2*>(&As[k][m0 + 4]);
      float4 wv = *reinterpret_cast<const float4*>(&Ws[k][n0]);
      u64 w2[4];
      w2[0] = splat2(wv.x); w2[1] = splat2(wv.y);
      w2[2] = splat2(wv.z); w2[3] = splat2(wv.w);
      #pragma unroll
      for (int n = 0; n < 4; ++n) {
        ffma2(acc[0][n], a01.x, w2[n]);
        ffma2(acc[1][n], a01.y, w2[n]);
        ffma2(acc[2][n], a23.x, w2[n]);
        ffma2(acc[3][n], a23.y, w2[n]);
      }
    }
    __syncthreads();
  }

  float bs[4];
  #pragma unroll
  for (int n = 0; n < 4; ++n) bs[n] = bias[bn + n0 + n];

  #pragma unroll
  for (int p = 0; p < 4; ++p) {
    float2 v0 = unpk2(acc[p][0]);
    float2 v1 = unpk2(acc[p][1]);
    float2 v2 = unpk2(acc[p][2]);
    float2 v3 = unpk2(acc[p][3]);
    int row = bm + m0 + p * 2;
    float4 lo = make_float4(v0.x + bs[0], v1.x + bs[1], v2.x + bs[2], v3.x + bs[3]);
    float4 hi = make_float4(v0.y + bs[0], v1.y + bs[1], v2.y + bs[2], v3.y + bs[3]);
    if (RELU) {
      lo.x = fmaxf(lo.x, 0.f); lo.y = fmaxf(lo.y, 0.f);
      lo.z = fmaxf(lo.z, 0.f); lo.w = fmaxf(lo.w, 0.f);
      hi.x = fmaxf(hi.x, 0.f); hi.y = fmaxf(hi.y, 0.f);
      hi.z = fmaxf(hi.z, 0.f); hi.w = fmaxf(hi.w, 0.f);
    }
    *reinterpret_cast<float4*>(&C[(size_t)row * N + bn + n0]) = lo;
    *reinterpret_cast<float4*>(&C[(size_t)(row + 1) * N + bn + n0]) = hi;
  }
}

// ---------------- q head ----------------
__global__ void k_q(const float* __restrict__ A, const float* __restrict__ qw,
                    const float* __restrict__ qb, float* __restrict__ out)
{
  __shared__ float red[64];
  int b = blockIdx.x;
  float sum = 0.f;
  for (int c = threadIdx.x; c < 256; c += 64) sum += A[(size_t)b * 256 + c] * qw[c];
  red[threadIdx.x] = sum;
  __syncthreads();
  if (threadIdx.x < 32) {
    float v = red[threadIdx.x] + red[threadIdx.x + 32];
    #pragma unroll
    for (int o = 16; o; o >>= 1) v += __shfl_down_sync(0xffffffffu, v, o);
    if (threadIdx.x == 0) out[b] = v + qb[0];
  }
}

// ---------------- launch ----------------
extern "C" void kernel_launch(void* const* d_in, const int* in_sizes, int n_in,
                              void* d_out, int out_size)
{
  const float* state   = (const float*)d_in[0];
  const float* action  = (const float*)d_in[1];
  const int*   lengths = (const int*)d_in[2];

  const float* gWih[2]; const float* gWhh[2];
  const float* gbih[2]; const float* gbhh[2];
  const float* fcw[2][5]; const float* fcb[2][5];
  for (int br = 0; br < 2; ++br) {
    int base = 3 + br * 14;
    gWih[br] = (const float*)d_in[base + 0];
    gWhh[br] = (const float*)d_in[base + 1];
    gbih[br] = (const float*)d_in[base + 2];
    gbhh[br] = (const float*)d_in[base + 3];
    for (int l = 0; l < 5; ++l) {
      fcw[br][l] = (const float*)d_in[base + 4 + 2 * l];
      fcb[br][l] = (const float*)d_in[base + 5 + 2 * l];
    }
  }

  float *p_xin, *p_a1, *p_a2, *p_a3, *p_a4;
  cudaGetSymbolAddress((void**)&p_xin, g_xin);
  cudaGetSymbolAddress((void**)&p_a1, g_a1);
  cudaGetSymbolAddress((void**)&p_a2, g_a2);
  cudaGetSymbolAddress((void**)&p_a3, g_a3);
  cudaGetSymbolAddress((void**)&p_a4, g_a4);

  cudaFuncSetAttribute(k_gru_step, cudaFuncAttributeMaxDynamicSharedMemorySize,
                       (int)sizeof(GruS));

  // prep
  k_sort<<<1, 1024>>>(lengths);
  k_prep<<<(2 * 4 * NKT * 32 * 32 + 255) / 256, 256>>>(gWhh[0], gWhh[1],
                                                       gWih[0], gbih[0], gbhh[0],
                                                       gWih[1], gbih[1], gbhh[1]);

  // recurrent steps
  for (int t = 0; t < NT; ++t) {
    k_gru_step<<<dim3(NBT, 4, 2), THR, sizeof(GruS)>>>(state, t);
  }

  k_concat<<<dim3(NB, 2), 128>>>(state, action);

  float* outp = (float*)d_out;
  for (int br = 0; br < 2; ++br) {
    float* xin = p_xin + (size_t)br * NB * 272;
    float* a1  = p_a1  + (size_t)br * NB * 1024;
    float* a2  = p_a2  + (size_t)br * NB * 1024;
    float* a3  = p_a3  + (size_t)br * NB * 512;
    float* a4  = p_a4  + (size_t)br * NB * 256;
    k_gemm2<true><<<dim3(16, 16), 256>>>(xin, fcw[br][0], fcb[br][0], a1, 272, 1024);
    k_gemm2<true><<<dim3(16, 16), 256>>>(a1,  fcw[br][1], fcb[br][1], a2, 1024, 1024);
    k_gemm2<true><<<dim3(16,  8), 256>>>(a2,  fcw[br][2], fcb[br][2], a3, 1024, 512);
    k_gemm2<true><<<dim3(16,  4), 256>>>(a3,  fcw[br][3], fcb[br][3], a4, 512, 256);
    k_q<<<NB, 64>>>(a4, fcw[br][4], fcb[br][4], outp + (size_t)br * NB);
  }
}

// round 12
// speedup vs baseline: 3.3232x; 1.1578x over previous
#include <cuda_runtime.h>
#include <math.h>

#define NB 2048
#define NT 64
#define ND 15
#define NH 256
#define TB 64
#define NBT 32       // NB / TB
#define THR 256
#define NKT 17       // GRU k-tiles: 16 h-tiles + 1 (x|1) tile  (K = 272)

// MLP packed-fragment layout (uint4 units)
#define MLPB_BR 495616
#define OFF_L1 0
#define OFF_L2 69632
#define OFF_L3 331776
#define OFF_L4 462848

typedef unsigned long long u64;
typedef unsigned u32;

// ---------------- bf16 helpers ----------------
__device__ __forceinline__ u32 pack_bf16x2(float e, float o) {   // low half = e
  u32 r; asm("cvt.rn.bf16x2.f32 %0, %1, %2;" : "=r"(r) : "f"(o), "f"(e)); return r;
}
__device__ __forceinline__ float bf16_lo_f(u32 v) { return __uint_as_float(v << 16); }
__device__ __forceinline__ float bf16_hi_f(u32 v) { return __uint_as_float(v & 0xffff0000u); }
__device__ __forceinline__ void split2(float v, float& hi, float& lo) {
  u32 h; asm("cvt.rn.bf16x2.f32 %0, %1, %2;" : "=r"(h) : "f"(0.f), "f"(v));
  hi = __uint_as_float(h << 16);
  lo = v - hi;
}

// ---------------- mma m16n8k16 bf16 ----------------
__device__ __forceinline__ void mma_bf16(float* d, const u32* a, u32 b0, u32 b1) {
  asm("mma.sync.aligned.m16n8k16.row.col.f32.bf16.bf16.f32 "
      "{%0,%1,%2,%3}, {%4,%5,%6,%7}, {%8,%9}, {%0,%1,%2,%3};"
      : "+f"(d[0]), "+f"(d[1]), "+f"(d[2]), "+f"(d[3])
      : "r"(a[0]), "r"(a[1]), "r"(a[2]), "r"(a[3]), "r"(b0), "r"(b1));
}

// ---------------- mbarrier / bulk-copy ----------------
__device__ __forceinline__ unsigned smem_u32p(const void* p) {
  unsigned a;
  asm("{ .reg .u64 t; cvta.to.shared.u64 t, %1; cvt.u32.u64 %0, t; }" : "=r"(a) : "l"(p));
  return a;
}
__device__ __forceinline__ void mbar_init(unsigned mbar, unsigned cnt) {
  asm volatile("mbarrier.init.shared.b64 [%0], %1;" :: "r"(mbar), "r"(cnt) : "memory");
}
__device__ __forceinline__ void mbar_expect(unsigned mbar, unsigned bytes) {
  asm volatile("mbarrier.arrive.expect_tx.shared.b64 _, [%0], %1;"
               :: "r"(mbar), "r"(bytes) : "memory");
}
__device__ __forceinline__ void bulk_g2s(unsigned dst, const void* src,
                                         unsigned bytes, unsigned mbar) {
  asm volatile(
      "cp.async.bulk.shared::cta.global.mbarrier::complete_tx::bytes [%0], [%1], %2, [%3];"
      :: "r"(dst), "l"(src), "r"(bytes), "r"(mbar) : "memory");
}
__device__ __forceinline__ void mbar_wait(unsigned mbar, unsigned parity) {
  asm volatile(
      "{\n\t.reg .pred P;\n\t"
      "W%=:\n\t"
      "mbarrier.try_wait.parity.acquire.cta.shared::cta.b64 P, [%0], %1, 0x989680;\n\t"
      "@P bra.uni D%=;\n\t"
      "bra.uni W%=;\n\t"
      "D%=:\n\t}"
      :: "r"(mbar), "r"(parity) : "memory");
}

// ---------------- device scratch ----------------
__device__ u32   g_hbh[2][2][NB][132];   // [parity][gru][sorted row][k-pair] bf16x2 hi
__device__ u32   g_hbl[2][2][NB][132];
__device__ uint4 g_wB4[2 * 4 * NKT * 32 * 32];   // GRU B fragments
__device__ uint4 g_mlpB[2 * MLPB_BR];            // MLP W fragments
__device__ u32   g_xh[NB][136];          // xin pairs (per-branch, reused)
__device__ u32   g_xl[NB][136];
__device__ u32   g_m0h[NB][512];         // activation ping-pong (pairs)
__device__ u32   g_m0l[NB][512];
__device__ u32   g_m1h[NB][512];
__device__ u32   g_m1l[NB][512];
__device__ int   g_perm[NB];
__device__ int   g_off[66];
__device__ int   g_hist[66];
__device__ int   g_tilemax[NBT];
__device__ int   g_invpos[NB];
__device__ int   g_finparp[NB];
__device__ int   g_lsort[NB];

// ---------------- fused length sort ----------------
__global__ void k_sort(const int* __restrict__ lengths) {
  int tid = threadIdx.x;
  if (tid < 66) g_hist[tid] = 0;
  __syncthreads();
  for (int b = tid; b < NB; b += 1024) atomicAdd(&g_hist[lengths[b]], 1);
  __syncthreads();
  if (tid == 0) {
    int s = 0;
    for (int l = 0; l < 66; ++l) { g_off[l] = s; s += g_hist[l]; }
  }
  __syncthreads();
  for (int b = tid; b < NB; b += 1024) {
    int p = atomicAdd(&g_off[lengths[b]], 1);
    g_perm[p] = b;
  }
  __syncthreads();
  if (tid < NBT) g_tilemax[tid] = lengths[g_perm[tid * TB + TB - 1]];
  __syncthreads();
  for (int p = tid; p < NB; p += 1024) {
    int b = g_perm[p];
    g_invpos[b] = p;
    g_finparp[p] = g_tilemax[p >> 6] & 1;
    g_lsort[p] = lengths[b];
  }
}

// ---------------- GRU B-value oracle (fp32) ----------------
__device__ float bval(const float* Whh, const float* Wih,
                      const float* bih, const float* bhh,
                      int jt, int n, int k) {
  int gate = n >> 6;              // 0:r 1:z 2:hn 3:in
  int j = jt * 64 + (n & 63);
  if (k < 256) {
    if (gate == 0) return Whh[(size_t)j * 256 + k];
    if (gate == 1) return Whh[(size_t)(256 + j) * 256 + k];
    if (gate == 2) return Whh[(size_t)(512 + j) * 256 + k];
    return 0.f;
  } else if (k < 271) {
    int i = k - 256;
    if (gate == 0) return Wih[(size_t)j * ND + i];
    if (gate == 1) return Wih[(size_t)(256 + j) * ND + i];
    if (gate == 2) return 0.f;
    return Wih[(size_t)(512 + j) * ND + i];
  } else {
    if (gate == 0) return bih[j] + bhh[j];
    if (gate == 1) return bih[256 + j] + bhh[256 + j];
    if (gate == 2) return bhh[512 + j];
    return bih[512 + j];
  }
}

// ---------------- GRU prep: pack B fragments ----------------
__global__ void k_prep(const float* __restrict__ Whh0, const float* __restrict__ Whh1,
                       const float* __restrict__ Wih0, const float* __restrict__ bih0,
                       const float* __restrict__ bhh0,
                       const float* __restrict__ Wih1, const float* __restrict__ bih1,
                       const float* __restrict__ bhh1) {
  int i = blockIdx.x * blockDim.x + threadIdx.x;
  if (i >= 2 * 4 * NKT * 32 * 32) return;
  int lane = i & 31;
  int nt   = (i >> 5) & 31;
  int kt   = (i >> 10) % NKT;
  int jt   = (i / (1024 * NKT)) & 3;
  int g    = i / (1024 * NKT * 4);
  const float* Whh = g ? Whh1 : Whh0;
  const float* Wih = g ? Wih1 : Wih0;
  const float* bih = g ? bih1 : bih0;
  const float* bhh = g ? bhh1 : bhh0;
  int n = nt * 8 + (lane >> 2);
  u32 out[4];
  #pragma unroll
  for (int reg = 0; reg < 2; ++reg) {
    int k0 = kt * 16 + 2 * (lane & 3) + reg * 8;
    float v0 = bval(Whh, Wih, bih, bhh, jt, n, k0);
    float v1 = bval(Whh, Wih, bih, bhh, jt, n, k0 + 1);
    float h0, l0, h1, l1;
    split2(v0, h0, l0); split2(v1, h1, l1);
    out[reg]     = pack_bf16x2(h0, h1);
    out[2 + reg] = pack_bf16x2(l0, l1);
  }
  g_wB4[i] = make_uint4(out[0], out[1], out[2], out[3]);
}

// ---------------- MLP prep: pack W[N][K] fragments ----------------
__global__ void k_packw(const float* __restrict__ W, int KT, int NTGtot, int K,
                        uint4* __restrict__ dst) {
  int i = blockIdx.x * blockDim.x + threadIdx.x;
  if (i >= KT * NTGtot * 32) return;
  int lane = i & 31;
  int ntg  = (i >> 5) % NTGtot;
  int kt   = (i >> 5) / NTGtot;
  int n = ntg * 8 + (lane >> 2);
  u32 out[4];
  #pragma unroll
  for (int reg = 0; reg < 2; ++reg) {
    int k0 = kt * 16 + 2 * (lane & 3) + reg * 8;
    float v0 = W[(size_t)n * K + k0];
    float v1 = W[(size_t)n * K + k0 + 1];
    float h0, l0, h1, l1;
    split2(v0, h0, l0); split2(v1, h1, l1);
    out[reg]     = pack_bf16x2(h0, h1);
    out[2 + reg] = pack_bf16x2(l0, l1);
  }
  dst[i] = make_uint4(out[0], out[1], out[2], out[3]);
}

// ---------------- GRU step kernel (unchanged from R11) ----------------
struct GruS {
  u32 hsbh[TB][132];
  u32 hsbl[TB][132];
  u32 xsbh[TB][9];
  u32 xsbl[TB][9];
  int ls[TB];
  u64 mb[2];
};

#define MMA3(g4, q, off)                                            \
  {                                                                 \
    uint4 v = pkt[(off)];                                           \
    mma_bf16(acc[g4][q], ah, v.x, v.y);                             \
    mma_bf16(acc[g4][q], al, v.x, v.y);                             \
    mma_bf16(acc[g4][q], ah, v.z, v.w);                             \
  }

__global__ void __launch_bounds__(THR, 2)
k_gru_step(const float* __restrict__ state, int t)
{
  extern __shared__ char sraw[];
  GruS& s = *reinterpret_cast<GruS*>(sraw);
  const int bt = blockIdx.x, jt = blockIdx.y, g = blockIdx.z;
  const int tid = threadIdx.x;
  const int pi = t & 1, po = pi ^ 1;

  if (t >= g_tilemax[bt]) return;

  const unsigned mb = smem_u32p(&s.mb[0]);
  const int gjt = g * 4 + jt;

  if (tid == 0) mbar_init(mb, 1);
  __syncthreads();
  if (tid == 0 && t > 0) {
    mbar_expect(mb, 2u * 33792u);
    bulk_g2s(smem_u32p(&s.hsbh[0][0]), &g_hbh[pi][g][bt * TB][0], 33792u, mb);
    bulk_g2s(smem_u32p(&s.hsbl[0][0]), &g_hbl[pi][g][bt * TB][0], 33792u, mb);
  }

  for (int i = tid; i < TB * 8; i += THR) {
    int r = i >> 3, p = i & 7;
    const float* xp = state + (size_t)g_perm[bt * TB + r] * (NT * ND) + (size_t)t * ND;
    float v0 = xp[2 * p];
    float v1 = (p == 7) ? 1.0f : xp[2 * p + 1];
    float h0, l0, h1, l1;
    split2(v0, h0, l0); split2(v1, h1, l1);
    s.xsbh[r][p] = pack_bf16x2(h0, h1);
    s.xsbl[r][p] = pack_bf16x2(l0, l1);
  }
  if (tid < TB) s.ls[tid] = g_lsort[bt * TB + tid];
  __syncthreads();
  if (t > 0) mbar_wait(mb, 0);

  const int w = tid >> 5, lane = tid & 31;
  const int m0 = (w & 3) * 16, jhalf = w >> 2;
  const int rA = m0 + (lane >> 2);
  const int cA = lane & 3;

  const uint4* __restrict__ wb =
      g_wB4 + (((size_t)gjt * NKT) * 32 + jhalf * 4) * 32 + lane;

  float acc[4][4][4];
  #pragma unroll
  for (int a = 0; a < 4; ++a)
    #pragma unroll
    for (int b = 0; b < 4; ++b)
      #pragma unroll
      for (int c = 0; c < 4; ++c) acc[a][b][c] = 0.f;

  u32 ah[4], al[4];

  if (t > 0) {
    #pragma unroll 4
    for (int kt = 0; kt < 16; ++kt) {
      int cb = kt * 8 + cA;
      ah[0] = s.hsbh[rA][cb];     ah[1] = s.hsbh[rA + 8][cb];
      ah[2] = s.hsbh[rA][cb + 4]; ah[3] = s.hsbh[rA + 8][cb + 4];
      al[0] = s.hsbl[rA][cb];     al[1] = s.hsbl[rA + 8][cb];
      al[2] = s.hsbl[rA][cb + 4]; al[3] = s.hsbl[rA + 8][cb + 4];
      const uint4* __restrict__ pkt = wb + kt * 1024;
      MMA3(0, 0, 0 * 32)   MMA3(0, 1, 1 * 32)   MMA3(0, 2, 2 * 32)   MMA3(0, 3, 3 * 32)
      MMA3(1, 0, 8 * 32)   MMA3(1, 1, 9 * 32)   MMA3(1, 2, 10 * 32)  MMA3(1, 3, 11 * 32)
      MMA3(2, 0, 16 * 32)  MMA3(2, 1, 17 * 32)  MMA3(2, 2, 18 * 32)  MMA3(2, 3, 19 * 32)
    }
  }
  {
    ah[0] = s.xsbh[rA][cA];     ah[1] = s.xsbh[rA + 8][cA];
    ah[2] = s.xsbh[rA][cA + 4]; ah[3] = s.xsbh[rA + 8][cA + 4];
    al[0] = s.xsbl[rA][cA];     al[1] = s.xsbl[rA + 8][cA];
    al[2] = s.xsbl[rA][cA + 4]; al[3] = s.xsbl[rA + 8][cA + 4];
    const uint4* __restrict__ pkt = wb + 16 * 1024;
    MMA3(0, 0, 0 * 32)   MMA3(0, 1, 1 * 32)   MMA3(0, 2, 2 * 32)   MMA3(0, 3, 3 * 32)
    MMA3(1, 0, 8 * 32)   MMA3(1, 1, 9 * 32)   MMA3(1, 2, 10 * 32)  MMA3(1, 3, 11 * 32)
    MMA3(2, 0, 16 * 32)  MMA3(2, 1, 17 * 32)  MMA3(2, 2, 18 * 32)  MMA3(2, 3, 19 * 32)
    MMA3(3, 0, 24 * 32)  MMA3(3, 1, 25 * 32)  MMA3(3, 2, 26 * 32)  MMA3(3, 3, 27 * 32)
  }

  #pragma unroll
  for (int q = 0; q < 4; ++q) {
    #pragma unroll
    for (int half = 0; half < 2; ++half) {
      int rl = m0 + (lane >> 2) + half * 8;
      bool act = (t < s.ls[rl]);
      int jloc = jhalf * 32 + q * 8 + 2 * (lane & 3);
      int jg = jt * 64 + jloc;
      float hold0 = 0.f, hold1 = 0.f;
      if (t > 0) {
        u32 vh = s.hsbh[rl][jg >> 1];
        u32 vl = s.hsbl[rl][jg >> 1];
        hold0 = bf16_lo_f(vh) + bf16_lo_f(vl);
        hold1 = bf16_hi_f(vh) + bf16_hi_f(vl);
      }
      float hn[2];
      #pragma unroll
      for (int e = 0; e < 2; ++e) {
        float xr = acc[0][q][half * 2 + e];
        float xz = acc[1][q][half * 2 + e];
        float xhn = acc[2][q][half * 2 + e];
        float xin = acc[3][q][half * 2 + e];
        float hold = e ? hold1 : hold0;
        if (act) {
          float r = __fdividef(1.f, 1.f + __expf(-xr));
          float z = __fdividef(1.f, 1.f + __expf(-xz));
          float n = tanhf(fmaf(r, xhn, xin));
          hn[e] = fmaf(z, hold - n, n);
        } else {
          hn[e] = hold;
        }
      }
      float h0, l0, h1, l1;
      split2(hn[0], h0, l0); split2(hn[1], h1, l1);
      int grow = bt * TB + rl;
      g_hbh[po][g][grow][jg >> 1] = pack_bf16x2(h0, h1);
      g_hbl[po][g][grow][jg >> 1] = pack_bf16x2(l0, l1);
    }
  }
}

// ---------------- concat -> xin bf16 pairs [NB][136] ----------------
__global__ void k_concat2(const float* __restrict__ state,
                          const float* __restrict__ action, int br) {
  int b = blockIdx.x;
  int p = g_invpos[b];
  int fp = g_finparp[p];
  for (int c = threadIdx.x; c < 136; c += 64) {
    float v0, v1;
    if (c < 7) {
      v0 = state[(size_t)b * NT * ND + 2 * c];
      v1 = state[(size_t)b * NT * ND + 2 * c + 1];
    } else if (c == 7) {
      v0 = state[(size_t)b * NT * ND + 14];
      v1 = action[b];
    } else {
      u32 vh = g_hbh[fp][br][p][c - 8];
      u32 vl = g_hbl[fp][br][p][c - 8];
      v0 = bf16_lo_f(vh) + bf16_lo_f(vl);
      v1 = bf16_hi_f(vh) + bf16_hi_f(vl);
    }
    float h0, l0, h1, l1;
    split2(v0, h0, l0); split2(v1, h1, l1);
    g_xh[b][c] = pack_bf16x2(h0, h1);
    g_xl[b][c] = pack_bf16x2(l0, l1);
  }
}

// ---------------- tensor-core MLP layer: O = relu(A @ W^T + b), pairs in/out ----------------
__global__ void __launch_bounds__(128)
k_tmma(const u32* __restrict__ Ah, const u32* __restrict__ Al,
       const uint4* __restrict__ Wfrag, const float* __restrict__ bias,
       u32* __restrict__ Oh, u32* __restrict__ Ol,
       int KT, int NTGtot, int relu)
{
  const int w = threadIdx.x >> 5, lane = threadIdx.x & 31;
  const int m0 = blockIdx.x * 64 + w * 16;
  const int ntg0 = blockIdx.y * 8;
  const int K2 = KT * 8;
  const int rA = m0 + (lane >> 2);
  const int cA = lane & 3;
  const int outK2 = NTGtot * 4;

  const u32* __restrict__ pAh = Ah + (size_t)rA * K2 + cA;
  const u32* __restrict__ pAl = Al + (size_t)rA * K2 + cA;
  const uint4* __restrict__ wb = Wfrag + (size_t)ntg0 * 32 + lane;
  const size_t rstep = (size_t)8 * K2;

  float acc[8][4];
  #pragma unroll
  for (int q = 0; q < 8; ++q)
    #pragma unroll
    for (int c = 0; c < 4; ++c) acc[q][c] = 0.f;

  for (int kt = 0; kt < KT; ++kt) {
    u32 ah[4], al[4];
    int o = kt * 8;
    ah[0] = pAh[o];         ah[1] = pAh[o + rstep];
    ah[2] = pAh[o + 4];     ah[3] = pAh[o + 4 + rstep];
    al[0] = pAl[o];         al[1] = pAl[o + rstep];
    al[2] = pAl[o + 4];     al[3] = pAl[o + 4 + rstep];
    const uint4* __restrict__ pkt = wb + (size_t)kt * NTGtot * 32;
    #pragma unroll
    for (int q = 0; q < 8; ++q) {
      uint4 v = pkt[q * 32];
      mma_bf16(acc[q], ah, v.x, v.y);
      mma_bf16(acc[q], al, v.x, v.y);
      mma_bf16(acc[q], ah, v.z, v.w);
    }
  }

  #pragma unroll
  for (int q = 0; q < 8; ++q) {
    int n0 = (ntg0 + q) * 8 + 2 * (lane & 3);
    float b0 = bias[n0], b1 = bias[n0 + 1];
    float c0 = acc[q][0] + b0, c1 = acc[q][1] + b1;   // row rA
    float c2 = acc[q][2] + b0, c3 = acc[q][3] + b1;   // row rA+8
    if (relu) {
      c0 = fmaxf(c0, 0.f); c1 = fmaxf(c1, 0.f);
      c2 = fmaxf(c2, 0.f); c3 = fmaxf(c3, 0.f);
    }
    float h0, l0, h1, l1;
    split2(c0, h0, l0); split2(c1, h1, l1);
    size_t o0 = (size_t)rA * outK2 + (n0 >> 1);
    Oh[o0] = pack_bf16x2(h0, h1);
    Ol[o0] = pack_bf16x2(l0, l1);
    split2(c2, h0, l0); split2(c3, h1, l1);
    size_t o1 = (size_t)(rA + 8) * outK2 + (n0 >> 1);
    Oh[o1] = pack_bf16x2(h0, h1);
    Ol[o1] = pack_bf16x2(l0, l1);
  }
}

// ---------------- q head (reads bf16 pairs) ----------------
__global__ void k_q2(const u32* __restrict__ Ah, const u32* __restrict__ Al,
                     const float* __restrict__ qw, const float* __restrict__ qb,
                     float* __restrict__ out)
{
  __shared__ float red[64];
  int b = blockIdx.x;
  float sum = 0.f;
  for (int p = threadIdx.x; p < 128; p += 64) {
    u32 vh = Ah[(size_t)b * 128 + p];
    u32 vl = Al[(size_t)b * 128 + p];
    float v0 = bf16_lo_f(vh) + bf16_lo_f(vl);
    float v1 = bf16_hi_f(vh) + bf16_hi_f(vl);
    sum += v0 * qw[2 * p] + v1 * qw[2 * p + 1];
  }
  red[threadIdx.x] = sum;
  __syncthreads();
  if (threadIdx.x < 32) {
    float v = red[threadIdx.x] + red[threadIdx.x + 32];
    #pragma unroll
    for (int o = 16; o; o >>= 1) v += __shfl_down_sync(0xffffffffu, v, o);
    if (threadIdx.x == 0) out[b] = v + qb[0];
  }
}

// ---------------- launch ----------------
extern "C" void kernel_launch(void* const* d_in, const int* in_sizes, int n_in,
                              void* d_out, int out_size)
{
  const float* state   = (const float*)d_in[0];
  const float* action  = (const float*)d_in[1];
  const int*   lengths = (const int*)d_in[2];

  const float* gWih[2]; const float* gWhh[2];
  const float* gbih[2]; const float* gbhh[2];
  const float* fcw[2][5]; const float* fcb[2][5];
  for (int br = 0; br < 2; ++br) {
    int base = 3 + br * 14;
    gWih[br] = (const float*)d_in[base + 0];
    gWhh[br] = (const float*)d_in[base + 1];
    gbih[br] = (const float*)d_in[base + 2];
    gbhh[br] = (const float*)d_in[base + 3];
    for (int l = 0; l < 5; ++l) {
      fcw[br][l] = (const float*)d_in[base + 4 + 2 * l];
      fcb[br][l] = (const float*)d_in[base + 5 + 2 * l];
    }
  }

  u32 *p_xh, *p_xl, *p_m0h, *p_m0l, *p_m1h, *p_m1l;
  uint4* p_mlpB;
  cudaGetSymbolAddress((void**)&p_xh, g_xh);
  cudaGetSymbolAddress((void**)&p_xl, g_xl);
  cudaGetSymbolAddress((void**)&p_m0h, g_m0h);
  cudaGetSymbolAddress((void**)&p_m0l, g_m0l);
  cudaGetSymbolAddress((void**)&p_m1h, g_m1h);
  cudaGetSymbolAddress((void**)&p_m1l, g_m1l);
  cudaGetSymbolAddress((void**)&p_mlpB, g_mlpB);

  cudaFuncSetAttribute(k_gru_step, cudaFuncAttributeMaxDynamicSharedMemorySize,
                       (int)sizeof(GruS));

  // prep
  k_sort<<<1, 1024>>>(lengths);
  k_prep<<<(2 * 4 * NKT * 32 * 32 + 255) / 256, 256>>>(gWhh[0], gWhh[1],
                                                       gWih[0], gbih[0], gbhh[0],
                                                       gWih[1], gbih[1], gbhh[1]);
  const int loff[4] = {OFF_L1, OFF_L2, OFF_L3, OFF_L4};
  const int lKT[4]  = {17, 64, 64, 32};
  const int lNTG[4] = {128, 128, 64, 32};
  for (int br = 0; br < 2; ++br) {
    for (int l = 0; l < 4; ++l) {
      int cnt = lKT[l] * lNTG[l] * 32;
      k_packw<<<(cnt + 255) / 256, 256>>>(fcw[br][l], lKT[l], lNTG[l], lKT[l] * 16,
                                          p_mlpB + (size_t)br * MLPB_BR + loff[l]);
    }
  }

  // recurrent steps
  for (int t = 0; t < NT; ++t) {
    k_gru_step<<<dim3(NBT, 4, 2), THR, sizeof(GruS)>>>(state, t);
  }

  // MLP branches (tensor cores)
  float* outp = (float*)d_out;
  for (int br = 0; br < 2; ++br) {
    const uint4* wbB = p_mlpB + (size_t)br * MLPB_BR;
    k_concat2<<<NB, 64>>>(state, action, br);
    k_tmma<<<dim3(32, 16), 128>>>(p_xh, p_xl, wbB + OFF_L1, fcb[br][0],
                                  p_m0h, p_m0l, 17, 128, 1);
    k_tmma<<<dim3(32, 16), 128>>>(p_m0h, p_m0l, wbB + OFF_L2, fcb[br][1],
                                  p_m1h, p_m1l, 64, 128, 1);
    k_tmma<<<dim3(32, 8), 128>>>(p_m1h, p_m1l, wbB + OFF_L3, fcb[br][2],
                                 p_m0h, p_m0l, 64, 64, 1);
    k_tmma<<<dim3(32, 4), 128>>>(p_m0h, p_m0l, wbB + OFF_L4, fcb[br][3],
                                 p_m1h, p_m1l, 32, 32, 1);
    k_q2<<<NB, 64>>>(p_m1h, p_m1l, fcw[br][4], fcb[br][4], outp + (size_t)br * NB);
  }
}

// round 13
// speedup vs baseline: 3.5920x; 1.0809x over previous
#include <cuda_runtime.h>
#include <math.h>

#define NB 2048
#define NT 64
#define ND 15
#define NH 256
#define TB 64
#define NBT 32       // NB / TB
#define THR 256
#define NKT 17       // GRU k-tiles: 16 h-tiles + 1 (x|1) tile  (K = 272)

// MLP packed-fragment layout (uint4 units)
#define MLPB_BR 495616
#define OFF_L1 0
#define OFF_L2 69632
#define OFF_L3 331776
#define OFF_L4 462848

typedef unsigned long long u64;
typedef unsigned u32;

// ---------------- bf16 helpers ----------------
__device__ __forceinline__ u32 pack_bf16x2(float e, float o) {   // low half = e
  u32 r; asm("cvt.rn.bf16x2.f32 %0, %1, %2;" : "=r"(r) : "f"(o), "f"(e)); return r;
}
__device__ __forceinline__ float bf16_lo_f(u32 v) { return __uint_as_float(v << 16); }
__device__ __forceinline__ float bf16_hi_f(u32 v) { return __uint_as_float(v & 0xffff0000u); }
__device__ __forceinline__ void split2(float v, float& hi, float& lo) {
  u32 h; asm("cvt.rn.bf16x2.f32 %0, %1, %2;" : "=r"(h) : "f"(0.f), "f"(v));
  hi = __uint_as_float(h << 16);
  lo = v - hi;
}

// ---------------- mma m16n8k16 bf16 ----------------
__device__ __forceinline__ void mma_bf16(float* d, const u32* a, u32 b0, u32 b1) {
  asm("mma.sync.aligned.m16n8k16.row.col.f32.bf16.bf16.f32 "
      "{%0,%1,%2,%3}, {%4,%5,%6,%7}, {%8,%9}, {%0,%1,%2,%3};"
      : "+f"(d[0]), "+f"(d[1]), "+f"(d[2]), "+f"(d[3])
      : "r"(a[0]), "r"(a[1]), "r"(a[2]), "r"(a[3]), "r"(b0), "r"(b1));
}

// ---------------- mbarrier / bulk-copy ----------------
__device__ __forceinline__ unsigned smem_u32p(const void* p) {
  unsigned a;
  asm("{ .reg .u64 t; cvta.to.shared.u64 t, %1; cvt.u32.u64 %0, t; }" : "=r"(a) : "l"(p));
  return a;
}
__device__ __forceinline__ void mbar_init(unsigned mbar, unsigned cnt) {
  asm volatile("mbarrier.init.shared.b64 [%0], %1;" :: "r"(mbar), "r"(cnt) : "memory");
}
__device__ __forceinline__ void mbar_expect(unsigned mbar, unsigned bytes) {
  asm volatile("mbarrier.arrive.expect_tx.shared.b64 _, [%0], %1;"
               :: "r"(mbar), "r"(bytes) : "memory");
}
__device__ __forceinline__ void bulk_g2s(unsigned dst, const void* src,
                                         unsigned bytes, unsigned mbar) {
  asm volatile(
      "cp.async.bulk.shared::cta.global.mbarrier::complete_tx::bytes [%0], [%1], %2, [%3];"
      :: "r"(dst), "l"(src), "r"(bytes), "r"(mbar) : "memory");
}
__device__ __forceinline__ void mbar_wait(unsigned mbar, unsigned parity) {
  asm volatile(
      "{\n\t.reg .pred P;\n\t"
      "W%=:\n\t"
      "mbarrier.try_wait.parity.acquire.cta.shared::cta.b64 P, [%0], %1, 0x989680;\n\t"
      "@P bra.uni D%=;\n\t"
      "bra.uni W%=;\n\t"
      "D%=:\n\t}"
      :: "r"(mbar), "r"(parity) : "memory");
}

// ---------------- device scratch ----------------
__device__ u32   g_hbh[2][2][NB][132];   // [parity][gru][sorted row][k-pair] bf16x2 hi
__device__ u32   g_hbl[2][2][NB][132];
__device__ uint4 g_wB4[2 * 4 * NKT * 32 * 32];   // GRU B fragments
__device__ uint4 g_mlpB[2 * MLPB_BR];            // MLP W fragments
__device__ u32   g_xh[NB][136];
__device__ u32   g_xl[NB][136];
__device__ u32   g_m0h[NB][512];
__device__ u32   g_m0l[NB][512];
__device__ u32   g_m1h[NB][512];
__device__ u32   g_m1l[NB][512];
__device__ unsigned g_sync[64];          // per-(bt,g) monotonic step counters
__device__ int   g_perm[NB];
__device__ int   g_off[66];
__device__ int   g_hist[66];
__device__ int   g_tilemax[NBT];
__device__ int   g_invpos[NB];
__device__ int   g_finparp[NB];
__device__ int   g_lsort[NB];

// ---------------- fused length sort (+ barrier counter reset) ----------------
__global__ void k_sort(const int* __restrict__ lengths) {
  int tid = threadIdx.x;
  if (tid < 66) g_hist[tid] = 0;
  if (tid < 64) g_sync[tid] = 0u;
  __syncthreads();
  for (int b = tid; b < NB; b += 1024) atomicAdd(&g_hist[lengths[b]], 1);
  __syncthreads();
  if (tid == 0) {
    int s = 0;
    for (int l = 0; l < 66; ++l) { g_off[l] = s; s += g_hist[l]; }
  }
  __syncthreads();
  for (int b = tid; b < NB; b += 1024) {
    int p = atomicAdd(&g_off[lengths[b]], 1);
    g_perm[p] = b;
  }
  __syncthreads();
  if (tid < NBT) g_tilemax[tid] = lengths[g_perm[tid * TB + TB - 1]];
  __syncthreads();
  for (int p = tid; p < NB; p += 1024) {
    int b = g_perm[p];
    g_invpos[b] = p;
    g_finparp[p] = g_tilemax[p >> 6] & 1;
    g_lsort[p] = lengths[b];
  }
}

// ---------------- GRU B-value oracle (fp32) ----------------
__device__ float bval(const float* Whh, const float* Wih,
                      const float* bih, const float* bhh,
                      int jt, int n, int k) {
  int gate = n >> 6;              // 0:r 1:z 2:hn 3:in
  int j = jt * 64 + (n & 63);
  if (k < 256) {
    if (gate == 0) return Whh[(size_t)j * 256 + k];
    if (gate == 1) return Whh[(size_t)(256 + j) * 256 + k];
    if (gate == 2) return Whh[(size_t)(512 + j) * 256 + k];
    return 0.f;
  } else if (k < 271) {
    int i = k - 256;
    if (gate == 0) return Wih[(size_t)j * ND + i];
    if (gate == 1) return Wih[(size_t)(256 + j) * ND + i];
    if (gate == 2) return 0.f;
    return Wih[(size_t)(512 + j) * ND + i];
  } else {
    if (gate == 0) return bih[j] + bhh[j];
    if (gate == 1) return bih[256 + j] + bhh[256 + j];
    if (gate == 2) return bhh[512 + j];
    return bih[512 + j];
  }
}

// ---------------- GRU prep: pack B fragments ----------------
__global__ void k_prep(const float* __restrict__ Whh0, const float* __restrict__ Whh1,
                       const float* __restrict__ Wih0, const float* __restrict__ bih0,
                       const float* __restrict__ bhh0,
                       const float* __restrict__ Wih1, const float* __restrict__ bih1,
                       const float* __restrict__ bhh1) {
  int i = blockIdx.x * blockDim.x + threadIdx.x;
  if (i >= 2 * 4 * NKT * 32 * 32) return;
  int lane = i & 31;
  int nt   = (i >> 5) & 31;
  int kt   = (i >> 10) % NKT;
  int jt   = (i / (1024 * NKT)) & 3;
  int g    = i / (1024 * NKT * 4);
  const float* Whh = g ? Whh1 : Whh0;
  const float* Wih = g ? Wih1 : Wih0;
  const float* bih = g ? bih1 : bih0;
  const float* bhh = g ? bhh1 : bhh0;
  int n = nt * 8 + (lane >> 2);
  u32 out[4];
  #pragma unroll
  for (int reg = 0; reg < 2; ++reg) {
    int k0 = kt * 16 + 2 * (lane & 3) + reg * 8;
    float v0 = bval(Whh, Wih, bih, bhh, jt, n, k0);
    float v1 = bval(Whh, Wih, bih, bhh, jt, n, k0 + 1);
    float h0, l0, h1, l1;
    split2(v0, h0, l0); split2(v1, h1, l1);
    out[reg]     = pack_bf16x2(h0, h1);
    out[2 + reg] = pack_bf16x2(l0, l1);
  }
  g_wB4[i] = make_uint4(out[0], out[1], out[2], out[3]);
}

// ---------------- MLP prep: pack W[N][K] fragments ----------------
__global__ void k_packw(const float* __restrict__ W, int KT, int NTGtot, int K,
                        uint4* __restrict__ dst) {
  int i = blockIdx.x * blockDim.x + threadIdx.x;
  if (i >= KT * NTGtot * 32) return;
  int lane = i & 31;
  int ntg  = (i >> 5) % NTGtot;
  int kt   = (i >> 5) / NTGtot;
  int n = ntg * 8 + (lane >> 2);
  u32 out[4];
  #pragma unroll
  for (int reg = 0; reg < 2; ++reg) {
    int k0 = kt * 16 + 2 * (lane & 3) + reg * 8;
    float v0 = W[(size_t)n * K + k0];
    float v1 = W[(size_t)n * K + k0 + 1];
    float h0, l0, h1, l1;
    split2(v0, h0, l0); split2(v1, h1, l1);
    out[reg]     = pack_bf16x2(h0, h1);
    out[2 + reg] = pack_bf16x2(l0, l1);
  }
  dst[i] = make_uint4(out[0], out[1], out[2], out[3]);
}

// ---------------- persistent GRU kernel ----------------
struct GruS {
  u32 hsbh[TB][132];
  u32 hsbl[TB][132];
  u32 xsbh[TB][9];
  u32 xsbl[TB][9];
  int ls[TB];
  u64 mb[2];
};

#define MMA3(g4, q, off)                                            \
  {                                                                 \
    uint4 v = pkt[(off)];                                           \
    mma_bf16(acc[g4][q], ah, v.x, v.y);                             \
    mma_bf16(acc[g4][q], al, v.x, v.y);                             \
    mma_bf16(acc[g4][q], ah, v.z, v.w);                             \
  }

__global__ void __launch_bounds__(THR, 2)
k_gru_persist(const float* __restrict__ state)
{
  extern __shared__ char sraw[];
  GruS& s = *reinterpret_cast<GruS*>(sraw);
  const int jt  = blockIdx.x & 3;
  const int gid = blockIdx.x >> 2;          // 0..63 = bt*2 + g
  const int bt  = gid >> 1;
  const int g   = gid & 1;
  const int tid = threadIdx.x;
  const int tmax = g_tilemax[bt];
  const int gjt = g * 4 + jt;

  const unsigned mb = smem_u32p(&s.mb[0]);
  if (tid == 0) mbar_init(mb, 1);
  if (tid < TB) s.ls[tid] = g_lsort[bt * TB + tid];
  __syncthreads();

  const int w = tid >> 5, lane = tid & 31;
  const int m0 = (w & 3) * 16, jhalf = w >> 2;
  const int rA = m0 + (lane >> 2);
  const int cA = lane & 3;
  const uint4* __restrict__ wb =
      g_wB4 + (((size_t)gjt * NKT) * 32 + jhalf * 4) * 32 + lane;

  int ph = 0;
  for (int t = 0; t < tmax; ++t) {
    const int pi = t & 1, po = pi ^ 1;

    if (tid == 0 && t > 0) {
      mbar_expect(mb, 2u * 33792u);
      bulk_g2s(smem_u32p(&s.hsbh[0][0]), &g_hbh[pi][g][bt * TB][0], 33792u, mb);
      bulk_g2s(smem_u32p(&s.hsbl[0][0]), &g_hbl[pi][g][bt * TB][0], 33792u, mb);
    }

    // x gather -> bf16 hi/lo pairs; slot 7 = (x14, 1.0) (bias row rides k=271)
    for (int i = tid; i < TB * 8; i += THR) {
      int r = i >> 3, p = i & 7;
      const float* xp = state + (size_t)g_perm[bt * TB + r] * (NT * ND) + (size_t)t * ND;
      float v0 = xp[2 * p];
      float v1 = (p == 7) ? 1.0f : xp[2 * p + 1];
      float h0, l0, h1, l1;
      split2(v0, h0, l0); split2(v1, h1, l1);
      s.xsbh[r][p] = pack_bf16x2(h0, h1);
      s.xsbl[r][p] = pack_bf16x2(l0, l1);
    }
    __syncthreads();
    if (t > 0) { mbar_wait(mb, ph); ph ^= 1; }

    float acc[4][4][4];
    #pragma unroll
    for (int a = 0; a < 4; ++a)
      #pragma unroll
      for (int b = 0; b < 4; ++b)
        #pragma unroll
        for (int c = 0; c < 4; ++c) acc[a][b][c] = 0.f;

    u32 ah[4], al[4];

    if (t > 0) {
      #pragma unroll 4
      for (int kt = 0; kt < 16; ++kt) {
        int cb = kt * 8 + cA;
        ah[0] = s.hsbh[rA][cb];     ah[1] = s.hsbh[rA + 8][cb];
        ah[2] = s.hsbh[rA][cb + 4]; ah[3] = s.hsbh[rA + 8][cb + 4];
        al[0] = s.hsbl[rA][cb];     al[1] = s.hsbl[rA + 8][cb];
        al[2] = s.hsbl[rA][cb + 4]; al[3] = s.hsbl[rA + 8][cb + 4];
        const uint4* __restrict__ pkt = wb + kt * 1024;
        MMA3(0, 0, 0 * 32)   MMA3(0, 1, 1 * 32)   MMA3(0, 2, 2 * 32)   MMA3(0, 3, 3 * 32)
        MMA3(1, 0, 8 * 32)   MMA3(1, 1, 9 * 32)   MMA3(1, 2, 10 * 32)  MMA3(1, 3, 11 * 32)
        MMA3(2, 0, 16 * 32)  MMA3(2, 1, 17 * 32)  MMA3(2, 2, 18 * 32)  MMA3(2, 3, 19 * 32)
      }
    }
    {
      ah[0] = s.xsbh[rA][cA];     ah[1] = s.xsbh[rA + 8][cA];
      ah[2] = s.xsbh[rA][cA + 4]; ah[3] = s.xsbh[rA + 8][cA + 4];
      al[0] = s.xsbl[rA][cA];     al[1] = s.xsbl[rA + 8][cA];
      al[2] = s.xsbl[rA][cA + 4]; al[3] = s.xsbl[rA + 8][cA + 4];
      const uint4* __restrict__ pkt = wb + 16 * 1024;
      MMA3(0, 0, 0 * 32)   MMA3(0, 1, 1 * 32)   MMA3(0, 2, 2 * 32)   MMA3(0, 3, 3 * 32)
      MMA3(1, 0, 8 * 32)   MMA3(1, 1, 9 * 32)   MMA3(1, 2, 10 * 32)  MMA3(1, 3, 11 * 32)
      MMA3(2, 0, 16 * 32)  MMA3(2, 1, 17 * 32)  MMA3(2, 2, 18 * 32)  MMA3(2, 3, 19 * 32)
      MMA3(3, 0, 24 * 32)  MMA3(3, 1, 25 * 32)  MMA3(3, 2, 26 * 32)  MMA3(3, 3, 27 * 32)
    }

    // gates + masked update + write
    #pragma unroll
    for (int q = 0; q < 4; ++q) {
      #pragma unroll
      for (int half = 0; half < 2; ++half) {
        int rl = m0 + (lane >> 2) + half * 8;
        bool act = (t < s.ls[rl]);
        int jloc = jhalf * 32 + q * 8 + 2 * (lane & 3);
        int jg = jt * 64 + jloc;
        float hold0 = 0.f, hold1 = 0.f;
        if (t > 0) {
          u32 vh = s.hsbh[rl][jg >> 1];
          u32 vl = s.hsbl[rl][jg >> 1];
          hold0 = bf16_lo_f(vh) + bf16_lo_f(vl);
          hold1 = bf16_hi_f(vh) + bf16_hi_f(vl);
        }
        float hn[2];
        #pragma unroll
        for (int e = 0; e < 2; ++e) {
          float xr = acc[0][q][half * 2 + e];
          float xz = acc[1][q][half * 2 + e];
          float xhn = acc[2][q][half * 2 + e];
          float xin = acc[3][q][half * 2 + e];
          float hold = e ? hold1 : hold0;
          if (act) {
            float r = __fdividef(1.f, 1.f + __expf(-xr));
            float z = __fdividef(1.f, 1.f + __expf(-xz));
            float n = tanhf(fmaf(r, xhn, xin));
            hn[e] = fmaf(z, hold - n, n);
          } else {
            hn[e] = hold;
          }
        }
        float h0, l0, h1, l1;
        split2(hn[0], h0, l0); split2(hn[1], h1, l1);
        int grow = bt * TB + rl;
        g_hbh[po][g][grow][jg >> 1] = pack_bf16x2(h0, h1);
        g_hbl[po][g][grow][jg >> 1] = pack_bf16x2(l0, l1);
      }
    }

    // group barrier (4 CTAs sharing (bt,g)); skip after the final step
    if (t + 1 < tmax) {
      __threadfence();
      __syncthreads();
      if (tid == 0) {
        unsigned target = 4u * (unsigned)(t + 1);
        atomicAdd(&g_sync[gid], 1u);
        while (*(volatile unsigned*)&g_sync[gid] < target) __nanosleep(64);
      }
      __syncthreads();
    }
  }
}

// ---------------- concat -> xin bf16 pairs [NB][136] ----------------
__global__ void k_concat2(const float* __restrict__ state,
                          const float* __restrict__ action, int br) {
  int b = blockIdx.x;
  int p = g_invpos[b];
  int fp = g_finparp[p];
  for (int c = threadIdx.x; c < 136; c += 64) {
    float v0, v1;
    if (c < 7) {
      v0 = state[(size_t)b * NT * ND + 2 * c];
      v1 = state[(size_t)b * NT * ND + 2 * c + 1];
    } else if (c == 7) {
      v0 = state[(size_t)b * NT * ND + 14];
      v1 = action[b];
    } else {
      u32 vh = g_hbh[fp][br][p][c - 8];
      u32 vl = g_hbl[fp][br][p][c - 8];
      v0 = bf16_lo_f(vh) + bf16_lo_f(vl);
      v1 = bf16_hi_f(vh) + bf16_hi_f(vl);
    }
    float h0, l0, h1, l1;
    split2(v0, h0, l0); split2(v1, h1, l1);
    g_xh[b][c] = pack_bf16x2(h0, h1);
    g_xl[b][c] = pack_bf16x2(l0, l1);
  }
}

// ---------------- tensor-core MLP layer ----------------
__global__ void __launch_bounds__(128)
k_tmma(const u32* __restrict__ Ah, const u32* __restrict__ Al,
       const uint4* __restrict__ Wfrag, const float* __restrict__ bias,
       u32* __restrict__ Oh, u32* __restrict__ Ol,
       int KT, int NTGtot, int relu)
{
  const int w = threadIdx.x >> 5, lane = threadIdx.x & 31;
  const int m0 = blockIdx.x * 64 + w * 16;
  const int ntg0 = blockIdx.y * 8;
  const int K2 = KT * 8;
  const int rA = m0 + (lane >> 2);
  const int cA = lane & 3;
  const int outK2 = NTGtot * 4;

  const u32* __restrict__ pAh = Ah + (size_t)rA * K2 + cA;
  const u32* __restrict__ pAl = Al + (size_t)rA * K2 + cA;
  const uint4* __restrict__ wb = Wfrag + (size_t)ntg0 * 32 + lane;
  const size_t rstep = (size_t)8 * K2;

  float acc[8][4];
  #pragma unroll
  for (int q = 0; q < 8; ++q)
    #pragma unroll
    for (int c = 0; c < 4; ++c) acc[q][c] = 0.f;

  for (int kt = 0; kt < KT; ++kt) {
    u32 ah[4], al[4];
    int o = kt * 8;
    ah[0] = pAh[o];         ah[1] = pAh[o + rstep];
    ah[2] = pAh[o + 4];     ah[3] = pAh[o + 4 + rstep];
    al[0] = pAl[o];         al[1] = pAl[o + rstep];
    al[2] = pAl[o + 4];     al[3] = pAl[o + 4 + rstep];
    const uint4* __restrict__ pkt = wb + (size_t)kt * NTGtot * 32;
    #pragma unroll
    for (int q = 0; q < 8; ++q) {
      uint4 v = pkt[q * 32];
      mma_bf16(acc[q], ah, v.x, v.y);
      mma_bf16(acc[q], al, v.x, v.y);
      mma_bf16(acc[q], ah, v.z, v.w);
    }
  }

  #pragma unroll
  for (int q = 0; q < 8; ++q) {
    int n0 = (ntg0 + q) * 8 + 2 * (lane & 3);
    float b0 = bias[n0], b1 = bias[n0 + 1];
    float c0 = acc[q][0] + b0, c1 = acc[q][1] + b1;
    float c2 = acc[q][2] + b0, c3 = acc[q][3] + b1;
    if (relu) {
      c0 = fmaxf(c0, 0.f); c1 = fmaxf(c1, 0.f);
      c2 = fmaxf(c2, 0.f); c3 = fmaxf(c3, 0.f);
    }
    float h0, l0, h1, l1;
    split2(c0, h0, l0); split2(c1, h1, l1);
    size_t o0 = (size_t)rA * outK2 + (n0 >> 1);
    Oh[o0] = pack_bf16x2(h0, h1);
    Ol[o0] = pack_bf16x2(l0, l1);
    split2(c2, h0, l0); split2(c3, h1, l1);
    size_t o1 = (size_t)(rA + 8) * outK2 + (n0 >> 1);
    Oh[o1] = pack_bf16x2(h0, h1);
    Ol[o1] = pack_bf16x2(l0, l1);
  }
}

// ---------------- q head ----------------
__global__ void k_q2(const u32* __restrict__ Ah, const u32* __restrict__ Al,
                     const float* __restrict__ qw, const float* __restrict__ qb,
                     float* __restrict__ out)
{
  __shared__ float red[64];
  int b = blockIdx.x;
  float sum = 0.f;
  for (int p = threadIdx.x; p < 128; p += 64) {
    u32 vh = Ah[(size_t)b * 128 + p];
    u32 vl = Al[(size_t)b * 128 + p];
    float v0 = bf16_lo_f(vh) + bf16_lo_f(vl);
    float v1 = bf16_hi_f(vh) + bf16_hi_f(vl);
    sum += v0 * qw[2 * p] + v1 * qw[2 * p + 1];
  }
  red[threadIdx.x] = sum;
  __syncthreads();
  if (threadIdx.x < 32) {
    float v = red[threadIdx.x] + red[threadIdx.x + 32];
    #pragma unroll
    for (int o = 16; o; o >>= 1) v += __shfl_down_sync(0xffffffffu, v, o);
    if (threadIdx.x == 0) out[b] = v + qb[0];
  }
}

// ---------------- launch ----------------
extern "C" void kernel_launch(void* const* d_in, const int* in_sizes, int n_in,
                              void* d_out, int out_size)
{
  const float* state   = (const float*)d_in[0];
  const float* action  = (const float*)d_in[1];
  const int*   lengths = (const int*)d_in[2];

  const float* gWih[2]; const float* gWhh[2];
  const float* gbih[2]; const float* gbhh[2];
  const float* fcw[2][5]; const float* fcb[2][5];
  for (int br = 0; br < 2; ++br) {
    int base = 3 + br * 14;
    gWih[br] = (const float*)d_in[base + 0];
    gWhh[br] = (const float*)d_in[base + 1];
    gbih[br] = (const float*)d_in[base + 2];
    gbhh[br] = (const float*)d_in[base + 3];
    for (int l = 0; l < 5; ++l) {
      fcw[br][l] = (const float*)d_in[base + 4 + 2 * l];
      fcb[br][l] = (const float*)d_in[base + 5 + 2 * l];
    }
  }

  u32 *p_xh, *p_xl, *p_m0h, *p_m0l, *p_m1h, *p_m1l;
  uint4* p_mlpB;
  cudaGetSymbolAddress((void**)&p_xh, g_xh);
  cudaGetSymbolAddress((void**)&p_xl, g_xl);
  cudaGetSymbolAddress((void**)&p_m0h, g_m0h);
  cudaGetSymbolAddress((void**)&p_m0l, g_m0l);
  cudaGetSymbolAddress((void**)&p_m1h, g_m1h);
  cudaGetSymbolAddress((void**)&p_m1l, g_m1l);
  cudaGetSymbolAddress((void**)&p_mlpB, g_mlpB);

  cudaFuncSetAttribute(k_gru_persist, cudaFuncAttributeMaxDynamicSharedMemorySize,
                       (int)sizeof(GruS));

  // prep
  k_sort<<<1, 1024>>>(lengths);
  k_prep<<<(2 * 4 * NKT * 32 * 32 + 255) / 256, 256>>>(gWhh[0], gWhh[1],
                                                       gWih[0], gbih[0], gbhh[0],
                                                       gWih[1], gbih[1], gbhh[1]);
  const int loff[4] = {OFF_L1, OFF_L2, OFF_L3, OFF_L4};
  const int lKT[4]  = {17, 64, 64, 32};
  const int lNTG[4] = {128, 128, 64, 32};
  for (int br = 0; br < 2; ++br) {
    for (int l = 0; l < 4; ++l) {
      int cnt = lKT[l] * lNTG[l] * 32;
      k_packw<<<(cnt + 255) / 256, 256>>>(fcw[br][l], lKT[l], lNTG[l], lKT[l] * 16,
                                          p_mlpB + (size_t)br * MLPB_BR + loff[l]);
    }
  }

  // persistent recurrent kernel: 256 CTAs (one wave), per-(bt,g) group barriers
  k_gru_persist<<<256, THR, sizeof(GruS)>>>(state);

  // MLP branches (tensor cores)
  float* outp = (float*)d_out;
  for (int br = 0; br < 2; ++br) {
    const uint4* wbB = p_mlpB + (size_t)br * MLPB_BR;
    k_concat2<<<NB, 64>>>(state, action, br);
    k_tmma<<<dim3(32, 16), 128>>>(p_xh, p_xl, wbB + OFF_L1, fcb[br][0],
                                  p_m0h, p_m0l, 17, 128, 1);
    k_tmma<<<dim3(32, 16), 128>>>(p_m0h, p_m0l, wbB + OFF_L2, fcb[br][1],
                                  p_m1h, p_m1l, 64, 128, 1);
    k_tmma<<<dim3(32, 8), 128>>>(p_m1h, p_m1l, wbB + OFF_L3, fcb[br][2],
                                 p_m0h, p_m0l, 64, 64, 1);
    k_tmma<<<dim3(32, 4), 128>>>(p_m0h, p_m0l, wbB + OFF_L4, fcb[br][3],
                                 p_m1h, p_m1l, 32, 32, 1);
    k_q2<<<NB, 64>>>(p_m1h, p_m1l, fcw[br][4], fcb[br][4], outp + (size_t)br * NB);
  }
}

// round 14
// speedup vs baseline: 3.6096x; 1.0049x over previous
#include <cuda_runtime.h>
#include <math.h>

#define NB 2048
#define NT 64
#define ND 15
#define NH 256
#define TB 64
#define NBT 32       // NB / TB
#define THR 256
#define NKT 17       // GRU k-tiles: 16 h-tiles + 1 (x|1) tile  (K = 272)

// MLP packed-fragment layout (uint4 units)
#define MLPB_BR 495616
#define OFF_L1 0
#define OFF_L2 69632
#define OFF_L3 331776
#define OFF_L4 462848

typedef unsigned long long u64;
typedef unsigned u32;

// ---------------- bf16 helpers ----------------
__device__ __forceinline__ u32 pack_bf16x2(float e, float o) {   // low half = e
  u32 r; asm("cvt.rn.bf16x2.f32 %0, %1, %2;" : "=r"(r) : "f"(o), "f"(e)); return r;
}
__device__ __forceinline__ float bf16_lo_f(u32 v) { return __uint_as_float(v << 16); }
__device__ __forceinline__ float bf16_hi_f(u32 v) { return __uint_as_float(v & 0xffff0000u); }
__device__ __forceinline__ void split2(float v, float& hi, float& lo) {
  u32 h; asm("cvt.rn.bf16x2.f32 %0, %1, %2;" : "=r"(h) : "f"(0.f), "f"(v));
  hi = __uint_as_float(h << 16);
  lo = v - hi;
}

// ---------------- mma m16n8k16 bf16 ----------------
__device__ __forceinline__ void mma_bf16(float* d, const u32* a, u32 b0, u32 b1) {
  asm("mma.sync.aligned.m16n8k16.row.col.f32.bf16.bf16.f32 "
      "{%0,%1,%2,%3}, {%4,%5,%6,%7}, {%8,%9}, {%0,%1,%2,%3};"
      : "+f"(d[0]), "+f"(d[1]), "+f"(d[2]), "+f"(d[3])
      : "r"(a[0]), "r"(a[1]), "r"(a[2]), "r"(a[3]), "r"(b0), "r"(b1));
}

// ---------------- mbarrier / bulk-copy ----------------
__device__ __forceinline__ unsigned smem_u32p(const void* p) {
  unsigned a;
  asm("{ .reg .u64 t; cvta.to.shared.u64 t, %1; cvt.u32.u64 %0, t; }" : "=r"(a) : "l"(p));
  return a;
}
__device__ __forceinline__ void mbar_init(unsigned mbar, unsigned cnt) {
  asm volatile("mbarrier.init.shared.b64 [%0], %1;" :: "r"(mbar), "r"(cnt) : "memory");
}
__device__ __forceinline__ void mbar_expect(unsigned mbar, unsigned bytes) {
  asm volatile("mbarrier.arrive.expect_tx.shared.b64 _, [%0], %1;"
               :: "r"(mbar), "r"(bytes) : "memory");
}
__device__ __forceinline__ void bulk_g2s(unsigned dst, const void* src,
                                         unsigned bytes, unsigned mbar) {
  asm volatile(
      "cp.async.bulk.shared::cta.global.mbarrier::complete_tx::bytes [%0], [%1], %2, [%3];"
      :: "r"(dst), "l"(src), "r"(bytes), "r"(mbar) : "memory");
}
__device__ __forceinline__ void mbar_wait(unsigned mbar, unsigned parity) {
  asm volatile(
      "{\n\t.reg .pred P;\n\t"
      "W%=:\n\t"
      "mbarrier.try_wait.parity.acquire.cta.shared::cta.b64 P, [%0], %1, 0x989680;\n\t"
      "@P bra.uni D%=;\n\t"
      "bra.uni W%=;\n\t"
      "D%=:\n\t}"
      :: "r"(mbar), "r"(parity) : "memory");
}

// ---------------- device scratch ----------------
__device__ u32   g_hbh[2][2][NB][132];   // [parity][gru][sorted row][k-pair] bf16x2 hi
__device__ u32   g_hbl[2][2][NB][132];
__device__ uint4 g_wB4[2 * 4 * NKT * 32 * 32];   // GRU B fragments
__device__ uint4 g_mlpB[2 * MLPB_BR];            // MLP W fragments
__device__ u32   g_xh[NB][136];
__device__ u32   g_xl[NB][136];
__device__ u32   g_m0h[NB][512];
__device__ u32   g_m0l[NB][512];
__device__ u32   g_m1h[NB][512];
__device__ u32   g_m1l[NB][512];
__device__ unsigned g_sync[64];          // per-(bt,g) monotonic step counters
__device__ int   g_perm[NB];
__device__ int   g_off[66];
__device__ int   g_hist[66];
__device__ int   g_tilemax[NBT];
__device__ int   g_invpos[NB];
__device__ int   g_finparp[NB];
__device__ int   g_lsort[NB];

// ---------------- fused length sort (+ barrier counter reset) ----------------
__global__ void k_sort(const int* __restrict__ lengths) {
  int tid = threadIdx.x;
  if (tid < 66) g_hist[tid] = 0;
  if (tid < 64) g_sync[tid] = 0u;
  __syncthreads();
  for (int b = tid; b < NB; b += 1024) atomicAdd(&g_hist[lengths[b]], 1);
  __syncthreads();
  if (tid == 0) {
    int s = 0;
    for (int l = 0; l < 66; ++l) { g_off[l] = s; s += g_hist[l]; }
  }
  __syncthreads();
  for (int b = tid; b < NB; b += 1024) {
    int p = atomicAdd(&g_off[lengths[b]], 1);
    g_perm[p] = b;
  }
  __syncthreads();
  if (tid < NBT) g_tilemax[tid] = lengths[g_perm[tid * TB + TB - 1]];
  __syncthreads();
  for (int p = tid; p < NB; p += 1024) {
    int b = g_perm[p];
    g_invpos[b] = p;
    g_finparp[p] = g_tilemax[p >> 6] & 1;
    g_lsort[p] = lengths[b];
  }
}

// ---------------- GRU B-value oracle (fp32) ----------------
__device__ float bval(const float* Whh, const float* Wih,
                      const float* bih, const float* bhh,
                      int jt, int n, int k) {
  int gate = n >> 6;              // 0:r 1:z 2:hn 3:in
  int j = jt * 64 + (n & 63);
  if (k < 256) {
    if (gate == 0) return Whh[(size_t)j * 256 + k];
    if (gate == 1) return Whh[(size_t)(256 + j) * 256 + k];
    if (gate == 2) return Whh[(size_t)(512 + j) * 256 + k];
    return 0.f;
  } else if (k < 271) {
    int i = k - 256;
    if (gate == 0) return Wih[(size_t)j * ND + i];
    if (gate == 1) return Wih[(size_t)(256 + j) * ND + i];
    if (gate == 2) return 0.f;
    return Wih[(size_t)(512 + j) * ND + i];
  } else {
    if (gate == 0) return bih[j] + bhh[j];
    if (gate == 1) return bih[256 + j] + bhh[256 + j];
    if (gate == 2) return bhh[512 + j];
    return bih[512 + j];
  }
}

// ---------------- GRU prep: pack B fragments ----------------
__global__ void k_prep(const float* __restrict__ Whh0, const float* __restrict__ Whh1,
                       const float* __restrict__ Wih0, const float* __restrict__ bih0,
                       const float* __restrict__ bhh0,
                       const float* __restrict__ Wih1, const float* __restrict__ bih1,
                       const float* __restrict__ bhh1) {
  int i = blockIdx.x * blockDim.x + threadIdx.x;
  if (i >= 2 * 4 * NKT * 32 * 32) return;
  int lane = i & 31;
  int nt   = (i >> 5) & 31;
  int kt   = (i >> 10) % NKT;
  int jt   = (i / (1024 * NKT)) & 3;
  int g    = i / (1024 * NKT * 4);
  const float* Whh = g ? Whh1 : Whh0;
  const float* Wih = g ? Wih1 : Wih0;
  const float* bih = g ? bih1 : bih0;
  const float* bhh = g ? bhh1 : bhh0;
  int n = nt * 8 + (lane >> 2);
  u32 out[4];
  #pragma unroll
  for (int reg = 0; reg < 2; ++reg) {
    int k0 = kt * 16 + 2 * (lane & 3) + reg * 8;
    float v0 = bval(Whh, Wih, bih, bhh, jt, n, k0);
    float v1 = bval(Whh, Wih, bih, bhh, jt, n, k0 + 1);
    float h0, l0, h1, l1;
    split2(v0, h0, l0); split2(v1, h1, l1);
    out[reg]     = pack_bf16x2(h0, h1);
    out[2 + reg] = pack_bf16x2(l0, l1);
  }
  g_wB4[i] = make_uint4(out[0], out[1], out[2], out[3]);
}

// ---------------- MLP prep: pack W[N][K] fragments ----------------
__global__ void k_packw(const float* __restrict__ W, int KT, int NTGtot, int K,
                        uint4* __restrict__ dst) {
  int i = blockIdx.x * blockDim.x + threadIdx.x;
  if (i >= KT * NTGtot * 32) return;
  int lane = i & 31;
  int ntg  = (i >> 5) % NTGtot;
  int kt   = (i >> 5) / NTGtot;
  int n = ntg * 8 + (lane >> 2);
  u32 out[4];
  #pragma unroll
  for (int reg = 0; reg < 2; ++reg) {
    int k0 = kt * 16 + 2 * (lane & 3) + reg * 8;
    float v0 = W[(size_t)n * K + k0];
    float v1 = W[(size_t)n * K + k0 + 1];
    float h0, l0, h1, l1;
    split2(v0, h0, l0); split2(v1, h1, l1);
    out[reg]     = pack_bf16x2(h0, h1);
    out[2 + reg] = pack_bf16x2(l0, l1);
  }
  dst[i] = make_uint4(out[0], out[1], out[2], out[3]);
}

// ---------------- persistent GRU kernel ----------------
struct GruS {
  u32 hsbh[TB][132];
  u32 hsbl[TB][132];
  u32 xsbh[TB][9];
  u32 xsbl[TB][9];
  int ls[TB];
  u64 mb[2];
};

#define MMA3(g4, q, off)                                            \
  {                                                                 \
    uint4 v = pkt[(off)];                                           \
    mma_bf16(acc[g4][q], ah, v.x, v.y);                             \
    mma_bf16(acc[g4][q], al, v.x, v.y);                             \
    mma_bf16(acc[g4][q], ah, v.z, v.w);                             \
  }

__global__ void __launch_bounds__(THR, 2)
k_gru_persist(const float* __restrict__ state)
{
  extern __shared__ char sraw[];
  GruS& s = *reinterpret_cast<GruS*>(sraw);
  const int jt  = blockIdx.x & 3;
  const int gid = blockIdx.x >> 2;          // 0..63 = bt*2 + g
  const int bt  = gid >> 1;
  const int g   = gid & 1;
  const int tid = threadIdx.x;
  const int tmax = g_tilemax[bt];
  const int gjt = g * 4 + jt;

  const unsigned mb = smem_u32p(&s.mb[0]);
  if (tid == 0) mbar_init(mb, 1);
  if (tid < TB) s.ls[tid] = g_lsort[bt * TB + tid];
  __syncthreads();

  const int w = tid >> 5, lane = tid & 31;
  const int m0 = (w & 3) * 16, jhalf = w >> 2;
  const int rA = m0 + (lane >> 2);
  const int cA = lane & 3;
  const uint4* __restrict__ wb =
      g_wB4 + (((size_t)gjt * NKT) * 32 + jhalf * 4) * 32 + lane;

  int ph = 0;
  for (int t = 0; t < tmax; ++t) {
    const int pi = t & 1, po = pi ^ 1;

    if (tid == 0 && t > 0) {
      mbar_expect(mb, 2u * 33792u);
      bulk_g2s(smem_u32p(&s.hsbh[0][0]), &g_hbh[pi][g][bt * TB][0], 33792u, mb);
      bulk_g2s(smem_u32p(&s.hsbl[0][0]), &g_hbl[pi][g][bt * TB][0], 33792u, mb);
    }

    // x gather -> bf16 hi/lo pairs; slot 7 = (x14, 1.0) (bias row rides k=271)
    for (int i = tid; i < TB * 8; i += THR) {
      int r = i >> 3, p = i & 7;
      const float* xp = state + (size_t)g_perm[bt * TB + r] * (NT * ND) + (size_t)t * ND;
      float v0 = xp[2 * p];
      float v1 = (p == 7) ? 1.0f : xp[2 * p + 1];
      float h0, l0, h1, l1;
      split2(v0, h0, l0); split2(v1, h1, l1);
      s.xsbh[r][p] = pack_bf16x2(h0, h1);
      s.xsbl[r][p] = pack_bf16x2(l0, l1);
    }
    __syncthreads();
    if (t > 0) { mbar_wait(mb, ph); ph ^= 1; }

    float acc[4][4][4];
    #pragma unroll
    for (int a = 0; a < 4; ++a)
      #pragma unroll
      for (int b = 0; b < 4; ++b)
        #pragma unroll
        for (int c = 0; c < 4; ++c) acc[a][b][c] = 0.f;

    u32 ah[4], al[4];

    if (t > 0) {
      #pragma unroll 4
      for (int kt = 0; kt < 16; ++kt) {
        int cb = kt * 8 + cA;
        ah[0] = s.hsbh[rA][cb];     ah[1] = s.hsbh[rA + 8][cb];
        ah[2] = s.hsbh[rA][cb + 4]; ah[3] = s.hsbh[rA + 8][cb + 4];
        al[0] = s.hsbl[rA][cb];     al[1] = s.hsbl[rA + 8][cb];
        al[2] = s.hsbl[rA][cb + 4]; al[3] = s.hsbl[rA + 8][cb + 4];
        const uint4* __restrict__ pkt = wb + kt * 1024;
        MMA3(0, 0, 0 * 32)   MMA3(0, 1, 1 * 32)   MMA3(0, 2, 2 * 32)   MMA3(0, 3, 3 * 32)
        MMA3(1, 0, 8 * 32)   MMA3(1, 1, 9 * 32)   MMA3(1, 2, 10 * 32)  MMA3(1, 3, 11 * 32)
        MMA3(2, 0, 16 * 32)  MMA3(2, 1, 17 * 32)  MMA3(2, 2, 18 * 32)  MMA3(2, 3, 19 * 32)
      }
    }
    {
      ah[0] = s.xsbh[rA][cA];     ah[1] = s.xsbh[rA + 8][cA];
      ah[2] = s.xsbh[rA][cA + 4]; ah[3] = s.xsbh[rA + 8][cA + 4];
      al[0] = s.xsbl[rA][cA];     al[1] = s.xsbl[rA + 8][cA];
      al[2] = s.xsbl[rA][cA + 4]; al[3] = s.xsbl[rA + 8][cA + 4];
      const uint4* __restrict__ pkt = wb + 16 * 1024;
      MMA3(0, 0, 0 * 32)   MMA3(0, 1, 1 * 32)   MMA3(0, 2, 2 * 32)   MMA3(0, 3, 3 * 32)
      MMA3(1, 0, 8 * 32)   MMA3(1, 1, 9 * 32)   MMA3(1, 2, 10 * 32)  MMA3(1, 3, 11 * 32)
      MMA3(2, 0, 16 * 32)  MMA3(2, 1, 17 * 32)  MMA3(2, 2, 18 * 32)  MMA3(2, 3, 19 * 32)
      MMA3(3, 0, 24 * 32)  MMA3(3, 1, 25 * 32)  MMA3(3, 2, 26 * 32)  MMA3(3, 3, 27 * 32)
    }

    // gates + masked update + write
    #pragma unroll
    for (int q = 0; q < 4; ++q) {
      #pragma unroll
      for (int half = 0; half < 2; ++half) {
        int rl = m0 + (lane >> 2) + half * 8;
        bool act = (t < s.ls[rl]);
        int jloc = jhalf * 32 + q * 8 + 2 * (lane & 3);
        int jg = jt * 64 + jloc;
        float hold0 = 0.f, hold1 = 0.f;
        if (t > 0) {
          u32 vh = s.hsbh[rl][jg >> 1];
          u32 vl = s.hsbl[rl][jg >> 1];
          hold0 = bf16_lo_f(vh) + bf16_lo_f(vl);
          hold1 = bf16_hi_f(vh) + bf16_hi_f(vl);
        }
        float hn[2];
        #pragma unroll
        for (int e = 0; e < 2; ++e) {
          float xr = acc[0][q][half * 2 + e];
          float xz = acc[1][q][half * 2 + e];
          float xhn = acc[2][q][half * 2 + e];
          float xin = acc[3][q][half * 2 + e];
          float hold = e ? hold1 : hold0;
          if (act) {
            float r = __fdividef(1.f, 1.f + __expf(-xr));
            float z = __fdividef(1.f, 1.f + __expf(-xz));
            float n = tanhf(fmaf(r, xhn, xin));
            hn[e] = fmaf(z, hold - n, n);
          } else {
            hn[e] = hold;
          }
        }
        float h0, l0, h1, l1;
        split2(hn[0], h0, l0); split2(hn[1], h1, l1);
        int grow = bt * TB + rl;
        g_hbh[po][g][grow][jg >> 1] = pack_bf16x2(h0, h1);
        g_hbl[po][g][grow][jg >> 1] = pack_bf16x2(l0, l1);
      }
    }

    // group barrier (4 CTAs sharing (bt,g)); skip after the final step
    if (t + 1 < tmax) {
      __threadfence();
      __syncthreads();
      if (tid == 0) {
        unsigned target = 4u * (unsigned)(t + 1);
        atomicAdd(&g_sync[gid], 1u);
        while (*(volatile unsigned*)&g_sync[gid] < target) __nanosleep(64);
      }
      __syncthreads();
    }
  }
}

// ---------------- concat -> xin bf16 pairs [NB][136] ----------------
__global__ void k_concat2(const float* __restrict__ state,
                          const float* __restrict__ action, int br) {
  int b = blockIdx.x;
  int p = g_invpos[b];
  int fp = g_finparp[p];
  for (int c = threadIdx.x; c < 136; c += 64) {
    float v0, v1;
    if (c < 7) {
      v0 = state[(size_t)b * NT * ND + 2 * c];
      v1 = state[(size_t)b * NT * ND + 2 * c + 1];
    } else if (c == 7) {
      v0 = state[(size_t)b * NT * ND + 14];
      v1 = action[b];
    } else {
      u32 vh = g_hbh[fp][br][p][c - 8];
      u32 vl = g_hbl[fp][br][p][c - 8];
      v0 = bf16_lo_f(vh) + bf16_lo_f(vl);
      v1 = bf16_hi_f(vh) + bf16_hi_f(vl);
    }
    float h0, l0, h1, l1;
    split2(v0, h0, l0); split2(v1, h1, l1);
    g_xh[b][c] = pack_bf16x2(h0, h1);
    g_xl[b][c] = pack_bf16x2(l0, l1);
  }
}

// ---------------- tensor-core MLP layer ----------------
__global__ void __launch_bounds__(128)
k_tmma(const u32* __restrict__ Ah, const u32* __restrict__ Al,
       const uint4* __restrict__ Wfrag, const float* __restrict__ bias,
       u32* __restrict__ Oh, u32* __restrict__ Ol,
       int KT, int NTGtot, int relu)
{
  const int w = threadIdx.x >> 5, lane = threadIdx.x & 31;
  const int m0 = blockIdx.x * 64 + w * 16;
  const int ntg0 = blockIdx.y * 8;
  const int K2 = KT * 8;
  const int rA = m0 + (lane >> 2);
  const int cA = lane & 3;
  const int outK2 = NTGtot * 4;

  const u32* __restrict__ pAh = Ah + (size_t)rA * K2 + cA;
  const u32* __restrict__ pAl = Al + (size_t)rA * K2 + cA;
  const uint4* __restrict__ wb = Wfrag + (size_t)ntg0 * 32 + lane;
  const size_t rstep = (size_t)8 * K2;

  float acc[8][4];
  #pragma unroll
  for (int q = 0; q < 8; ++q)
    #pragma unroll
    for (int c = 0; c < 4; ++c) acc[q][c] = 0.f;

  for (int kt = 0; kt < KT; ++kt) {
    u32 ah[4], al[4];
    int o = kt * 8;
    ah[0] = pAh[o];         ah[1] = pAh[o + rstep];
    ah[2] = pAh[o + 4];     ah[3] = pAh[o + 4 + rstep];
    al[0] = pAl[o];         al[1] = pAl[o + rstep];
    al[2] = pAl[o + 4];     al[3] = pAl[o + 4 + rstep];
    const uint4* __restrict__ pkt = wb + (size_t)kt * NTGtot * 32;
    #pragma unroll
    for (int q = 0; q < 8; ++q) {
      uint4 v = pkt[q * 32];
      mma_bf16(acc[q], ah, v.x, v.y);
      mma_bf16(acc[q], al, v.x, v.y);
      mma_bf16(acc[q], ah, v.z, v.w);
    }
  }

  #pragma unroll
  for (int q = 0; q < 8; ++q) {
    int n0 = (ntg0 + q) * 8 + 2 * (lane & 3);
    float b0 = bias[n0], b1 = bias[n0 + 1];
    float c0 = acc[q][0] + b0, c1 = acc[q][1] + b1;
    float c2 = acc[q][2] + b0, c3 = acc[q][3] + b1;
    if (relu) {
      c0 = fmaxf(c0, 0.f); c1 = fmaxf(c1, 0.f);
      c2 = fmaxf(c2, 0.f); c3 = fmaxf(c3, 0.f);
    }
    float h0, l0, h1, l1;
    split2(c0, h0, l0); split2(c1, h1, l1);
    size_t o0 = (size_t)rA * outK2 + (n0 >> 1);
    Oh[o0] = pack_bf16x2(h0, h1);
    Ol[o0] = pack_bf16x2(l0, l1);
    split2(c2, h0, l0); split2(c3, h1, l1);
    size_t o1 = (size_t)(rA + 8) * outK2 + (n0 >> 1);
    Oh[o1] = pack_bf16x2(h0, h1);
    Ol[o1] = pack_bf16x2(l0, l1);
  }
}

// ---------------- q head ----------------
__global__ void k_q2(const u32* __restrict__ Ah, const u32* __restrict__ Al,
                     const float* __restrict__ qw, const float* __restrict__ qb,
                     float* __restrict__ out)
{
  __shared__ float red[64];
  int b = blockIdx.x;
  float sum = 0.f;
  for (int p = threadIdx.x; p < 128; p += 64) {
    u32 vh = Ah[(size_t)b * 128 + p];
    u32 vl = Al[(size_t)b * 128 + p];
    float v0 = bf16_lo_f(vh) + bf16_lo_f(vl);
    float v1 = bf16_hi_f(vh) + bf16_hi_f(vl);
    sum += v0 * qw[2 * p] + v1 * qw[2 * p + 1];
  }
  red[threadIdx.x] = sum;
  __syncthreads();
  if (threadIdx.x < 32) {
    float v = red[threadIdx.x] + red[threadIdx.x + 32];
    #pragma unroll
    for (int o = 16; o; o >>= 1) v += __shfl_down_sync(0xffffffffu, v, o);
    if (threadIdx.x == 0) out[b] = v + qb[0];
  }
}

// ---------------- launch ----------------
extern "C" void kernel_launch(void* const* d_in, const int* in_sizes, int n_in,
                              void* d_out, int out_size)
{
  const float* state   = (const float*)d_in[0];
  const float* action  = (const float*)d_in[1];
  const int*   lengths = (const int*)d_in[2];

  const float* gWih[2]; const float* gWhh[2];
  const float* gbih[2]; const float* gbhh[2];
  const float* fcw[2][5]; const float* fcb[2][5];
  for (int br = 0; br < 2; ++br) {
    int base = 3 + br * 14;
    gWih[br] = (const float*)d_in[base + 0];
    gWhh[br] = (const float*)d_in[base + 1];
    gbih[br] = (const float*)d_in[base + 2];
    gbhh[br] = (const float*)d_in[base + 3];
    for (int l = 0; l < 5; ++l) {
      fcw[br][l] = (const float*)d_in[base + 4 + 2 * l];
      fcb[br][l] = (const float*)d_in[base + 5 + 2 * l];
    }
  }

  u32 *p_xh, *p_xl, *p_m0h, *p_m0l, *p_m1h, *p_m1l;
  uint4* p_mlpB;
  cudaGetSymbolAddress((void**)&p_xh, g_xh);
  cudaGetSymbolAddress((void**)&p_xl, g_xl);
  cudaGetSymbolAddress((void**)&p_m0h, g_m0h);
  cudaGetSymbolAddress((void**)&p_m0l, g_m0l);
  cudaGetSymbolAddress((void**)&p_m1h, g_m1h);
  cudaGetSymbolAddress((void**)&p_m1l, g_m1l);
  cudaGetSymbolAddress((void**)&p_mlpB, g_mlpB);

  cudaFuncSetAttribute(k_gru_persist, cudaFuncAttributeMaxDynamicSharedMemorySize,
                       (int)sizeof(GruS));

  // prep
  k_sort<<<1, 1024>>>(lengths);
  k_prep<<<(2 * 4 * NKT * 32 * 32 + 255) / 256, 256>>>(gWhh[0], gWhh[1],
                                                       gWih[0], gbih[0], gbhh[0],
                                                       gWih[1], gbih[1], gbhh[1]);
  const int loff[4] = {OFF_L1, OFF_L2, OFF_L3, OFF_L4};
  const int lKT[4]  = {17, 64, 64, 32};
  const int lNTG[4] = {128, 128, 64, 32};
  for (int br = 0; br < 2; ++br) {
    for (int l = 0; l < 4; ++l) {
      int cnt = lKT[l] * lNTG[l] * 32;
      k_packw<<<(cnt + 255) / 256, 256>>>(fcw[br][l], lKT[l], lNTG[l], lKT[l] * 16,
                                          p_mlpB + (size_t)br * MLPB_BR + loff[l]);
    }
  }

  // persistent recurrent kernel: 256 CTAs (one wave), per-(bt,g) group barriers
  k_gru_persist<<<256, THR, sizeof(GruS)>>>(state);

  // MLP branches (tensor cores)
  float* outp = (float*)d_out;
  for (int br = 0; br < 2; ++br) {
    const uint4* wbB = p_mlpB + (size_t)br * MLPB_BR;
    k_concat2<<<NB, 64>>>(state, action, br);
    k_tmma<<<dim3(32, 16), 128>>>(p_xh, p_xl, wbB + OFF_L1, fcb[br][0],
                                  p_m0h, p_m0l, 17, 128, 1);
    k_tmma<<<dim3(32, 16), 128>>>(p_m0h, p_m0l, wbB + OFF_L2, fcb[br][1],
                                  p_m1h, p_m1l, 64, 128, 1);
    k_tmma<<<dim3(32, 8), 128>>>(p_m1h, p_m1l, wbB + OFF_L3, fcb[br][2],
                                 p_m0h, p_m0l, 64, 64, 1);
    k_tmma<<<dim3(32, 4), 128>>>(p_m0h, p_m0l, wbB + OFF_L4, fcb[br][3],
                                 p_m1h, p_m1l, 32, 32, 1);
    k_q2<<<NB, 64>>>(p_m1h, p_m1l, fcw[br][4], fcb[br][4], outp + (size_t)br * NB);
  }
}

// round 16
// speedup vs baseline: 3.7498x; 1.0388x over previous
#include <cuda_runtime.h>
#include <math.h>

#define NB 2048
#define NT 64
#define ND 15
#define NH 256
#define TB 64
#define NBT 32       // NB / TB
#define THR 256
#define NKT 17       // GRU k-tiles: 16 h-tiles + 1 (x|1) tile  (K = 272)

// MLP packed-fragment layout (uint4 units)
#define MLPB_BR 495616
#define OFF_L1 0
#define OFF_L2 69632
#define OFF_L3 331776
#define OFF_L4 462848

typedef unsigned long long u64;
typedef unsigned u32;

// ---------------- bf16 helpers ----------------
__device__ __forceinline__ u32 pack_bf16x2(float e, float o) {   // low half = e
  u32 r; asm("cvt.rn.bf16x2.f32 %0, %1, %2;" : "=r"(r) : "f"(o), "f"(e)); return r;
}
__device__ __forceinline__ float bf16_lo_f(u32 v) { return __uint_as_float(v << 16); }
__device__ __forceinline__ float bf16_hi_f(u32 v) { return __uint_as_float(v & 0xffff0000u); }
__device__ __forceinline__ void split2(float v, float& hi, float& lo) {
  u32 h; asm("cvt.rn.bf16x2.f32 %0, %1, %2;" : "=r"(h) : "f"(0.f), "f"(v));
  hi = __uint_as_float(h << 16);
  lo = v - hi;
}

// ---------------- mma m16n8k16 bf16 ----------------
__device__ __forceinline__ void mma_bf16(float* d, const u32* a, u32 b0, u32 b1) {
  asm("mma.sync.aligned.m16n8k16.row.col.f32.bf16.bf16.f32 "
      "{%0,%1,%2,%3}, {%4,%5,%6,%7}, {%8,%9}, {%0,%1,%2,%3};"
      : "+f"(d[0]), "+f"(d[1]), "+f"(d[2]), "+f"(d[3])
      : "r"(a[0]), "r"(a[1]), "r"(a[2]), "r"(a[3]), "r"(b0), "r"(b1));
}

// ---------------- mbarrier / bulk-copy ----------------
__device__ __forceinline__ unsigned smem_u32p(const void* p) {
  unsigned a;
  asm("{ .reg .u64 t; cvta.to.shared.u64 t, %1; cvt.u32.u64 %0, t; }" : "=r"(a) : "l"(p));
  return a;
}
__device__ __forceinline__ void mbar_init(unsigned mbar, unsigned cnt) {
  asm volatile("mbarrier.init.shared.b64 [%0], %1;" :: "r"(mbar), "r"(cnt) : "memory");
}
__device__ __forceinline__ void mbar_expect(unsigned mbar, unsigned bytes) {
  asm volatile("mbarrier.arrive.expect_tx.shared.b64 _, [%0], %1;"
               :: "r"(mbar), "r"(bytes) : "memory");
}
__device__ __forceinline__ void bulk_g2s(unsigned dst, const void* src,
                                         unsigned bytes, unsigned mbar) {
  asm volatile(
      "cp.async.bulk.shared::cta.global.mbarrier::complete_tx::bytes [%0], [%1], %2, [%3];"
      :: "r"(dst), "l"(src), "r"(bytes), "r"(mbar) : "memory");
}
__device__ __forceinline__ void mbar_wait(unsigned mbar, unsigned parity) {
  asm volatile(
      "{\n\t.reg .pred P;\n\t"
      "W%=:\n\t"
      "mbarrier.try_wait.parity.acquire.cta.shared::cta.b64 P, [%0], %1, 0x989680;\n\t"
      "@P bra.uni D%=;\n\t"
      "bra.uni W%=;\n\t"
      "D%=:\n\t}"
      :: "r"(mbar), "r"(parity) : "memory");
}

// ---------------- device scratch ----------------
__device__ u32   g_hbh[2][2][NB][132];   // [parity][gru][sorted row][k-pair] bf16x2 hi
__device__ u32   g_hbl[2][2][NB][132];
__device__ uint4 g_wB4[2 * 4 * NKT * 32 * 32];   // GRU B fragments
__device__ uint4 g_mlpB[2 * MLPB_BR];            // MLP W fragments
__device__ u32   g_xh[2][NB][136];       // per-branch xin pairs
__device__ u32   g_xl[2][NB][136];
__device__ u32   g_m0h[2][NB][512];      // per-branch activation ping-pong
__device__ u32   g_m0l[2][NB][512];
__device__ u32   g_m1h[2][NB][512];
__device__ u32   g_m1l[2][NB][512];
__device__ unsigned g_sync[64];          // per-(bt,g) monotonic step counters
__device__ int   g_perm[NB];
__device__ int   g_off[66];
__device__ int   g_hist[66];
__device__ int   g_tilemax[NBT];
__device__ int   g_invpos[NB];
__device__ int   g_finparp[NB];
__device__ int   g_lsort[NB];

// ---------------- fused length sort ----------------
__global__ void k_sort(const int* __restrict__ lengths) {
  int tid = threadIdx.x;
  if (tid < 66) g_hist[tid] = 0;
  __syncthreads();
  for (int b = tid; b < NB; b += 1024) atomicAdd(&g_hist[lengths[b]], 1);
  __syncthreads();
  if (tid == 0) {
    int s = 0;
    for (int l = 0; l < 66; ++l) { g_off[l] = s; s += g_hist[l]; }
  }
  __syncthreads();
  for (int b = tid; b < NB; b += 1024) {
    int p = atomicAdd(&g_off[lengths[b]], 1);
    g_perm[p] = b;
  }
  __syncthreads();
  if (tid < NBT) g_tilemax[tid] = lengths[g_perm[tid * TB + TB - 1]];
  __syncthreads();
  for (int p = tid; p < NB; p += 1024) {
    int b = g_perm[p];
    g_invpos[b] = p;
    g_finparp[p] = g_tilemax[p >> 6] & 1;
    g_lsort[p] = lengths[b];
  }
}

// barrier counter reset (launch #5 so gru is #6 for ncu)
__global__ void k_zsync() { if (threadIdx.x < 64) g_sync[threadIdx.x] = 0u; }

// ---------------- GRU B-value oracle (fp32) ----------------
__device__ float bval(const float* Whh, const float* Wih,
                      const float* bih, const float* bhh,
                      int jt, int n, int k) {
  int gate = n >> 6;              // 0:r 1:z 2:hn 3:in
  int j = jt * 64 + (n & 63);
  if (k < 256) {
    if (gate == 0) return Whh[(size_t)j * 256 + k];
    if (gate == 1) return Whh[(size_t)(256 + j) * 256 + k];
    if (gate == 2) return Whh[(size_t)(512 + j) * 256 + k];
    return 0.f;
  } else if (k < 271) {
    int i = k - 256;
    if (gate == 0) return Wih[(size_t)j * ND + i];
    if (gate == 1) return Wih[(size_t)(256 + j) * ND + i];
    if (gate == 2) return 0.f;
    return Wih[(size_t)(512 + j) * ND + i];
  } else {
    if (gate == 0) return bih[j] + bhh[j];
    if (gate == 1) return bih[256 + j] + bhh[256 + j];
    if (gate == 2) return bhh[512 + j];
    return bih[512 + j];
  }
}

// ---------------- GRU prep: pack B fragments ----------------
__global__ void k_prep(const float* __restrict__ Whh0, const float* __restrict__ Whh1,
                       const float* __restrict__ Wih0, const float* __restrict__ bih0,
                       const float* __restrict__ bhh0,
                       const float* __restrict__ Wih1, const float* __restrict__ bih1,
                       const float* __restrict__ bhh1) {
  int i = blockIdx.x * blockDim.x + threadIdx.x;
  if (i >= 2 * 4 * NKT * 32 * 32) return;
  int lane = i & 31;
  int nt   = (i >> 5) & 31;
  int kt   = (i >> 10) % NKT;
  int jt   = (i / (1024 * NKT)) & 3;
  int g    = i / (1024 * NKT * 4);
  const float* Whh = g ? Whh1 : Whh0;
  const float* Wih = g ? Wih1 : Wih0;
  const float* bih = g ? bih1 : bih0;
  const float* bhh = g ? bhh1 : bhh0;
  int n = nt * 8 + (lane >> 2);
  u32 out[4];
  #pragma unroll
  for (int reg = 0; reg < 2; ++reg) {
    int k0 = kt * 16 + 2 * (lane & 3) + reg * 8;
    float v0 = bval(Whh, Wih, bih, bhh, jt, n, k0);
    float v1 = bval(Whh, Wih, bih, bhh, jt, n, k0 + 1);
    float h0, l0, h1, l1;
    split2(v0, h0, l0); split2(v1, h1, l1);
    out[reg]     = pack_bf16x2(h0, h1);
    out[2 + reg] = pack_bf16x2(l0, l1);
  }
  g_wB4[i] = make_uint4(out[0], out[1], out[2], out[3]);
}

// ---------------- MLP prep: all 4 layers of one branch, range-decoded ----------------
__global__ void k_packw_all(const float* __restrict__ W1, const float* __restrict__ W2,
                            const float* __restrict__ W3, const float* __restrict__ W4,
                            uint4* __restrict__ dst) {
  int i = blockIdx.x * blockDim.x + threadIdx.x;
  if (i >= MLPB_BR) return;
  const float* W; int li, NTG, K;
  if (i < OFF_L2)      { W = W1; li = i;          NTG = 128; K = 272; }
  else if (i < OFF_L3) { W = W2; li = i - OFF_L2; NTG = 128; K = 1024; }
  else if (i < OFF_L4) { W = W3; li = i - OFF_L3; NTG = 64;  K = 1024; }
  else                 { W = W4; li = i - OFF_L4; NTG = 32;  K = 512; }
  int lane = li & 31;
  int ntg  = (li >> 5) % NTG;
  int kt   = (li >> 5) / NTG;
  int n = ntg * 8 + (lane >> 2);
  u32 out[4];
  #pragma unroll
  for (int reg = 0; reg < 2; ++reg) {
    int k0 = kt * 16 + 2 * (lane & 3) + reg * 8;
    float v0 = W[(size_t)n * K + k0];
    float v1 = W[(size_t)n * K + k0 + 1];
    float h0, l0, h1, l1;
    split2(v0, h0, l0); split2(v1, h1, l1);
    out[reg]     = pack_bf16x2(h0, h1);
    out[2 + reg] = pack_bf16x2(l0, l1);
  }
  dst[i] = make_uint4(out[0], out[1], out[2], out[3]);
}

// ---------------- persistent GRU kernel (unchanged math) ----------------
struct GruS {
  u32 hsbh[TB][132];
  u32 hsbl[TB][132];
  u32 xsbh[TB][9];
  u32 xsbl[TB][9];
  int ls[TB];
  u64 mb[2];
};

#define MMA3(g4, q, off)                                            \
  {                                                                 \
    uint4 v = pkt[(off)];                                           \
    mma_bf16(acc[g4][q], ah, v.x, v.y);                             \
    mma_bf16(acc[g4][q], al, v.x, v.y);                             \
    mma_bf16(acc[g4][q], ah, v.z, v.w);                             \
  }

__global__ void __launch_bounds__(THR, 2)
k_gru_persist(const float* __restrict__ state)
{
  extern __shared__ char sraw[];
  GruS& s = *reinterpret_cast<GruS*>(sraw);
  const int jt  = blockIdx.x & 3;
  const int gid = blockIdx.x >> 2;
  const int bt  = gid >> 1;
  const int g   = gid & 1;
  const int tid = threadIdx.x;
  const int tmax = g_tilemax[bt];
  const int gjt = g * 4 + jt;

  const unsigned mb = smem_u32p(&s.mb[0]);
  if (tid == 0) mbar_init(mb, 1);
  if (tid < TB) s.ls[tid] = g_lsort[bt * TB + tid];
  __syncthreads();

  const int w = tid >> 5, lane = tid & 31;
  const int m0 = (w & 3) * 16, jhalf = w >> 2;
  const int rA = m0 + (lane >> 2);
  const int cA = lane & 3;
  const uint4* __restrict__ wb =
      g_wB4 + (((size_t)gjt * NKT) * 32 + jhalf * 4) * 32 + lane;

  int ph = 0;
  for (int t = 0; t < tmax; ++t) {
    const int pi = t & 1, po = pi ^ 1;

    if (tid == 0 && t > 0) {
      mbar_expect(mb, 2u * 33792u);
      bulk_g2s(smem_u32p(&s.hsbh[0][0]), &g_hbh[pi][g][bt * TB][0], 33792u, mb);
      bulk_g2s(smem_u32p(&s.hsbl[0][0]), &g_hbl[pi][g][bt * TB][0], 33792u, mb);
    }

    for (int i = tid; i < TB * 8; i += THR) {
      int r = i >> 3, p = i & 7;
      const float* xp = state + (size_t)g_perm[bt * TB + r] * (NT * ND) + (size_t)t * ND;
      float v0 = xp[2 * p];
      float v1 = (p == 7) ? 1.0f : xp[2 * p + 1];
      float h0, l0, h1, l1;
      split2(v0, h0, l0); split2(v1, h1, l1);
      s.xsbh[r][p] = pack_bf16x2(h0, h1);
      s.xsbl[r][p] = pack_bf16x2(l0, l1);
    }
    __syncthreads();
    if (t > 0) { mbar_wait(mb, ph); ph ^= 1; }

    float acc[4][4][4];
    #pragma unroll
    for (int a = 0; a < 4; ++a)
      #pragma unroll
      for (int b = 0; b < 4; ++b)
        #pragma unroll
        for (int c = 0; c < 4; ++c) acc[a][b][c] = 0.f;

    u32 ah[4], al[4];

    if (t > 0) {
      #pragma unroll 4
      for (int kt = 0; kt < 16; ++kt) {
        int cb = kt * 8 + cA;
        ah[0] = s.hsbh[rA][cb];     ah[1] = s.hsbh[rA + 8][cb];
        ah[2] = s.hsbh[rA][cb + 4]; ah[3] = s.hsbh[rA + 8][cb + 4];
        al[0] = s.hsbl[rA][cb];     al[1] = s.hsbl[rA + 8][cb];
        al[2] = s.hsbl[rA][cb + 4]; al[3] = s.hsbl[rA + 8][cb + 4];
        const uint4* __restrict__ pkt = wb + kt * 1024;
        MMA3(0, 0, 0 * 32)   MMA3(0, 1, 1 * 32)   MMA3(0, 2, 2 * 32)   MMA3(0, 3, 3 * 32)
        MMA3(1, 0, 8 * 32)   MMA3(1, 1, 9 * 32)   MMA3(1, 2, 10 * 32)  MMA3(1, 3, 11 * 32)
        MMA3(2, 0, 16 * 32)  MMA3(2, 1, 17 * 32)  MMA3(2, 2, 18 * 32)  MMA3(2, 3, 19 * 32)
      }
    }
    {
      ah[0] = s.xsbh[rA][cA];     ah[1] = s.xsbh[rA + 8][cA];
      ah[2] = s.xsbh[rA][cA + 4]; ah[3] = s.xsbh[rA + 8][cA + 4];
      al[0] = s.xsbl[rA][cA];     al[1] = s.xsbl[rA + 8][cA];
      al[2] = s.xsbl[rA][cA + 4]; al[3] = s.xsbl[rA + 8][cA + 4];
      const uint4* __restrict__ pkt = wb + 16 * 1024;
      MMA3(0, 0, 0 * 32)   MMA3(0, 1, 1 * 32)   MMA3(0, 2, 2 * 32)   MMA3(0, 3, 3 * 32)
      MMA3(1, 0, 8 * 32)   MMA3(1, 1, 9 * 32)   MMA3(1, 2, 10 * 32)  MMA3(1, 3, 11 * 32)
      MMA3(2, 0, 16 * 32)  MMA3(2, 1, 17 * 32)  MMA3(2, 2, 18 * 32)  MMA3(2, 3, 19 * 32)
      MMA3(3, 0, 24 * 32)  MMA3(3, 1, 25 * 32)  MMA3(3, 2, 26 * 32)  MMA3(3, 3, 27 * 32)
    }

    #pragma unroll
    for (int q = 0; q < 4; ++q) {
      #pragma unroll
      for (int half = 0; half < 2; ++half) {
        int rl = m0 + (lane >> 2) + half * 8;
        bool act = (t < s.ls[rl]);
        int jloc = jhalf * 32 + q * 8 + 2 * (lane & 3);
        int jg = jt * 64 + jloc;
        float hold0 = 0.f, hold1 = 0.f;
        if (t > 0) {
          u32 vh = s.hsbh[rl][jg >> 1];
          u32 vl = s.hsbl[rl][jg >> 1];
          hold0 = bf16_lo_f(vh) + bf16_lo_f(vl);
          hold1 = bf16_hi_f(vh) + bf16_hi_f(vl);
        }
        float hn[2];
        #pragma unroll
        for (int e = 0; e < 2; ++e) {
          float xr = acc[0][q][half * 2 + e];
          float xz = acc[1][q][half * 2 + e];
          float xhn = acc[2][q][half * 2 + e];
          float xin = acc[3][q][half * 2 + e];
          float hold = e ? hold1 : hold0;
          if (act) {
            float r = __fdividef(1.f, 1.f + __expf(-xr));
            float z = __fdividef(1.f, 1.f + __expf(-xz));
            float n = tanhf(fmaf(r, xhn, xin));
            hn[e] = fmaf(z, hold - n, n);
          } else {
            hn[e] = hold;
          }
        }
        float h0, l0, h1, l1;
        split2(hn[0], h0, l0); split2(hn[1], h1, l1);
        int grow = bt * TB + rl;
        g_hbh[po][g][grow][jg >> 1] = pack_bf16x2(h0, h1);
        g_hbl[po][g][grow][jg >> 1] = pack_bf16x2(l0, l1);
      }
    }

    if (t + 1 < tmax) {
      __threadfence();
      __syncthreads();
      if (tid == 0) {
        unsigned target = 4u * (unsigned)(t + 1);
        atomicAdd(&g_sync[gid], 1u);
        while (*(volatile unsigned*)&g_sync[gid] < target) __nanosleep(64);
      }
      __syncthreads();
    }
  }
}

// ---------------- concat -> xin bf16 pairs, both branches ----------------
__global__ void k_concat2(const float* __restrict__ state,
                          const float* __restrict__ action) {
  int b = blockIdx.x, br = blockIdx.y;
  int p = g_invpos[b];
  int fp = g_finparp[p];
  for (int c = threadIdx.x; c < 136; c += 64) {
    float v0, v1;
    if (c < 7) {
      v0 = state[(size_t)b * NT * ND + 2 * c];
      v1 = state[(size_t)b * NT * ND + 2 * c + 1];
    } else if (c == 7) {
      v0 = state[(size_t)b * NT * ND + 14];
      v1 = action[b];
    } else {
      u32 vh = g_hbh[fp][br][p][c - 8];
      u32 vl = g_hbl[fp][br][p][c - 8];
      v0 = bf16_lo_f(vh) + bf16_lo_f(vl);
      v1 = bf16_hi_f(vh) + bf16_hi_f(vl);
    }
    float h0, l0, h1, l1;
    split2(v0, h0, l0); split2(v1, h1, l1);
    g_xh[br][b][c] = pack_bf16x2(h0, h1);
    g_xl[br][b][c] = pack_bf16x2(l0, l1);
  }
}

// ---------------- tensor-core MLP layer, both branches via blockIdx.z ----------------
__global__ void __launch_bounds__(128)
k_tmma(const u32* __restrict__ Ah, const u32* __restrict__ Al, int abrs,
       const uint4* __restrict__ Wfrag,
       const float* __restrict__ bias0, const float* __restrict__ bias1,
       u32* __restrict__ Oh, u32* __restrict__ Ol, int obrs,
       int KT, int NTGtot, int relu)
{
  const int br = blockIdx.z;
  Ah += (size_t)br * abrs;  Al += (size_t)br * abrs;
  Oh += (size_t)br * obrs;  Ol += (size_t)br * obrs;
  const uint4* Wb = Wfrag + (size_t)br * MLPB_BR;
  const float* bias = br ? bias1 : bias0;

  const int w = threadIdx.x >> 5, lane = threadIdx.x & 31;
  const int m0 = blockIdx.x * 64 + w * 16;
  const int ntg0 = blockIdx.y * 8;
  const int K2 = KT * 8;
  const int rA = m0 + (lane >> 2);
  const int cA = lane & 3;
  const int outK2 = NTGtot * 4;

  const u32* __restrict__ pAh = Ah + (size_t)rA * K2 + cA;
  const u32* __restrict__ pAl = Al + (size_t)rA * K2 + cA;
  const uint4* __restrict__ wbp = Wb + (size_t)ntg0 * 32 + lane;
  const size_t rstep = (size_t)8 * K2;

  float acc[8][4];
  #pragma unroll
  for (int q = 0; q < 8; ++q)
    #pragma unroll
    for (int c = 0; c < 4; ++c) acc[q][c] = 0.f;

  for (int kt = 0; kt < KT; ++kt) {
    u32 ah[4], al[4];
    int o = kt * 8;
    ah[0] = pAh[o];         ah[1] = pAh[o + rstep];
    ah[2] = pAh[o + 4];     ah[3] = pAh[o + 4 + rstep];
    al[0] = pAl[o];         al[1] = pAl[o + rstep];
    al[2] = pAl[o + 4];     al[3] = pAl[o + 4 + rstep];
    const uint4* __restrict__ pkt = wbp + (size_t)kt * NTGtot * 32;
    #pragma unroll
    for (int q = 0; q < 8; ++q) {
      uint4 v = pkt[q * 32];
      mma_bf16(acc[q], ah, v.x, v.y);
      mma_bf16(acc[q], al, v.x, v.y);
      mma_bf16(acc[q], ah, v.z, v.w);
    }
  }

  #pragma unroll
  for (int q = 0; q < 8; ++q) {
    int n0 = (ntg0 + q) * 8 + 2 * (lane & 3);
    float b0 = bias[n0], b1 = bias[n0 + 1];
    float c0 = acc[q][0] + b0, c1 = acc[q][1] + b1;
    float c2 = acc[q][2] + b0, c3 = acc[q][3] + b1;
    if (relu) {
      c0 = fmaxf(c0, 0.f); c1 = fmaxf(c1, 0.f);
      c2 = fmaxf(c2, 0.f); c3 = fmaxf(c3, 0.f);
    }
    float h0, l0, h1, l1;
    split2(c0, h0, l0); split2(c1, h1, l1);
    size_t o0 = (size_t)rA * outK2 + (n0 >> 1);
    Oh[o0] = pack_bf16x2(h0, h1);
    Ol[o0] = pack_bf16x2(l0, l1);
    split2(c2, h0, l0); split2(c3, h1, l1);
    size_t o1 = (size_t)(rA + 8) * outK2 + (n0 >> 1);
    Oh[o1] = pack_bf16x2(h0, h1);
    Ol[o1] = pack_bf16x2(l0, l1);
  }
}

// ---------------- q head, both branches (branch stride = NB*512 u32) ----------------
__global__ void k_q2(const u32* __restrict__ Ah, const u32* __restrict__ Al,
                     const float* __restrict__ qw0, const float* __restrict__ qb0,
                     const float* __restrict__ qw1, const float* __restrict__ qb1,
                     float* __restrict__ out)
{
  __shared__ float red[64];
  int b = blockIdx.x, br = blockIdx.y;
  const u32* pAh = Ah + (size_t)br * NB * 512;   // FIX: buffer branch stride is NB*512
  const u32* pAl = Al + (size_t)br * NB * 512;
  const float* qw = br ? qw1 : qw0;
  const float* qb = br ? qb1 : qb0;
  float sum = 0.f;
  for (int p = threadIdx.x; p < 128; p += 64) {
    u32 vh = pAh[(size_t)b * 128 + p];
    u32 vl = pAl[(size_t)b * 128 + p];
    float v0 = bf16_lo_f(vh) + bf16_lo_f(vl);
    float v1 = bf16_hi_f(vh) + bf16_hi_f(vl);
    sum += v0 * qw[2 * p] + v1 * qw[2 * p + 1];
  }
  red[threadIdx.x] = sum;
  __syncthreads();
  if (threadIdx.x < 32) {
    float v = red[threadIdx.x] + red[threadIdx.x + 32];
    #pragma unroll
    for (int o = 16; o; o >>= 1) v += __shfl_down_sync(0xffffffffu, v, o);
    if (threadIdx.x == 0) out[(size_t)br * NB + b] = v + qb[0];
  }
}

// ---------------- launch ----------------
extern "C" void kernel_launch(void* const* d_in, const int* in_sizes, int n_in,
                              void* d_out, int out_size)
{
  const float* state   = (const float*)d_in[0];
  const float* action  = (const float*)d_in[1];
  const int*   lengths = (const int*)d_in[2];

  const float* gWih[2]; const float* gWhh[2];
  const float* gbih[2]; const float* gbhh[2];
  const float* fcw[2][5]; const float* fcb[2][5];
  for (int br = 0; br < 2; ++br) {
    int base = 3 + br * 14;
    gWih[br] = (const float*)d_in[base + 0];
    gWhh[br] = (const float*)d_in[base + 1];
    gbih[br] = (const float*)d_in[base + 2];
    gbhh[br] = (const float*)d_in[base + 3];
    for (int l = 0; l < 5; ++l) {
      fcw[br][l] = (const float*)d_in[base + 4 + 2 * l];
      fcb[br][l] = (const float*)d_in[base + 5 + 2 * l];
    }
  }

  u32 *p_xh, *p_xl, *p_m0h, *p_m0l, *p_m1h, *p_m1l;
  uint4* p_mlpB;
  cudaGetSymbolAddress((void**)&p_xh, g_xh);
  cudaGetSymbolAddress((void**)&p_xl, g_xl);
  cudaGetSymbolAddress((void**)&p_m0h, g_m0h);
  cudaGetSymbolAddress((void**)&p_m0l, g_m0l);
  cudaGetSymbolAddress((void**)&p_m1h, g_m1h);
  cudaGetSymbolAddress((void**)&p_m1l, g_m1l);
  cudaGetSymbolAddress((void**)&p_mlpB, g_mlpB);

  cudaFuncSetAttribute(k_gru_persist, cudaFuncAttributeMaxDynamicSharedMemorySize,
                       (int)sizeof(GruS));

  // prep: launches 1-5 (gru persistent = launch 6 for ncu -s 5 -c 1)
  k_sort<<<1, 1024>>>(lengths);
  k_prep<<<(2 * 4 * NKT * 32 * 32 + 255) / 256, 256>>>(gWhh[0], gWhh[1],
                                                       gWih[0], gbih[0], gbhh[0],
                                                       gWih[1], gbih[1], gbhh[1]);
  k_packw_all<<<(MLPB_BR + 255) / 256, 256>>>(fcw[0][0], fcw[0][1], fcw[0][2], fcw[0][3],
                                              p_mlpB);
  k_packw_all<<<(MLPB_BR + 255) / 256, 256>>>(fcw[1][0], fcw[1][1], fcw[1][2], fcw[1][3],
                                              p_mlpB + MLPB_BR);
  k_zsync<<<1, 64>>>();

  // persistent recurrent kernel: 256 CTAs (one wave)
  k_gru_persist<<<256, THR, sizeof(GruS)>>>(state);

  // MLP, both branches fused via grid.z
  float* outp = (float*)d_out;
  k_concat2<<<dim3(NB, 2), 64>>>(state, action);
  k_tmma<<<dim3(32, 16, 2), 128>>>(p_xh, p_xl, NB * 136, p_mlpB + OFF_L1,
                                   fcb[0][0], fcb[1][0],
                                   p_m0h, p_m0l, NB * 512, 17, 128, 1);
  k_tmma<<<dim3(32, 16, 2), 128>>>(p_m0h, p_m0l, NB * 512, p_mlpB + OFF_L2,
                                   fcb[0][1], fcb[1][1],
                                   p_m1h, p_m1l, NB * 512, 64, 128, 1);
  k_tmma<<<dim3(32, 8, 2), 128>>>(p_m1h, p_m1l, NB * 512, p_mlpB + OFF_L3,
                                  fcb[0][2], fcb[1][2],
                                  p_m0h, p_m0l, NB * 512, 64, 64, 1);
  k_tmma<<<dim3(32, 4, 2), 128>>>(p_m0h, p_m0l, NB * 512, p_mlpB + OFF_L4,
                                  fcb[0][3], fcb[1][3],
                                  p_m1h, p_m1l, NB * 512, 32, 32, 1);
  k_q2<<<dim3(NB, 2), 64>>>(p_m1h, p_m1l, fcw[0][4], fcb[0][4], fcw[1][4], fcb[1][4],
                            outp);
}

// round 17
// speedup vs baseline: 3.7553x; 1.0015x over previous
#include <cuda_runtime.h>
#include <math.h>

#define NB 2048
#define NT 64
#define ND 15
#define NH 256
#define TB 64
#define NBT 32       // NB / TB
#define THR 256
#define NKT 17       // GRU k-tiles: 16 h-tiles + 1 (x|1) tile  (K = 272)

// MLP packed-fragment layout (uint4 units)
#define MLPB_BR 495616
#define OFF_L1 0
#define OFF_L2 69632
#define OFF_L3 331776
#define OFF_L4 462848

typedef unsigned long long u64;
typedef unsigned u32;

// ---------------- bf16 helpers ----------------
__device__ __forceinline__ u32 pack_bf16x2(float e, float o) {   // low half = e
  u32 r; asm("cvt.rn.bf16x2.f32 %0, %1, %2;" : "=r"(r) : "f"(o), "f"(e)); return r;
}
__device__ __forceinline__ float bf16_lo_f(u32 v) { return __uint_as_float(v << 16); }
__device__ __forceinline__ float bf16_hi_f(u32 v) { return __uint_as_float(v & 0xffff0000u); }
__device__ __forceinline__ void split2(float v, float& hi, float& lo) {
  u32 h; asm("cvt.rn.bf16x2.f32 %0, %1, %2;" : "=r"(h) : "f"(0.f), "f"(v));
  hi = __uint_as_float(h << 16);
  lo = v - hi;
}

// ---------------- mma m16n8k16 bf16 ----------------
__device__ __forceinline__ void mma_bf16(float* d, const u32* a, u32 b0, u32 b1) {
  asm("mma.sync.aligned.m16n8k16.row.col.f32.bf16.bf16.f32 "
      "{%0,%1,%2,%3}, {%4,%5,%6,%7}, {%8,%9}, {%0,%1,%2,%3};"
      : "+f"(d[0]), "+f"(d[1]), "+f"(d[2]), "+f"(d[3])
      : "r"(a[0]), "r"(a[1]), "r"(a[2]), "r"(a[3]), "r"(b0), "r"(b1));
}

// ---------------- mbarrier / bulk-copy ----------------
__device__ __forceinline__ unsigned smem_u32p(const void* p) {
  unsigned a;
  asm("{ .reg .u64 t; cvta.to.shared.u64 t, %1; cvt.u32.u64 %0, t; }" : "=r"(a) : "l"(p));
  return a;
}
__device__ __forceinline__ void mbar_init(unsigned mbar, unsigned cnt) {
  asm volatile("mbarrier.init.shared.b64 [%0], %1;" :: "r"(mbar), "r"(cnt) : "memory");
}
__device__ __forceinline__ void mbar_expect(unsigned mbar, unsigned bytes) {
  asm volatile("mbarrier.arrive.expect_tx.shared.b64 _, [%0], %1;"
               :: "r"(mbar), "r"(bytes) : "memory");
}
__device__ __forceinline__ void bulk_g2s(unsigned dst, const void* src,
                                         unsigned bytes, unsigned mbar) {
  asm volatile(
      "cp.async.bulk.shared::cta.global.mbarrier::complete_tx::bytes [%0], [%1], %2, [%3];"
      :: "r"(dst), "l"(src), "r"(bytes), "r"(mbar) : "memory");
}
__device__ __forceinline__ void mbar_wait(unsigned mbar, unsigned parity) {
  asm volatile(
      "{\n\t.reg .pred P;\n\t"
      "W%=:\n\t"
      "mbarrier.try_wait.parity.acquire.cta.shared::cta.b64 P, [%0], %1, 0x989680;\n\t"
      "@P bra.uni D%=;\n\t"
      "bra.uni W%=;\n\t"
      "D%=:\n\t}"
      :: "r"(mbar), "r"(parity) : "memory");
}

// ---------------- device scratch ----------------
__device__ u32   g_hbh[2][2][NB][132];   // [parity][gru][sorted row][k-pair] bf16x2 hi
__device__ u32   g_hbl[2][2][NB][132];
__device__ uint4 g_wB4[2 * 4 * NKT * 32 * 32];   // GRU B fragments
__device__ uint4 g_mlpB[2 * MLPB_BR];            // MLP W fragments
__device__ u32   g_xh[2][NB][136];       // per-branch xin pairs
__device__ u32   g_xl[2][NB][136];
__device__ u32   g_m0h[2][NB][512];      // per-branch activation ping-pong
__device__ u32   g_m0l[2][NB][512];
__device__ u32   g_m1h[2][NB][512];
__device__ u32   g_m1l[2][NB][512];
__device__ unsigned g_sync[64];          // per-(bt,g) monotonic step counters
__device__ int   g_perm[NB];
__device__ int   g_off[66];
__device__ int   g_hist[66];
__device__ int   g_tilemax[NBT];
__device__ int   g_invpos[NB];
__device__ int   g_finparp[NB];
__device__ int   g_lsort[NB];

// ---------------- fused length sort ----------------
__global__ void k_sort(const int* __restrict__ lengths) {
  int tid = threadIdx.x;
  if (tid < 66) g_hist[tid] = 0;
  __syncthreads();
  for (int b = tid; b < NB; b += 1024) atomicAdd(&g_hist[lengths[b]], 1);
  __syncthreads();
  if (tid == 0) {
    int s = 0;
    for (int l = 0; l < 66; ++l) { g_off[l] = s; s += g_hist[l]; }
  }
  __syncthreads();
  for (int b = tid; b < NB; b += 1024) {
    int p = atomicAdd(&g_off[lengths[b]], 1);
    g_perm[p] = b;
  }
  __syncthreads();
  if (tid < NBT) g_tilemax[tid] = lengths[g_perm[tid * TB + TB - 1]];
  __syncthreads();
  for (int p = tid; p < NB; p += 1024) {
    int b = g_perm[p];
    g_invpos[b] = p;
    g_finparp[p] = g_tilemax[p >> 6] & 1;
    g_lsort[p] = lengths[b];
  }
}

// barrier counter reset (launch #5 so gru is #6 for ncu)
__global__ void k_zsync() { if (threadIdx.x < 64) g_sync[threadIdx.x] = 0u; }

// ---------------- GRU B-value oracle (fp32) ----------------
__device__ float bval(const float* Whh, const float* Wih,
                      const float* bih, const float* bhh,
                      int jt, int n, int k) {
  int gate = n >> 6;              // 0:r 1:z 2:hn 3:in
  int j = jt * 64 + (n & 63);
  if (k < 256) {
    if (gate == 0) return Whh[(size_t)j * 256 + k];
    if (gate == 1) return Whh[(size_t)(256 + j) * 256 + k];
    if (gate == 2) return Whh[(size_t)(512 + j) * 256 + k];
    return 0.f;
  } else if (k < 271) {
    int i = k - 256;
    if (gate == 0) return Wih[(size_t)j * ND + i];
    if (gate == 1) return Wih[(size_t)(256 + j) * ND + i];
    if (gate == 2) return 0.f;
    return Wih[(size_t)(512 + j) * ND + i];
  } else {
    if (gate == 0) return bih[j] + bhh[j];
    if (gate == 1) return bih[256 + j] + bhh[256 + j];
    if (gate == 2) return bhh[512 + j];
    return bih[512 + j];
  }
}

// ---------------- GRU prep: pack B fragments ----------------
__global__ void k_prep(const float* __restrict__ Whh0, const float* __restrict__ Whh1,
                       const float* __restrict__ Wih0, const float* __restrict__ bih0,
                       const float* __restrict__ bhh0,
                       const float* __restrict__ Wih1, const float* __restrict__ bih1,
                       const float* __restrict__ bhh1) {
  int i = blockIdx.x * blockDim.x + threadIdx.x;
  if (i >= 2 * 4 * NKT * 32 * 32) return;
  int lane = i & 31;
  int nt   = (i >> 5) & 31;
  int kt   = (i >> 10) % NKT;
  int jt   = (i / (1024 * NKT)) & 3;
  int g    = i / (1024 * NKT * 4);
  const float* Whh = g ? Whh1 : Whh0;
  const float* Wih = g ? Wih1 : Wih0;
  const float* bih = g ? bih1 : bih0;
  const float* bhh = g ? bhh1 : bhh0;
  int n = nt * 8 + (lane >> 2);
  u32 out[4];
  #pragma unroll
  for (int reg = 0; reg < 2; ++reg) {
    int k0 = kt * 16 + 2 * (lane & 3) + reg * 8;
    float v0 = bval(Whh, Wih, bih, bhh, jt, n, k0);
    float v1 = bval(Whh, Wih, bih, bhh, jt, n, k0 + 1);
    float h0, l0, h1, l1;
    split2(v0, h0, l0); split2(v1, h1, l1);
    out[reg]     = pack_bf16x2(h0, h1);
    out[2 + reg] = pack_bf16x2(l0, l1);
  }
  g_wB4[i] = make_uint4(out[0], out[1], out[2], out[3]);
}

// ---------------- MLP prep: all 4 layers of one branch, range-decoded ----------------
__global__ void k_packw_all(const float* __restrict__ W1, const float* __restrict__ W2,
                            const float* __restrict__ W3, const float* __restrict__ W4,
                            uint4* __restrict__ dst) {
  int i = blockIdx.x * blockDim.x + threadIdx.x;
  if (i >= MLPB_BR) return;
  const float* W; int li, NTG, K;
  if (i < OFF_L2)      { W = W1; li = i;          NTG = 128; K = 272; }
  else if (i < OFF_L3) { W = W2; li = i - OFF_L2; NTG = 128; K = 1024; }
  else if (i < OFF_L4) { W = W3; li = i - OFF_L3; NTG = 64;  K = 1024; }
  else                 { W = W4; li = i - OFF_L4; NTG = 32;  K = 512; }
  int lane = li & 31;
  int ntg  = (li >> 5) % NTG;
  int kt   = (li >> 5) / NTG;
  int n = ntg * 8 + (lane >> 2);
  u32 out[4];
  #pragma unroll
  for (int reg = 0; reg < 2; ++reg) {
    int k0 = kt * 16 + 2 * (lane & 3) + reg * 8;
    float v0 = W[(size_t)n * K + k0];
    float v1 = W[(size_t)n * K + k0 + 1];
    float h0, l0, h1, l1;
    split2(v0, h0, l0); split2(v1, h1, l1);
    out[reg]     = pack_bf16x2(h0, h1);
    out[2 + reg] = pack_bf16x2(l0, l1);
  }
  dst[i] = make_uint4(out[0], out[1], out[2], out[3]);
}

// ---------------- persistent GRU kernel (unchanged math) ----------------
struct GruS {
  u32 hsbh[TB][132];
  u32 hsbl[TB][132];
  u32 xsbh[TB][9];
  u32 xsbl[TB][9];
  int ls[TB];
  u64 mb[2];
};

#define MMA3(g4, q, off)                                            \
  {                                                                 \
    uint4 v = pkt[(off)];                                           \
    mma_bf16(acc[g4][q], ah, v.x, v.y);                             \
    mma_bf16(acc[g4][q], al, v.x, v.y);                             \
    mma_bf16(acc[g4][q], ah, v.z, v.w);                             \
  }

__global__ void __launch_bounds__(THR, 2)
k_gru_persist(const float* __restrict__ state)
{
  extern __shared__ char sraw[];
  GruS& s = *reinterpret_cast<GruS*>(sraw);
  const int jt  = blockIdx.x & 3;
  const int gid = blockIdx.x >> 2;
  const int bt  = gid >> 1;
  const int g   = gid & 1;
  const int tid = threadIdx.x;
  const int tmax = g_tilemax[bt];
  const int gjt = g * 4 + jt;

  const unsigned mb = smem_u32p(&s.mb[0]);
  if (tid == 0) mbar_init(mb, 1);
  if (tid < TB) s.ls[tid] = g_lsort[bt * TB + tid];
  __syncthreads();

  const int w = tid >> 5, lane = tid & 31;
  const int m0 = (w & 3) * 16, jhalf = w >> 2;
  const int rA = m0 + (lane >> 2);
  const int cA = lane & 3;
  const uint4* __restrict__ wb =
      g_wB4 + (((size_t)gjt * NKT) * 32 + jhalf * 4) * 32 + lane;

  int ph = 0;
  for (int t = 0; t < tmax; ++t) {
    const int pi = t & 1, po = pi ^ 1;

    if (tid == 0 && t > 0) {
      mbar_expect(mb, 2u * 33792u);
      bulk_g2s(smem_u32p(&s.hsbh[0][0]), &g_hbh[pi][g][bt * TB][0], 33792u, mb);
      bulk_g2s(smem_u32p(&s.hsbl[0][0]), &g_hbl[pi][g][bt * TB][0], 33792u, mb);
    }

    for (int i = tid; i < TB * 8; i += THR) {
      int r = i >> 3, p = i & 7;
      const float* xp = state + (size_t)g_perm[bt * TB + r] * (NT * ND) + (size_t)t * ND;
      float v0 = xp[2 * p];
      float v1 = (p == 7) ? 1.0f : xp[2 * p + 1];
      float h0, l0, h1, l1;
      split2(v0, h0, l0); split2(v1, h1, l1);
      s.xsbh[r][p] = pack_bf16x2(h0, h1);
      s.xsbl[r][p] = pack_bf16x2(l0, l1);
    }
    __syncthreads();
    if (t > 0) { mbar_wait(mb, ph); ph ^= 1; }

    float acc[4][4][4];
    #pragma unroll
    for (int a = 0; a < 4; ++a)
      #pragma unroll
      for (int b = 0; b < 4; ++b)
        #pragma unroll
        for (int c = 0; c < 4; ++c) acc[a][b][c] = 0.f;

    u32 ah[4], al[4];

    if (t > 0) {
      #pragma unroll 4
      for (int kt = 0; kt < 16; ++kt) {
        int cb = kt * 8 + cA;
        ah[0] = s.hsbh[rA][cb];     ah[1] = s.hsbh[rA + 8][cb];
        ah[2] = s.hsbh[rA][cb + 4]; ah[3] = s.hsbh[rA + 8][cb + 4];
        al[0] = s.hsbl[rA][cb];     al[1] = s.hsbl[rA + 8][cb];
        al[2] = s.hsbl[rA][cb + 4]; al[3] = s.hsbl[rA + 8][cb + 4];
        const uint4* __restrict__ pkt = wb + kt * 1024;
        MMA3(0, 0, 0 * 32)   MMA3(0, 1, 1 * 32)   MMA3(0, 2, 2 * 32)   MMA3(0, 3, 3 * 32)
        MMA3(1, 0, 8 * 32)   MMA3(1, 1, 9 * 32)   MMA3(1, 2, 10 * 32)  MMA3(1, 3, 11 * 32)
        MMA3(2, 0, 16 * 32)  MMA3(2, 1, 17 * 32)  MMA3(2, 2, 18 * 32)  MMA3(2, 3, 19 * 32)
      }
    }
    {
      ah[0] = s.xsbh[rA][cA];     ah[1] = s.xsbh[rA + 8][cA];
      ah[2] = s.xsbh[rA][cA + 4]; ah[3] = s.xsbh[rA + 8][cA + 4];
      al[0] = s.xsbl[rA][cA];     al[1] = s.xsbl[rA + 8][cA];
      al[2] = s.xsbl[rA][cA + 4]; al[3] = s.xsbl[rA + 8][cA + 4];
      const uint4* __restrict__ pkt = wb + 16 * 1024;
      MMA3(0, 0, 0 * 32)   MMA3(0, 1, 1 * 32)   MMA3(0, 2, 2 * 32)   MMA3(0, 3, 3 * 32)
      MMA3(1, 0, 8 * 32)   MMA3(1, 1, 9 * 32)   MMA3(1, 2, 10 * 32)  MMA3(1, 3, 11 * 32)
      MMA3(2, 0, 16 * 32)  MMA3(2, 1, 17 * 32)  MMA3(2, 2, 18 * 32)  MMA3(2, 3, 19 * 32)
      MMA3(3, 0, 24 * 32)  MMA3(3, 1, 25 * 32)  MMA3(3, 2, 26 * 32)  MMA3(3, 3, 27 * 32)
    }

    #pragma unroll
    for (int q = 0; q < 4; ++q) {
      #pragma unroll
      for (int half = 0; half < 2; ++half) {
        int rl = m0 + (lane >> 2) + half * 8;
        bool act = (t < s.ls[rl]);
        int jloc = jhalf * 32 + q * 8 + 2 * (lane & 3);
        int jg = jt * 64 + jloc;
        float hold0 = 0.f, hold1 = 0.f;
        if (t > 0) {
          u32 vh = s.hsbh[rl][jg >> 1];
          u32 vl = s.hsbl[rl][jg >> 1];
          hold0 = bf16_lo_f(vh) + bf16_lo_f(vl);
          hold1 = bf16_hi_f(vh) + bf16_hi_f(vl);
        }
        float hn[2];
        #pragma unroll
        for (int e = 0; e < 2; ++e) {
          float xr = acc[0][q][half * 2 + e];
          float xz = acc[1][q][half * 2 + e];
          float xhn = acc[2][q][half * 2 + e];
          float xin = acc[3][q][half * 2 + e];
          float hold = e ? hold1 : hold0;
          if (act) {
            float r = __fdividef(1.f, 1.f + __expf(-xr));
            float z = __fdividef(1.f, 1.f + __expf(-xz));
            float n = tanhf(fmaf(r, xhn, xin));
            hn[e] = fmaf(z, hold - n, n);
          } else {
            hn[e] = hold;
          }
        }
        float h0, l0, h1, l1;
        split2(hn[0], h0, l0); split2(hn[1], h1, l1);
        int grow = bt * TB + rl;
        g_hbh[po][g][grow][jg >> 1] = pack_bf16x2(h0, h1);
        g_hbl[po][g][grow][jg >> 1] = pack_bf16x2(l0, l1);
      }
    }

    if (t + 1 < tmax) {
      __threadfence();
      __syncthreads();
      if (tid == 0) {
        unsigned target = 4u * (unsigned)(t + 1);
        atomicAdd(&g_sync[gid], 1u);
        while (*(volatile unsigned*)&g_sync[gid] < target) __nanosleep(64);
      }
      __syncthreads();
    }
  }
}

// ---------------- concat -> xin bf16 pairs, both branches ----------------
__global__ void k_concat2(const float* __restrict__ state,
                          const float* __restrict__ action) {
  int b = blockIdx.x, br = blockIdx.y;
  int p = g_invpos[b];
  int fp = g_finparp[p];
  for (int c = threadIdx.x; c < 136; c += 64) {
    float v0, v1;
    if (c < 7) {
      v0 = state[(size_t)b * NT * ND + 2 * c];
      v1 = state[(size_t)b * NT * ND + 2 * c + 1];
    } else if (c == 7) {
      v0 = state[(size_t)b * NT * ND + 14];
      v1 = action[b];
    } else {
      u32 vh = g_hbh[fp][br][p][c - 8];
      u32 vl = g_hbl[fp][br][p][c - 8];
      v0 = bf16_lo_f(vh) + bf16_lo_f(vl);
      v1 = bf16_hi_f(vh) + bf16_hi_f(vl);
    }
    float h0, l0, h1, l1;
    split2(v0, h0, l0); split2(v1, h1, l1);
    g_xh[br][b][c] = pack_bf16x2(h0, h1);
    g_xl[br][b][c] = pack_bf16x2(l0, l1);
  }
}

// ---------------- tensor-core MLP layer, both branches via blockIdx.z ----------------
__global__ void __launch_bounds__(128)
k_tmma(const u32* __restrict__ Ah, const u32* __restrict__ Al, int abrs,
       const uint4* __restrict__ Wfrag,
       const float* __restrict__ bias0, const float* __restrict__ bias1,
       u32* __restrict__ Oh, u32* __restrict__ Ol, int obrs,
       int KT, int NTGtot, int relu)
{
  const int br = blockIdx.z;
  Ah += (size_t)br * abrs;  Al += (size_t)br * abrs;
  Oh += (size_t)br * obrs;  Ol += (size_t)br * obrs;
  const uint4* Wb = Wfrag + (size_t)br * MLPB_BR;
  const float* bias = br ? bias1 : bias0;

  const int w = threadIdx.x >> 5, lane = threadIdx.x & 31;
  const int m0 = blockIdx.x * 64 + w * 16;
  const int ntg0 = blockIdx.y * 8;
  const int K2 = KT * 8;
  const int rA = m0 + (lane >> 2);
  const int cA = lane & 3;
  const int outK2 = NTGtot * 4;

  const u32* __restrict__ pAh = Ah + (size_t)rA * K2 + cA;
  const u32* __restrict__ pAl = Al + (size_t)rA * K2 + cA;
  const uint4* __restrict__ wbp = Wb + (size_t)ntg0 * 32 + lane;
  const size_t rstep = (size_t)8 * K2;

  float acc[8][4];
  #pragma unroll
  for (int q = 0; q < 8; ++q)
    #pragma unroll
    for (int c = 0; c < 4; ++c) acc[q][c] = 0.f;

  for (int kt = 0; kt < KT; ++kt) {
    u32 ah[4], al[4];
    int o = kt * 8;
    ah[0] = pAh[o];         ah[1] = pAh[o + rstep];
    ah[2] = pAh[o + 4];     ah[3] = pAh[o + 4 + rstep];
    al[0] = pAl[o];         al[1] = pAl[o + rstep];
    al[2] = pAl[o + 4];     al[3] = pAl[o + 4 + rstep];
    const uint4* __restrict__ pkt = wbp + (size_t)kt * NTGtot * 32;
    #pragma unroll
    for (int q = 0; q < 8; ++q) {
      uint4 v = pkt[q * 32];
      mma_bf16(acc[q], ah, v.x, v.y);
      mma_bf16(acc[q], al, v.x, v.y);
      mma_bf16(acc[q], ah, v.z, v.w);
    }
  }

  #pragma unroll
  for (int q = 0; q < 8; ++q) {
    int n0 = (ntg0 + q) * 8 + 2 * (lane & 3);
    float b0 = bias[n0], b1 = bias[n0 + 1];
    float c0 = acc[q][0] + b0, c1 = acc[q][1] + b1;
    float c2 = acc[q][2] + b0, c3 = acc[q][3] + b1;
    if (relu) {
      c0 = fmaxf(c0, 0.f); c1 = fmaxf(c1, 0.f);
      c2 = fmaxf(c2, 0.f); c3 = fmaxf(c3, 0.f);
    }
    float h0, l0, h1, l1;
    split2(c0, h0, l0); split2(c1, h1, l1);
    size_t o0 = (size_t)rA * outK2 + (n0 >> 1);
    Oh[o0] = pack_bf16x2(h0, h1);
    Ol[o0] = pack_bf16x2(l0, l1);
    split2(c2, h0, l0); split2(c3, h1, l1);
    size_t o1 = (size_t)(rA + 8) * outK2 + (n0 >> 1);
    Oh[o1] = pack_bf16x2(h0, h1);
    Ol[o1] = pack_bf16x2(l0, l1);
  }
}

// ---------------- q head, both branches (branch stride = NB*512 u32) ----------------
__global__ void k_q2(const u32* __restrict__ Ah, const u32* __restrict__ Al,
                     const float* __restrict__ qw0, const float* __restrict__ qb0,
                     const float* __restrict__ qw1, const float* __restrict__ qb1,
                     float* __restrict__ out)
{
  __shared__ float red[64];
  int b = blockIdx.x, br = blockIdx.y;
  const u32* pAh = Ah + (size_t)br * NB * 512;   // FIX: buffer branch stride is NB*512
  const u32* pAl = Al + (size_t)br * NB * 512;
  const float* qw = br ? qw1 : qw0;
  const float* qb = br ? qb1 : qb0;
  float sum = 0.f;
  for (int p = threadIdx.x; p < 128; p += 64) {
    u32 vh = pAh[(size_t)b * 128 + p];
    u32 vl = pAl[(size_t)b * 128 + p];
    float v0 = bf16_lo_f(vh) + bf16_lo_f(vl);
    float v1 = bf16_hi_f(vh) + bf16_hi_f(vl);
    sum += v0 * qw[2 * p] + v1 * qw[2 * p + 1];
  }
  red[threadIdx.x] = sum;
  __syncthreads();
  if (threadIdx.x < 32) {
    float v = red[threadIdx.x] + red[threadIdx.x + 32];
    #pragma unroll
    for (int o = 16; o; o >>= 1) v += __shfl_down_sync(0xffffffffu, v, o);
    if (threadIdx.x == 0) out[(size_t)br * NB + b] = v + qb[0];
  }
}

// ---------------- launch ----------------
extern "C" void kernel_launch(void* const* d_in, const int* in_sizes, int n_in,
                              void* d_out, int out_size)
{
  const float* state   = (const float*)d_in[0];
  const float* action  = (const float*)d_in[1];
  const int*   lengths = (const int*)d_in[2];

  const float* gWih[2]; const float* gWhh[2];
  const float* gbih[2]; const float* gbhh[2];
  const float* fcw[2][5]; const float* fcb[2][5];
  for (int br = 0; br < 2; ++br) {
    int base = 3 + br * 14;
    gWih[br] = (const float*)d_in[base + 0];
    gWhh[br] = (const float*)d_in[base + 1];
    gbih[br] = (const float*)d_in[base + 2];
    gbhh[br] = (const float*)d_in[base + 3];
    for (int l = 0; l < 5; ++l) {
      fcw[br][l] = (const float*)d_in[base + 4 + 2 * l];
      fcb[br][l] = (const float*)d_in[base + 5 + 2 * l];
    }
  }

  u32 *p_xh, *p_xl, *p_m0h, *p_m0l, *p_m1h, *p_m1l;
  uint4* p_mlpB;
  cudaGetSymbolAddress((void**)&p_xh, g_xh);
  cudaGetSymbolAddress((void**)&p_xl, g_xl);
  cudaGetSymbolAddress((void**)&p_m0h, g_m0h);
  cudaGetSymbolAddress((void**)&p_m0l, g_m0l);
  cudaGetSymbolAddress((void**)&p_m1h, g_m1h);
  cudaGetSymbolAddress((void**)&p_m1l, g_m1l);
  cudaGetSymbolAddress((void**)&p_mlpB, g_mlpB);

  cudaFuncSetAttribute(k_gru_persist, cudaFuncAttributeMaxDynamicSharedMemorySize,
                       (int)sizeof(GruS));

  // prep: launches 1-5 (gru persistent = launch 6 for ncu -s 5 -c 1)
  k_sort<<<1, 1024>>>(lengths);
  k_prep<<<(2 * 4 * NKT * 32 * 32 + 255) / 256, 256>>>(gWhh[0], gWhh[1],
                                                       gWih[0], gbih[0], gbhh[0],
                                                       gWih[1], gbih[1], gbhh[1]);
  k_packw_all<<<(MLPB_BR + 255) / 256, 256>>>(fcw[0][0], fcw[0][1], fcw[0][2], fcw[0][3],
                                              p_mlpB);
  k_packw_all<<<(MLPB_BR + 255) / 256, 256>>>(fcw[1][0], fcw[1][1], fcw[1][2], fcw[1][3],
                                              p_mlpB + MLPB_BR);
  k_zsync<<<1, 64>>>();

  // persistent recurrent kernel: 256 CTAs (one wave)
  k_gru_persist<<<256, THR, sizeof(GruS)>>>(state);

  // MLP, both branches fused via grid.z
  float* outp = (float*)d_out;
  k_concat2<<<dim3(NB, 2), 64>>>(state, action);
  k_tmma<<<dim3(32, 16, 2), 128>>>(p_xh, p_xl, NB * 136, p_mlpB + OFF_L1,
                                   fcb[0][0], fcb[1][0],
                                   p_m0h, p_m0l, NB * 512, 17, 128, 1);
  k_tmma<<<dim3(32, 16, 2), 128>>>(p_m0h, p_m0l, NB * 512, p_mlpB + OFF_L2,
                                   fcb[0][1], fcb[1][1],
                                   p_m1h, p_m1l, NB * 512, 64, 128, 1);
  k_tmma<<<dim3(32, 8, 2), 128>>>(p_m1h, p_m1l, NB * 512, p_mlpB + OFF_L3,
                                  fcb[0][2], fcb[1][2],
                                  p_m0h, p_m0l, NB * 512, 64, 64, 1);
  k_tmma<<<dim3(32, 4, 2), 128>>>(p_m0h, p_m0l, NB * 512, p_mlpB + OFF_L4,
                                  fcb[0][3], fcb[1][3],
                                  p_m1h, p_m1l, NB * 512, 32, 32, 1);
  k_q2<<<dim3(NB, 2), 64>>>(p_m1h, p_m1l, fcw[0][4], fcb[0][4], fcw[1][4], fcb[1][4],
                            outp);
}